// round 5
// baseline (speedup 1.0000x reference)
#include <cuda_runtime.h>
#include <cuda_bf16.h>
#include <cstdint>

// ---------------- problem constants ----------------
#define Bb 2
#define Ss 4096
#define Dm 768
#define Hh 12
#define HD 64
#define BLKSZ 32
#define NBR 128
#define NUMBLK 1024
#define MBT (Bb*Hh)        // 24
#define MROWS (Bb*Ss)      // 8192

typedef unsigned long long ull;

// ---------------- f32x2 helpers ----------------
__device__ __forceinline__ void ffma2(ull &d, ull a, ull b) {
    asm("fma.rn.f32x2 %0, %1, %2, %0;" : "+l"(d) : "l"(a), "l"(b));
}
__device__ __forceinline__ ull fmul2(ull a, ull b) {
    ull d; asm("mul.rn.f32x2 %0, %1, %2;" : "=l"(d) : "l"(a), "l"(b)); return d;
}
__device__ __forceinline__ ull pack2(float x, float y) {
    ull r; asm("mov.b64 %0, {%1, %2};" : "=l"(r) : "f"(x), "f"(y)); return r;
}
__device__ __forceinline__ void unpack2(ull v, float &x, float &y) {
    asm("mov.b64 {%0, %1}, %2;" : "=f"(x), "=f"(y) : "l"(v));
}

__device__ __forceinline__ uint32_t smem_u32(const void* p) {
    uint32_t a;
    asm("{ .reg .u64 t; cvta.to.shared.u64 t, %1; cvt.u32.u64 %0, t; }" : "=r"(a) : "l"(p));
    return a;
}

// ---------------- mma.sync helpers ----------------
__device__ __forceinline__ void ldsm4(uint32_t &r0, uint32_t &r1, uint32_t &r2, uint32_t &r3, uint32_t addr) {
    asm volatile("ldmatrix.sync.aligned.m8n8.x4.shared.b16 {%0,%1,%2,%3}, [%4];"
        : "=r"(r0), "=r"(r1), "=r"(r2), "=r"(r3) : "r"(addr));
}
__device__ __forceinline__ void mma16816(float* c,
    uint32_t a0, uint32_t a1, uint32_t a2, uint32_t a3, uint32_t b0, uint32_t b1) {
    asm volatile("mma.sync.aligned.m16n8k16.row.col.f32.bf16.bf16.f32 "
        "{%0,%1,%2,%3}, {%4,%5,%6,%7}, {%8,%9}, {%0,%1,%2,%3};"
        : "+f"(c[0]), "+f"(c[1]), "+f"(c[2]), "+f"(c[3])
        : "r"(a0), "r"(a1), "r"(a2), "r"(a3), "r"(b0), "r"(b1));
}

// ---------------- device scratch ----------------
__device__ float g_Q[MBT*Ss*HD];
__device__ float g_K[MBT*Ss*HD];
__device__ float g_V[MBT*Ss*HD];
__device__ __nv_bfloat16 g_Xh[MROWS*Dm];
__device__ __nv_bfloat16 g_Xl[MROWS*Dm];
__device__ __nv_bfloat16 g_Wh[3*Dm*Dm];
__device__ __nv_bfloat16 g_Wl[3*Dm*Dm];
__device__ float g_Xbar[Bb*NBR*Dm];
__device__ float g_tcb[Bb*NBR];
__device__ float g_tcf[Bb*NBR];
__device__ float g_Qh[MBT*NBR*HD];
__device__ float g_Kh[MBT*NBR*HD];
__device__ float g_Vh[MBT*NBR*HD];
__device__ float g_rowmax[MBT*NBR];
__device__ int   g_cnt[MBT*NBR];
__device__ int   g_list[MBT*NBR*NBR];
__device__ float g_high_out[MBT*Ss*HD];
__device__ float g_high_norm[MBT*Ss];
__device__ float g_maxrows[MBT*Ss];
__device__ float g_low_out[MBT*NBR*HD];
__device__ float g_low_norm[MBT*NBR];

__device__ __forceinline__ unsigned f2ord(float f) {
    unsigned u = __float_as_uint(f);
    return (u & 0x80000000u) ? ~u : (u | 0x80000000u);
}

// ---------------- kernel 0a: split X into bf16 hi/lo ----------------
__global__ void convX_kernel(const float* __restrict__ X)
{
    int i = (blockIdx.x*256 + threadIdx.x)*4;
    float4 v = *(const float4*)(X + i);
    float vf[4] = {v.x, v.y, v.z, v.w};
    __nv_bfloat16 h[4], l[4];
    #pragma unroll
    for (int j = 0; j < 4; j++) {
        h[j] = __float2bfloat16(vf[j]);
        l[j] = __float2bfloat16(vf[j] - __bfloat162float(h[j]));
    }
    *(ull*)(g_Xh + i) = *(ull*)h;
    *(ull*)(g_Xl + i) = *(ull*)l;
}

// ---------------- kernel 0b: split W into bf16 hi/lo ----------------
__global__ void convW_kernel(const float* __restrict__ Wq,
                             const float* __restrict__ Wk,
                             const float* __restrict__ Wv)
{
    int mat = blockIdx.y;
    const float* W = (mat == 0) ? Wq : (mat == 1) ? Wk : Wv;
    int i = (blockIdx.x*256 + threadIdx.x)*4;
    float4 v = *(const float4*)(W + i);
    float vf[4] = {v.x, v.y, v.z, v.w};
    __nv_bfloat16 h[4], l[4];
    #pragma unroll
    for (int j = 0; j < 4; j++) {
        h[j] = __float2bfloat16(vf[j]);
        l[j] = __float2bfloat16(vf[j] - __bfloat162float(h[j]));
    }
    size_t o = (size_t)mat*Dm*Dm + i;
    *(ull*)(g_Wh + o) = *(ull*)h;
    *(ull*)(g_Wl + o) = *(ull*)l;
}

// ---------------- kernel 0c: masked block-mean of X ----------------
__global__ void xbar_kernel(const float* __restrict__ X, const float* __restrict__ mask)
{
    int bn = blockIdx.x;             // Bb*NBR
    int bb = bn >> 7, n = bn & 127;
    int d = threadIdx.x;             // 768
    const float* mrow = mask + (size_t)bb*Ss + n*BLKSZ;
    float tc = 0.f;
    #pragma unroll
    for (int t = 0; t < BLKSZ; t++) tc += mrow[t];
    float denom = tc + 1e-6f;
    const float* xp = X + ((size_t)bb*Ss + n*BLKSZ)*Dm + d;
    float s = 0.f;
    #pragma unroll 4
    for (int t = 0; t < BLKSZ; t++) s += mrow[t]*xp[(size_t)t*Dm];
    g_Xbar[(size_t)bn*Dm + d] = s/denom;
    if (d == 0) { g_tcb[bn] = tc; g_tcf[bn] = tc/denom; }
}

// ---------------- kernel 1: QKV projection via mma.sync bf16 (3-term split) ----------------
#define BUFA_L 10240
#define BUFB_H 20480
#define BUFB_L 40960
#define BUF_STRIDE 61440
#define GEMM_SMEM (2*BUF_STRIDE)

__global__ __launch_bounds__(256, 1) void qkv_mma_kernel(
    const float* __restrict__ mask,
    const float* __restrict__ bq, const float* __restrict__ bk, const float* __restrict__ bv)
{
    extern __shared__ __align__(16) char smem[];
    const uint32_t sb = smem_u32(smem);
    const int tid = threadIdx.x, lane = tid & 31, wid = tid >> 5;
    const int m0 = blockIdx.x * 128;
    const int tile = blockIdx.y;          // 0..8
    const int mat = tile / 3;
    const int n0 = (tile % 3) * 256;
    const int wm = wid & 1;
    const int wn = wid >> 1;

    const uint4* XH = (const uint4*)g_Xh;
    const uint4* XL = (const uint4*)g_Xl;
    const uint4* WH = (const uint4*)(g_Wh + (size_t)mat*Dm*Dm);
    const uint4* WL = (const uint4*)(g_Wl + (size_t)mat*Dm*Dm);
    const float* bias = (mat == 0) ? bq : (mat == 1) ? bk : bv;
    float* out = (mat == 0) ? g_Q : (mat == 1) ? g_K : g_V;

    float acc[4][8][4];
    #pragma unroll
    for (int a = 0; a < 4; a++)
        #pragma unroll
        for (int b = 0; b < 8; b++)
            #pragma unroll
            for (int c = 0; c < 4; c++) acc[a][b][c] = 0.f;

    const int arow = tid >> 2, ac = tid & 3;

    #define ISSUE_STAGE(s) do { \
        const int _buf = (s) & 1; \
        const uint32_t _bb = sb + _buf*BUF_STRIDE; \
        const int _kc4 = (s)*4; \
        _Pragma("unroll") \
        for (int _i = 0; _i < 2; _i++) { \
            int _row = arow + _i*64; \
            uint32_t _so = _bb + _row*80 + ac*16; \
            const void* _gh = &XH[(size_t)(m0 + _row)*96 + _kc4 + ac]; \
            const void* _gl = &XL[(size_t)(m0 + _row)*96 + _kc4 + ac]; \
            asm volatile("cp.async.cg.shared.global [%0], [%1], 16;" :: "r"(_so), "l"(_gh)); \
            asm volatile("cp.async.cg.shared.global [%0], [%1], 16;" :: "r"(_so + BUFA_L), "l"(_gl)); \
        } \
        _Pragma("unroll") \
        for (int _i = 0; _i < 4; _i++) { \
            int _row = arow + _i*64; \
            uint32_t _so = _bb + BUFB_H + _row*80 + ac*16; \
            const void* _gh = &WH[(size_t)(n0 + _row)*96 + _kc4 + ac]; \
            const void* _gl = &WL[(size_t)(n0 + _row)*96 + _kc4 + ac]; \
            asm volatile("cp.async.cg.shared.global [%0], [%1], 16;" :: "r"(_so), "l"(_gh)); \
            asm volatile("cp.async.cg.shared.global [%0], [%1], 16;" :: "r"(_so + (BUFB_L - BUFB_H)), "l"(_gl)); \
        } \
        asm volatile("cp.async.commit_group;" ::: "memory"); \
    } while (0)

    ISSUE_STAGE(0);

    for (int s = 0; s < 24; s++) {
        asm volatile("cp.async.wait_group 0;" ::: "memory");
        __syncthreads();
        if (s + 1 < 24) ISSUE_STAGE(s + 1);
        const uint32_t base = sb + (s & 1)*BUF_STRIDE;

        #pragma unroll
        for (int kk = 0; kk < 2; kk++) {
            const uint32_t koff = kk*32;
            uint32_t ah[4][4], al[4][4];
            #pragma unroll
            for (int mt = 0; mt < 4; mt++) {
                int row = wm*64 + mt*16 + (lane & 7) + ((lane >> 3) & 1)*8;
                uint32_t ad = base + row*80 + koff + (lane >> 4)*16;
                ldsm4(ah[mt][0], ah[mt][1], ah[mt][2], ah[mt][3], ad);
                ldsm4(al[mt][0], al[mt][1], al[mt][2], al[mt][3], ad + BUFA_L);
            }
            #pragma unroll
            for (int np = 0; np < 4; np++) {
                int n = wn*64 + np*16 + (lane & 7) + (lane >> 4)*8;
                uint32_t bd = base + BUFB_H + n*80 + koff + ((lane >> 3) & 1)*16;
                uint32_t b0, b1, b2, b3;
                ldsm4(b0, b1, b2, b3, bd);
                #pragma unroll
                for (int mt = 0; mt < 4; mt++) {
                    mma16816(acc[mt][np*2],   ah[mt][0], ah[mt][1], ah[mt][2], ah[mt][3], b0, b1);
                    mma16816(acc[mt][np*2+1], ah[mt][0], ah[mt][1], ah[mt][2], ah[mt][3], b2, b3);
                    mma16816(acc[mt][np*2],   al[mt][0], al[mt][1], al[mt][2], al[mt][3], b0, b1);
                    mma16816(acc[mt][np*2+1], al[mt][0], al[mt][1], al[mt][2], al[mt][3], b2, b3);
                }
            }
            #pragma unroll
            for (int np = 0; np < 4; np++) {
                int n = wn*64 + np*16 + (lane & 7) + (lane >> 4)*8;
                uint32_t bd = base + BUFB_L + n*80 + koff + ((lane >> 3) & 1)*16;
                uint32_t b0, b1, b2, b3;
                ldsm4(b0, b1, b2, b3, bd);
                #pragma unroll
                for (int mt = 0; mt < 4; mt++) {
                    mma16816(acc[mt][np*2],   ah[mt][0], ah[mt][1], ah[mt][2], ah[mt][3], b0, b1);
                    mma16816(acc[mt][np*2+1], ah[mt][0], ah[mt][1], ah[mt][2], ah[mt][3], b2, b3);
                }
            }
        }
    }

    const int h = (n0 + wn*64) >> 6;
    const float* bp = bias + n0 + wn*64;
    float2 bias2[8];
    #pragma unroll
    for (int nt = 0; nt < 8; nt++) bias2[nt] = *(const float2*)(bp + nt*8 + (lane & 3)*2);

    #pragma unroll
    for (int mt = 0; mt < 4; mt++) {
        #pragma unroll
        for (int half = 0; half < 2; half++) {
            int m = m0 + wm*64 + mt*16 + (lane >> 2) + half*8;
            int bbm = m >> 12, sx = m & 4095;
            float mv = mask[(size_t)bbm*Ss + sx];
            float* op = out + ((size_t)(bbm*Hh + h)*Ss + sx)*HD;
            #pragma unroll
            for (int nt = 0; nt < 8; nt++) {
                int col = nt*8 + (lane & 3)*2;
                float2 w;
                w.x = (acc[mt][nt][half*2+0] + bias2[nt].x)*mv;
                w.y = (acc[mt][nt][half*2+1] + bias2[nt].y)*mv;
                *(float2*)(op + col) = w;
            }
        }
    }
}

// ---------------- kernel 1b: exact fp32 block-mean projection (f32x2 GEMM) ----------------
// Qh/Kh/Vh[mb,n,:] = Xbar[bb*NBR+n] @ W^T + bias * tcf. M=256, N=768, K=768.
__global__ __launch_bounds__(256) void hmean_gemm_kernel(
    const float* __restrict__ Wq, const float* __restrict__ Wk, const float* __restrict__ Wv,
    const float* __restrict__ bq, const float* __restrict__ bk, const float* __restrict__ bv)
{
    __shared__ __align__(16) float As[2][8][136];
    __shared__ __align__(16) float Bs[2][8][136];

    const int mat = blockIdx.z;
    const float* W = (mat == 0) ? Wq : (mat == 1) ? Wk : Wv;
    const float* bias = (mat == 0) ? bq : (mat == 1) ? bk : bv;
    float* out = (mat == 0) ? g_Qh : (mat == 1) ? g_Kh : g_Vh;

    const int tid = threadIdx.x;
    const int r0 = blockIdx.x * 128;
    const int e0 = blockIdx.y * 128;
    const int lrow = tid >> 1;
    const int lhalf = tid & 1;
    const int ty = tid >> 4;
    const int tx = tid & 15;

    const float4* Ag = (const float4*)(g_Xbar + (size_t)(r0 + lrow)*Dm);
    const float4* Bg = (const float4*)(W + (size_t)(e0 + lrow)*Dm);

    float4 ra = Ag[lhalf];
    float4 rb = Bg[lhalf];

    ull acc[4][8];
    #pragma unroll
    for (int i = 0; i < 4; i++)
        #pragma unroll
        for (int j = 0; j < 8; j++) acc[i][j] = 0ull;

    for (int it = 0; it < 96; ++it) {
        const int buf = it & 1;
        As[buf][lhalf*4+0][lrow] = ra.x;
        As[buf][lhalf*4+1][lrow] = ra.y;
        As[buf][lhalf*4+2][lrow] = ra.z;
        As[buf][lhalf*4+3][lrow] = ra.w;
        Bs[buf][lhalf*4+0][lrow] = rb.x;
        Bs[buf][lhalf*4+1][lrow] = rb.y;
        Bs[buf][lhalf*4+2][lrow] = rb.z;
        Bs[buf][lhalf*4+3][lrow] = rb.w;
        __syncthreads();
        if (it < 95) {
            ra = Ag[(it+1)*2 + lhalf];
            rb = Bg[(it+1)*2 + lhalf];
        }
        #pragma unroll
        for (int kk = 0; kk < 8; kk++) {
            const ulonglong2 a01 = *(const ulonglong2*)&As[buf][kk][ty*8];
            const ulonglong2 a23 = *(const ulonglong2*)&As[buf][kk][ty*8+4];
            ull av[4] = {a01.x, a01.y, a23.x, a23.y};
            const float4 b0 = *(const float4*)&Bs[buf][kk][tx*8];
            const float4 b1 = *(const float4*)&Bs[buf][kk][tx*8+4];
            ull bv2[8];
            bv2[0] = pack2(b0.x, b0.x); bv2[1] = pack2(b0.y, b0.y);
            bv2[2] = pack2(b0.z, b0.z); bv2[3] = pack2(b0.w, b0.w);
            bv2[4] = pack2(b1.x, b1.x); bv2[5] = pack2(b1.y, b1.y);
            bv2[6] = pack2(b1.z, b1.z); bv2[7] = pack2(b1.w, b1.w);
            #pragma unroll
            for (int i = 0; i < 4; i++)
                #pragma unroll
                for (int j = 0; j < 8; j++)
                    ffma2(acc[i][j], av[i], bv2[j]);
        }
        __syncthreads();
    }

    #pragma unroll
    for (int i = 0; i < 4; i++) {
        float vlo[8], vhi[8];
        #pragma unroll
        for (int j = 0; j < 8; j++) unpack2(acc[i][j], vlo[j], vhi[j]);
        #pragma unroll
        for (int ln = 0; ln < 2; ln++) {
            const int r = r0 + ty*8 + i*2 + ln;
            const int bb2 = r >> 7, n = r & 127;
            const float tcf = g_tcf[r];
            const float* vv = ln ? vhi : vlo;
            #pragma unroll
            for (int j = 0; j < 8; j++) {
                int e = e0 + tx*8 + j;
                int hh = e >> 6, hd = e & 63;
                out[(((size_t)(bb2*Hh + hh))*NBR + n)*HD + hd] = vv[j] + bias[e]*tcf;
            }
        }
    }
}

// ---------------- kernel 2: fused low-res stage (logits+rowmax+thresh+select+lowattn) ----------------
#define LS_QH   0
#define LS_KV   33280
#define LS_LL   66560
#define LS_RM   132608
#define LS_TC   133120
#define LS_A    133632
#define LS_PS   134656
#define LS_HIST 134688
#define LS_CTRL 135712
#define LS_SMEM 135936

__global__ __launch_bounds__(256) void lowstage_kernel()
{
    extern __shared__ __align__(16) char sm[];
    float* Qhs = (float*)(sm + LS_QH);     // [128][65]
    float* Kts = (float*)(sm + LS_KV);     // [64][129], later Vhs [128][65]
    float* ll  = (float*)(sm + LS_LL);     // [128][129]
    float* rm_s = (float*)(sm + LS_RM);
    float* tc_sh = (float*)(sm + LS_TC);
    float* a_sh = (float*)(sm + LS_A);     // [2][128]
    float* psum = (float*)(sm + LS_PS);    // [2][4]
    unsigned* hist = (unsigned*)(sm + LS_HIST);
    unsigned* ctrl = (unsigned*)(sm + LS_CTRL);

    const int mb = blockIdx.x;
    const int bb = mb / Hh;
    const int tid = threadIdx.x;
    const int lane = tid & 31;

    for (int i = tid; i < 128*64; i += 256) {
        int n = i >> 6, d = i & 63;
        Qhs[n*65+d] = g_Qh[((size_t)mb*NBR+n)*HD+d];
        Kts[d*129+n] = g_Kh[((size_t)mb*NBR+n)*HD+d];
    }
    if (tid < 128) tc_sh[tid] = g_tcb[bb*NBR+tid];
    if (tid == 0) { ctrl[0] = 0u; ctrl[1] = NUMBLK; }
    __syncthreads();

    // logits (raw, pre-mask), 4-m register blocking
    for (int it = 0; it < 16; it++) {
        int n = it*8 + (tid >> 5);
        int m4 = tid & 31;
        float s0 = 0.f, s1 = 0.f, s2 = 0.f, s3 = 0.f;
        #pragma unroll 8
        for (int d = 0; d < 64; d++) {
            float qv = Qhs[n*65+d];
            const float* kr = &Kts[d*129];
            s0 += qv*kr[m4];
            s1 += qv*kr[m4+32];
            s2 += qv*kr[m4+64];
            s3 += qv*kr[m4+96];
        }
        float* lr = &ll[n*129];
        lr[m4] = s0*0.125f; lr[m4+32] = s1*0.125f; lr[m4+64] = s2*0.125f; lr[m4+96] = s3*0.125f;
    }
    __syncthreads();
    // row max (pre empty-pair mask)
    if (tid < 128) {
        float mx = -1e30f;
        const float* lr = &ll[tid*129];
        #pragma unroll 8
        for (int m = 0; m < 128; m++) mx = fmaxf(mx, lr[m]);
        rm_s[tid] = mx;
        g_rowmax[mb*NBR+tid] = mx;
    }
    __syncthreads();
    // empty-pair mask
    for (int i = tid; i < 128*128; i += 256) {
        int n = i >> 7, m = i & 127;
        if (tc_sh[n]*tc_sh[m] < 0.5f) ll[n*129+m] -= 1e4f;
    }
    __syncthreads();
    // radix select 1024-th largest prior
    for (int pass = 0; pass < 4; pass++) {
        int shift = 24 - pass*8;
        hist[tid] = 0u;
        __syncthreads();
        unsigned pref = ctrl[0];
        for (int i = tid; i < 128*128; i += 256) {
            int n = i >> 7, m = i & 127;
            int dif = n - m; if (dif < 0) dif = -dif;
            float pv = ll[n*129+m] - rm_s[n] + (dif <= 1 ? 5e3f : 0.f);
            unsigned u = f2ord(pv);
            bool ok = (pass == 0) ? true : (((u ^ pref) >> (shift + 8)) == 0u);
            unsigned bin = ok ? ((u >> shift) & 255u) : 0xFFFFFFFFu;
            unsigned mm = __match_any_sync(0xffffffffu, bin);
            if (bin != 0xFFFFFFFFu && (__ffs(mm) - 1) == lane)
                atomicAdd(&hist[bin], __popc(mm));
        }
        __syncthreads();
        if (tid == 0) {
            int k = (int)ctrl[1]; unsigned cum = 0u; int sel = 0;
            for (int b2 = 255; b2 >= 0; b2--) {
                unsigned h2 = hist[b2];
                if (cum + h2 >= (unsigned)k) { sel = b2; break; }
                cum += h2;
            }
            ctrl[1] = (unsigned)(k - (int)cum);
            ctrl[0] = pref | ((unsigned)sel << shift);
        }
        __syncthreads();
    }
    float t;
    {
        unsigned u = ctrl[0];
        unsigned raw = (u & 0x80000000u) ? (u & 0x7FFFFFFFu) : ~u;
        t = __uint_as_float(raw);
    }
    // select (tid<128) in parallel with Vh load (tid>=128)
    float* Vhs = Kts;   // [128][65], reuse
    if (tid < 128) {
        int n = tid;
        const float* lr = &ll[n*129];
        float rmn = rm_s[n];
        int* lst = g_list + ((size_t)mb*NBR+n)*NBR;
        int c = 0;
        for (int m = 0; m < 128; m++) {
            int dif = n - m; if (dif < 0) dif = -dif;
            float pv = lr[m] - rmn + (dif <= 1 ? 5e3f : 0.f);
            if (pv >= t) lst[c++] = m;
        }
        g_cnt[mb*NBR+n] = c;
    } else {
        for (int i = tid - 128; i < 128*64; i += 128) {
            int m = i >> 6, d = i & 63;
            Vhs[m*65+d] = g_Vh[((size_t)mb*NBR+m)*HD+d];
        }
    }
    __syncthreads();
    // low-res attention over non-selected blocks
    for (int it = 0; it < 64; it++) {
        int nn = tid >> 7;
        int n = it*2 + nn;
        int m = tid & 127;
        int dif = n - m; if (dif < 0) dif = -dif;
        float lv = ll[n*129+m];
        float pv = lv - rm_s[n] + (dif <= 1 ? 5e3f : 0.f);
        float selv = (pv >= t) ? 1e4f : 0.f;
        float a = __expf(lv - rm_s[n] - selv) * tc_sh[m];
        a_sh[nn*128+m] = a;
        float w = a;
        #pragma unroll
        for (int off = 16; off >= 1; off >>= 1) w += __shfl_down_sync(0xffffffffu, w, off);
        if (lane == 0) psum[nn*4 + ((tid >> 5) & 3)] = w;
        __syncthreads();
        if (tid < 128) {
            int nn2 = tid >> 6;
            int n2 = it*2 + nn2;
            int d = tid & 63;
            float s = 0.f;
            const float* ar = &a_sh[nn2*128];
            #pragma unroll 8
            for (int m3 = 0; m3 < 128; m3++) s += ar[m3]*Vhs[m3*65+d];
            g_low_out[((size_t)mb*NBR+n2)*HD+d] = s;
            if (d == 0)
                g_low_norm[mb*NBR+n2] = psum[nn2*4]+psum[nn2*4+1]+psum[nn2*4+2]+psum[nn2*4+3];
        }
        __syncthreads();
    }
}

// ---------------- kernel 6: high-res sparse attention (online softmax, f32x2) ----------------
__global__ __launch_bounds__(256) void highres_kernel(const float* __restrict__ mask)
{
    const int mbn = blockIdx.x;                 // MB*NBR
    const int mb = mbn >> 7, q = mbn & 127;
    const int bb = mb / Hh;
    const int tid = threadIdx.x;                // 256
    const int row = tid >> 3, g8 = tid & 7;
    const int c0 = g8*4, d0 = g8*8;

    __shared__ __align__(16) float Qs[32][68];
    __shared__ __align__(16) float Kt[64][36];
    __shared__ __align__(16) float Vs[32][68];
    __shared__ __align__(16) float Ps[32][33];
    __shared__ float rm[32], sc[32], nrm[32], km[32];

    const int nb = g_cnt[mbn];
    const int* lst = g_list + (size_t)mbn*NBR;

    for (int i = tid; i < 512; i += 256) {
        int r = i >> 4, c4 = i & 15;
        *(float4*)&Qs[r][c4*4] = *(const float4*)&g_Q[((size_t)mb*Ss + q*BLKSZ + r)*HD + c4*4];
    }
    if (tid < 32) { rm[tid] = -1e30f; nrm[tid] = 0.f; }
    ull o[4];
    #pragma unroll
    for (int j = 0; j < 4; j++) o[j] = 0ull;
    __syncthreads();

    for (int it = 0; it < nb; it++) {
        const int kb = lst[it];
        for (int i = tid; i < 512; i += 256) {
            int r = i >> 4, c4 = i & 15;
            float4 kv = *(const float4*)&g_K[((size_t)mb*Ss + kb*BLKSZ + r)*HD + c4*4];
            Kt[c4*4+0][r] = kv.x; Kt[c4*4+1][r] = kv.y;
            Kt[c4*4+2][r] = kv.z; Kt[c4*4+3][r] = kv.w;
            *(float4*)&Vs[r][c4*4] = *(const float4*)&g_V[((size_t)mb*Ss + kb*BLKSZ + r)*HD + c4*4];
        }
        if (tid < 32) km[tid] = mask[(size_t)bb*Ss + kb*BLKSZ + tid];
        __syncthreads();

        ull accp[2] = {0ull, 0ull};
        #pragma unroll
        for (int d4 = 0; d4 < 64; d4 += 4) {
            const float4 qv = *(const float4*)&Qs[row][d4];
            const float qf[4] = {qv.x, qv.y, qv.z, qv.w};
            #pragma unroll
            for (int dd = 0; dd < 4; dd++) {
                const ulonglong2 kk2 = *(const ulonglong2*)&Kt[d4+dd][c0];
                const ull qd = pack2(qf[dd], qf[dd]);
                ffma2(accp[0], qd, kk2.x);
                ffma2(accp[1], qd, kk2.y);
            }
        }
        float s01a, s01b, s23a, s23b;
        unpack2(accp[0], s01a, s01b);
        unpack2(accp[1], s23a, s23b);
        float sj[4] = {s01a*0.125f, s01b*0.125f, s23a*0.125f, s23b*0.125f};

        float tm = fmaxf(fmaxf(sj[0], sj[1]), fmaxf(sj[2], sj[3]));
        #pragma unroll
        for (int off = 4; off >= 1; off >>= 1)
            tm = fmaxf(tm, __shfl_down_sync(0xffffffffu, tm, off, 8));
        if (g8 == 0) {
            float nm = fmaxf(rm[row], tm);
            sc[row] = __expf(rm[row] - nm);
            rm[row] = nm;
        }
        __syncthreads();

        const float c = sc[row];
        const ull c2 = pack2(c, c);
        #pragma unroll
        for (int j = 0; j < 4; j++) o[j] = fmul2(o[j], c2);
        const float rmr = rm[row];
        float ps = 0.f;
        #pragma unroll
        for (int j = 0; j < 4; j++) {
            float p = __expf(sj[j] - rmr - 1e4f*(1.0f - km[c0+j]));
            Ps[row][c0+j] = p;
            ps += p;
        }
        #pragma unroll
        for (int off = 4; off >= 1; off >>= 1)
            ps += __shfl_down_sync(0xffffffffu, ps, off, 8);
        if (g8 == 0) nrm[row] = nrm[row]*c + ps;
        __syncthreads();

        #pragma unroll 8
        for (int kk = 0; kk < BLKSZ; kk++) {
            const float pv = Ps[row][kk];
            const ull p2 = pack2(pv, pv);
            const ulonglong2 v0 = *(const ulonglong2*)&Vs[kk][d0];
            const ulonglong2 v1 = *(const ulonglong2*)&Vs[kk][d0+4];
            ffma2(o[0], p2, v0.x); ffma2(o[1], p2, v0.y);
            ffma2(o[2], p2, v1.x); ffma2(o[3], p2, v1.y);
        }
        __syncthreads();
    }

    float of[8];
    unpack2(o[0], of[0], of[1]); unpack2(o[1], of[2], of[3]);
    unpack2(o[2], of[4], of[5]); unpack2(o[3], of[6], of[7]);
    float* op = &g_high_out[((size_t)mb*Ss + q*BLKSZ + row)*HD + d0];
    *(float4*)(op)     = make_float4(of[0], of[1], of[2], of[3]);
    *(float4*)(op + 4) = make_float4(of[4], of[5], of[6], of[7]);
    if (tid < 32) {
        g_maxrows[(size_t)mb*Ss + q*BLKSZ + tid] = fmaxf(rm[tid], -1e6f);
        g_high_norm[(size_t)mb*Ss + q*BLKSZ + tid] = nrm[tid];
    }
}

// ---------------- kernel 8: combine + final layout ----------------
__global__ void combine_kernel(const float* __restrict__ mask, float* __restrict__ out)
{
    int mb = blockIdx.y;
    int tid = threadIdx.x;                 // 256 = 4 tokens x 64 dims
    int s = blockIdx.x*4 + (tid >> 6);
    int hd = tid & 63;
    int bb = mb / Hh, h = mb % Hh;
    int blk = s >> 5;
    float mval = mask[(size_t)bb*Ss + s];
    float lcl = (g_rowmax[mb*NBR + blk] - g_maxrows[(size_t)mb*Ss + s]) * mval;
    float lcorr = __expf(fminf(lcl, 0.f));
    float hcorr = __expf(-fmaxf(lcl, 0.f));
    float hn = g_high_norm[(size_t)mb*Ss + s];
    float ln = g_low_norm[mb*NBR + blk];
    float inv = 1.0f / (hn*hcorr + ln*lcorr + 1e-6f);
    float val = (g_high_out[((size_t)mb*Ss + s)*HD + hd]*hcorr
               + g_low_out[((size_t)mb*NBR + blk)*HD + hd]*lcorr) * inv;
    out[((size_t)bb*Ss + s)*Dm + h*HD + hd] = val;
}

// ---------------- launch ----------------
extern "C" void kernel_launch(void* const* d_in, const int* in_sizes, int n_in,
                              void* d_out, int out_size)
{
    const float* X    = (const float*)d_in[0];
    const float* mask = (const float*)d_in[1];
    const float* Wq   = (const float*)d_in[2];
    const float* bq   = (const float*)d_in[3];
    const float* Wk   = (const float*)d_in[4];
    const float* bk   = (const float*)d_in[5];
    const float* Wv   = (const float*)d_in[6];
    const float* bv   = (const float*)d_in[7];
    float* out = (float*)d_out;

    cudaFuncSetAttribute(qkv_mma_kernel, cudaFuncAttributeMaxDynamicSharedMemorySize, GEMM_SMEM);
    cudaFuncSetAttribute(lowstage_kernel, cudaFuncAttributeMaxDynamicSharedMemorySize, LS_SMEM);

    convX_kernel<<<MROWS*Dm/1024, 256>>>(X);                       // 1
    convW_kernel<<<dim3(Dm*Dm/1024, 3), 256>>>(Wq, Wk, Wv);        // 2
    xbar_kernel<<<Bb*NBR, Dm>>>(X, mask);                          // 3
    qkv_mma_kernel<<<dim3(MROWS/128, 9), 256, GEMM_SMEM>>>(mask, bq, bk, bv);  // 4 (profiled slot)
    hmean_gemm_kernel<<<dim3(2, 6, 3), 256>>>(Wq, Wk, Wv, bq, bk, bv);         // 5
    lowstage_kernel<<<MBT, 256, LS_SMEM>>>();                      // 6
    highres_kernel<<<MBT*NBR, 256>>>(mask);                        // 7
    combine_kernel<<<dim3(Ss/4, MBT), 256>>>(mask, out);           // 8
}

// round 6
// speedup vs baseline: 1.0309x; 1.0309x over previous
#include <cuda_runtime.h>
#include <cuda_bf16.h>
#include <cstdint>

// ---------------- problem constants ----------------
#define Bb 2
#define Ss 4096
#define Dm 768
#define Hh 12
#define HD 64
#define BLKSZ 32
#define NBR 128
#define NUMBLK 1024
#define MBT (Bb*Hh)        // 24
#define MROWS (Bb*Ss)      // 8192

typedef unsigned long long ull;

// ---------------- f32x2 helpers ----------------
__device__ __forceinline__ void ffma2(ull &d, ull a, ull b) {
    asm("fma.rn.f32x2 %0, %1, %2, %0;" : "+l"(d) : "l"(a), "l"(b));
}
__device__ __forceinline__ ull fmul2(ull a, ull b) {
    ull d; asm("mul.rn.f32x2 %0, %1, %2;" : "=l"(d) : "l"(a), "l"(b)); return d;
}
__device__ __forceinline__ ull pack2(float x, float y) {
    ull r; asm("mov.b64 %0, {%1, %2};" : "=l"(r) : "f"(x), "f"(y)); return r;
}
__device__ __forceinline__ void unpack2(ull v, float &x, float &y) {
    asm("mov.b64 {%0, %1}, %2;" : "=f"(x), "=f"(y) : "l"(v));
}

__device__ __forceinline__ uint32_t smem_u32(const void* p) {
    uint32_t a;
    asm("{ .reg .u64 t; cvta.to.shared.u64 t, %1; cvt.u32.u64 %0, t; }" : "=r"(a) : "l"(p));
    return a;
}

// ---------------- mma.sync helpers ----------------
__device__ __forceinline__ void ldsm4(uint32_t &r0, uint32_t &r1, uint32_t &r2, uint32_t &r3, uint32_t addr) {
    asm volatile("ldmatrix.sync.aligned.m8n8.x4.shared.b16 {%0,%1,%2,%3}, [%4];"
        : "=r"(r0), "=r"(r1), "=r"(r2), "=r"(r3) : "r"(addr));
}
__device__ __forceinline__ void mma16816(float* c,
    uint32_t a0, uint32_t a1, uint32_t a2, uint32_t a3, uint32_t b0, uint32_t b1) {
    asm volatile("mma.sync.aligned.m16n8k16.row.col.f32.bf16.bf16.f32 "
        "{%0,%1,%2,%3}, {%4,%5,%6,%7}, {%8,%9}, {%0,%1,%2,%3};"
        : "+f"(c[0]), "+f"(c[1]), "+f"(c[2]), "+f"(c[3])
        : "r"(a0), "r"(a1), "r"(a2), "r"(a3), "r"(b0), "r"(b1));
}

// ---------------- device scratch ----------------
__device__ float g_Q[MBT*Ss*HD];
__device__ float g_K[MBT*Ss*HD];
__device__ float g_V[MBT*Ss*HD];
__device__ __nv_bfloat16 g_Xh[MROWS*Dm];
__device__ __nv_bfloat16 g_Xl[MROWS*Dm];
__device__ __nv_bfloat16 g_Wh[3*Dm*Dm];
__device__ __nv_bfloat16 g_Wl[3*Dm*Dm];
__device__ float g_Xbar[Bb*NBR*Dm];
__device__ float g_tcb[Bb*NBR];
__device__ float g_tcf[Bb*NBR];
__device__ float g_Qh[MBT*NBR*HD];
__device__ float g_Kh[MBT*NBR*HD];
__device__ float g_Vh[MBT*NBR*HD];
__device__ float g_ll[MBT*NBR*NBR];
__device__ float g_prior[MBT*NBR*NBR];
__device__ float g_rowmax[MBT*NBR];
__device__ float g_thresh[MBT];
__device__ int   g_cnt[MBT*NBR];
__device__ int   g_list[MBT*NBR*NBR];
__device__ float g_high_out[MBT*Ss*HD];
__device__ float g_high_norm[MBT*Ss];
__device__ float g_maxrows[MBT*Ss];
__device__ float g_low_out[MBT*NBR*HD];
__device__ float g_low_norm[MBT*NBR];

__device__ __forceinline__ unsigned f2ord(float f) {
    unsigned u = __float_as_uint(f);
    return (u & 0x80000000u) ? ~u : (u | 0x80000000u);
}

// ---------------- kernel 0a: split X into bf16 hi/lo ----------------
__global__ void convX_kernel(const float* __restrict__ X)
{
    int i = (blockIdx.x*256 + threadIdx.x)*4;
    float4 v = *(const float4*)(X + i);
    float vf[4] = {v.x, v.y, v.z, v.w};
    __nv_bfloat16 h[4], l[4];
    #pragma unroll
    for (int j = 0; j < 4; j++) {
        h[j] = __float2bfloat16(vf[j]);
        l[j] = __float2bfloat16(vf[j] - __bfloat162float(h[j]));
    }
    *(ull*)(g_Xh + i) = *(ull*)h;
    *(ull*)(g_Xl + i) = *(ull*)l;
}

// ---------------- kernel 0b: split W into bf16 hi/lo ----------------
__global__ void convW_kernel(const float* __restrict__ Wq,
                             const float* __restrict__ Wk,
                             const float* __restrict__ Wv)
{
    int mat = blockIdx.y;
    const float* W = (mat == 0) ? Wq : (mat == 1) ? Wk : Wv;
    int i = (blockIdx.x*256 + threadIdx.x)*4;
    float4 v = *(const float4*)(W + i);
    float vf[4] = {v.x, v.y, v.z, v.w};
    __nv_bfloat16 h[4], l[4];
    #pragma unroll
    for (int j = 0; j < 4; j++) {
        h[j] = __float2bfloat16(vf[j]);
        l[j] = __float2bfloat16(vf[j] - __bfloat162float(h[j]));
    }
    size_t o = (size_t)mat*Dm*Dm + i;
    *(ull*)(g_Wh + o) = *(ull*)h;
    *(ull*)(g_Wl + o) = *(ull*)l;
}

// ---------------- kernel 0c: masked block-mean of X ----------------
__global__ void xbar_kernel(const float* __restrict__ X, const float* __restrict__ mask)
{
    int bn = blockIdx.x;             // Bb*NBR
    int bb = bn >> 7, n = bn & 127;
    int d = threadIdx.x;             // 768
    const float* mrow = mask + (size_t)bb*Ss + n*BLKSZ;
    float tc = 0.f;
    #pragma unroll
    for (int t = 0; t < BLKSZ; t++) tc += mrow[t];
    float denom = tc + 1e-6f;
    const float* xp = X + ((size_t)bb*Ss + n*BLKSZ)*Dm + d;
    float s = 0.f;
    #pragma unroll 4
    for (int t = 0; t < BLKSZ; t++) s += mrow[t]*xp[(size_t)t*Dm];
    g_Xbar[(size_t)bn*Dm + d] = s/denom;
    if (d == 0) { g_tcb[bn] = tc; g_tcf[bn] = tc/denom; }
}

// ---------------- kernel 1: QKV projection via mma.sync bf16 (3-term split, 3-stage) ----------------
#define BUFA_L 10240
#define BUFB_H 20480
#define BUFB_L 40960
#define BUF_STRIDE 61440
#define GEMM_SMEM (3*BUF_STRIDE)

__global__ __launch_bounds__(256, 1) void qkv_mma_kernel(
    const float* __restrict__ mask,
    const float* __restrict__ bq, const float* __restrict__ bk, const float* __restrict__ bv)
{
    extern __shared__ __align__(16) char smem[];
    const uint32_t sb = smem_u32(smem);
    const int tid = threadIdx.x, lane = tid & 31, wid = tid >> 5;
    const int m0 = blockIdx.x * 128;
    const int tile = blockIdx.y;          // 0..8
    const int mat = tile / 3;
    const int n0 = (tile % 3) * 256;
    const int wm = wid & 1;
    const int wn = wid >> 1;

    const uint4* XH = (const uint4*)g_Xh;
    const uint4* XL = (const uint4*)g_Xl;
    const uint4* WH = (const uint4*)(g_Wh + (size_t)mat*Dm*Dm);
    const uint4* WL = (const uint4*)(g_Wl + (size_t)mat*Dm*Dm);
    const float* bias = (mat == 0) ? bq : (mat == 1) ? bk : bv;
    float* out = (mat == 0) ? g_Q : (mat == 1) ? g_K : g_V;

    float acc[4][8][4];
    #pragma unroll
    for (int a = 0; a < 4; a++)
        #pragma unroll
        for (int b = 0; b < 8; b++)
            #pragma unroll
            for (int c = 0; c < 4; c++) acc[a][b][c] = 0.f;

    const int arow = tid >> 2, ac = tid & 3;

    #define ISSUE_STAGE(s) do { \
        const int _buf = (s) % 3; \
        const uint32_t _bb = sb + _buf*BUF_STRIDE; \
        const int _kc4 = (s)*4; \
        _Pragma("unroll") \
        for (int _i = 0; _i < 2; _i++) { \
            int _row = arow + _i*64; \
            uint32_t _so = _bb + _row*80 + ac*16; \
            const void* _gh = &XH[(size_t)(m0 + _row)*96 + _kc4 + ac]; \
            const void* _gl = &XL[(size_t)(m0 + _row)*96 + _kc4 + ac]; \
            asm volatile("cp.async.cg.shared.global [%0], [%1], 16;" :: "r"(_so), "l"(_gh)); \
            asm volatile("cp.async.cg.shared.global [%0], [%1], 16;" :: "r"(_so + BUFA_L), "l"(_gl)); \
        } \
        _Pragma("unroll") \
        for (int _i = 0; _i < 4; _i++) { \
            int _row = arow + _i*64; \
            uint32_t _so = _bb + BUFB_H + _row*80 + ac*16; \
            const void* _gh = &WH[(size_t)(n0 + _row)*96 + _kc4 + ac]; \
            const void* _gl = &WL[(size_t)(n0 + _row)*96 + _kc4 + ac]; \
            asm volatile("cp.async.cg.shared.global [%0], [%1], 16;" :: "r"(_so), "l"(_gh)); \
            asm volatile("cp.async.cg.shared.global [%0], [%1], 16;" :: "r"(_so + (BUFB_L - BUFB_H)), "l"(_gl)); \
        } \
        asm volatile("cp.async.commit_group;" ::: "memory"); \
    } while (0)

    ISSUE_STAGE(0);
    ISSUE_STAGE(1);

    for (int s = 0; s < 24; s++) {
        if (s < 23) { asm volatile("cp.async.wait_group 1;" ::: "memory"); }
        else        { asm volatile("cp.async.wait_group 0;" ::: "memory"); }
        __syncthreads();
        if (s + 2 < 24) ISSUE_STAGE(s + 2);
        const uint32_t base = sb + (s % 3)*BUF_STRIDE;

        #pragma unroll
        for (int kk = 0; kk < 2; kk++) {
            const uint32_t koff = kk*32;
            uint32_t ah[4][4], al[4][4];
            #pragma unroll
            for (int mt = 0; mt < 4; mt++) {
                int row = wm*64 + mt*16 + (lane & 7) + ((lane >> 3) & 1)*8;
                uint32_t ad = base + row*80 + koff + (lane >> 4)*16;
                ldsm4(ah[mt][0], ah[mt][1], ah[mt][2], ah[mt][3], ad);
                ldsm4(al[mt][0], al[mt][1], al[mt][2], al[mt][3], ad + BUFA_L);
            }
            #pragma unroll
            for (int np = 0; np < 4; np++) {
                int n = wn*64 + np*16 + (lane & 7) + (lane >> 4)*8;
                uint32_t bd = base + BUFB_H + n*80 + koff + ((lane >> 3) & 1)*16;
                uint32_t b0, b1, b2, b3;
                ldsm4(b0, b1, b2, b3, bd);
                #pragma unroll
                for (int mt = 0; mt < 4; mt++) {
                    mma16816(acc[mt][np*2],   ah[mt][0], ah[mt][1], ah[mt][2], ah[mt][3], b0, b1);
                    mma16816(acc[mt][np*2+1], ah[mt][0], ah[mt][1], ah[mt][2], ah[mt][3], b2, b3);
                    mma16816(acc[mt][np*2],   al[mt][0], al[mt][1], al[mt][2], al[mt][3], b0, b1);
                    mma16816(acc[mt][np*2+1], al[mt][0], al[mt][1], al[mt][2], al[mt][3], b2, b3);
                }
            }
            #pragma unroll
            for (int np = 0; np < 4; np++) {
                int n = wn*64 + np*16 + (lane & 7) + (lane >> 4)*8;
                uint32_t bd = base + BUFB_L + n*80 + koff + ((lane >> 3) & 1)*16;
                uint32_t b0, b1, b2, b3;
                ldsm4(b0, b1, b2, b3, bd);
                #pragma unroll
                for (int mt = 0; mt < 4; mt++) {
                    mma16816(acc[mt][np*2],   ah[mt][0], ah[mt][1], ah[mt][2], ah[mt][3], b0, b1);
                    mma16816(acc[mt][np*2+1], ah[mt][0], ah[mt][1], ah[mt][2], ah[mt][3], b2, b3);
                }
            }
        }
    }

    const int h = (n0 + wn*64) >> 6;
    const float* bp = bias + n0 + wn*64;
    float2 bias2[8];
    #pragma unroll
    for (int nt = 0; nt < 8; nt++) bias2[nt] = *(const float2*)(bp + nt*8 + (lane & 3)*2);

    #pragma unroll
    for (int mt = 0; mt < 4; mt++) {
        #pragma unroll
        for (int half = 0; half < 2; half++) {
            int m = m0 + wm*64 + mt*16 + (lane >> 2) + half*8;
            int bbm = m >> 12, sx = m & 4095;
            float mv = mask[(size_t)bbm*Ss + sx];
            float* op = out + ((size_t)(bbm*Hh + h)*Ss + sx)*HD;
            #pragma unroll
            for (int nt = 0; nt < 8; nt++) {
                int col = nt*8 + (lane & 3)*2;
                float2 w;
                w.x = (acc[mt][nt][half*2+0] + bias2[nt].x)*mv;
                w.y = (acc[mt][nt][half*2+1] + bias2[nt].y)*mv;
                *(float2*)(op + col) = w;
            }
        }
    }
}

// ---------------- kernel 1b: exact fp32 block-mean projection (f32x2 GEMM) ----------------
__global__ __launch_bounds__(256) void hmean_gemm_kernel(
    const float* __restrict__ Wq, const float* __restrict__ Wk, const float* __restrict__ Wv,
    const float* __restrict__ bq, const float* __restrict__ bk, const float* __restrict__ bv)
{
    __shared__ __align__(16) float As[2][8][136];
    __shared__ __align__(16) float Bs[2][8][136];

    const int mat = blockIdx.z;
    const float* W = (mat == 0) ? Wq : (mat == 1) ? Wk : Wv;
    const float* bias = (mat == 0) ? bq : (mat == 1) ? bk : bv;
    float* out = (mat == 0) ? g_Qh : (mat == 1) ? g_Kh : g_Vh;

    const int tid = threadIdx.x;
    const int r0 = blockIdx.x * 128;
    const int e0 = blockIdx.y * 128;
    const int lrow = tid >> 1;
    const int lhalf = tid & 1;
    const int ty = tid >> 4;
    const int tx = tid & 15;

    const float4* Ag = (const float4*)(g_Xbar + (size_t)(r0 + lrow)*Dm);
    const float4* Bg = (const float4*)(W + (size_t)(e0 + lrow)*Dm);

    float4 ra = Ag[lhalf];
    float4 rb = Bg[lhalf];

    ull acc[4][8];
    #pragma unroll
    for (int i = 0; i < 4; i++)
        #pragma unroll
        for (int j = 0; j < 8; j++) acc[i][j] = 0ull;

    for (int it = 0; it < 96; ++it) {
        const int buf = it & 1;
        As[buf][lhalf*4+0][lrow] = ra.x;
        As[buf][lhalf*4+1][lrow] = ra.y;
        As[buf][lhalf*4+2][lrow] = ra.z;
        As[buf][lhalf*4+3][lrow] = ra.w;
        Bs[buf][lhalf*4+0][lrow] = rb.x;
        Bs[buf][lhalf*4+1][lrow] = rb.y;
        Bs[buf][lhalf*4+2][lrow] = rb.z;
        Bs[buf][lhalf*4+3][lrow] = rb.w;
        __syncthreads();
        if (it < 95) {
            ra = Ag[(it+1)*2 + lhalf];
            rb = Bg[(it+1)*2 + lhalf];
        }
        #pragma unroll
        for (int kk = 0; kk < 8; kk++) {
            const ulonglong2 a01 = *(const ulonglong2*)&As[buf][kk][ty*8];
            const ulonglong2 a23 = *(const ulonglong2*)&As[buf][kk][ty*8+4];
            ull av[4] = {a01.x, a01.y, a23.x, a23.y};
            const float4 b0 = *(const float4*)&Bs[buf][kk][tx*8];
            const float4 b1 = *(const float4*)&Bs[buf][kk][tx*8+4];
            ull bv2[8];
            bv2[0] = pack2(b0.x, b0.x); bv2[1] = pack2(b0.y, b0.y);
            bv2[2] = pack2(b0.z, b0.z); bv2[3] = pack2(b0.w, b0.w);
            bv2[4] = pack2(b1.x, b1.x); bv2[5] = pack2(b1.y, b1.y);
            bv2[6] = pack2(b1.z, b1.z); bv2[7] = pack2(b1.w, b1.w);
            #pragma unroll
            for (int i = 0; i < 4; i++)
                #pragma unroll
                for (int j = 0; j < 8; j++)
                    ffma2(acc[i][j], av[i], bv2[j]);
        }
        __syncthreads();
    }

    #pragma unroll
    for (int i = 0; i < 4; i++) {
        float vlo[8], vhi[8];
        #pragma unroll
        for (int j = 0; j < 8; j++) unpack2(acc[i][j], vlo[j], vhi[j]);
        #pragma unroll
        for (int ln = 0; ln < 2; ln++) {
            const int r = r0 + ty*8 + i*2 + ln;
            const int bb2 = r >> 7, n = r & 127;
            const float tcf = g_tcf[r];
            const float* vv = ln ? vhi : vlo;
            #pragma unroll
            for (int j = 0; j < 8; j++) {
                int e = e0 + tx*8 + j;
                int hh = e >> 6, hd = e & 63;
                out[(((size_t)(bb2*Hh + hh))*NBR + n)*HD + hd] = vv[j] + bias[e]*tcf;
            }
        }
    }
}

// ---------------- kernel 3: low-res logits + row max + prior ----------------
__global__ void lowlogit_kernel()
{
    int mb = blockIdx.y, n = blockIdx.x, tid = threadIdx.x;   // 128 threads
    int bb = mb / Hh;
    __shared__ float Khs[NBR][65];
    __shared__ float qv[HD];
    __shared__ float red[NBR];
    for (int i = tid; i < NBR*HD; i += 128) {
        int r = i >> 6, d = i & 63;
        Khs[r][d] = g_Kh[((size_t)mb*NBR + r)*HD + d];
    }
    if (tid < HD) qv[tid] = g_Qh[((size_t)mb*NBR + n)*HD + tid];
    __syncthreads();

    int m = tid;
    float s = 0.f;
    #pragma unroll 8
    for (int d = 0; d < HD; d++) s += qv[d]*Khs[m][d];
    s *= 0.125f;
    red[m] = s;
    __syncthreads();
    for (int off = 64; off >= 1; off >>= 1) {
        if (tid < off) red[tid] = fmaxf(red[tid], red[tid + off]);
        __syncthreads();
    }
    float rm = red[0];

    float tcn = g_tcb[bb*NBR + n], tcm = g_tcb[bb*NBR + m];
    float pe = (tcn*tcm < 0.5f) ? 1.0f : 0.0f;
    float ll = s - 1e4f*pe;
    float prior = ll - rm;
    int dif = n - m; if (dif < 0) dif = -dif;
    if (dif <= 1) prior += 5e3f;    // DIAG_N=3 -> off=1; FIRST_N=0
    size_t idx = ((size_t)mb*NBR + n)*NBR + m;
    g_ll[idx] = ll;
    g_prior[idx] = prior;
    if (m == 0) g_rowmax[mb*NBR + n] = rm;
}

// ---------------- kernel 4: exact 1024-th largest via byte radix select ----------------
__global__ void thresh_kernel()
{
    int mb = blockIdx.x;
    const float* pr = g_prior + (size_t)mb*NBR*NBR;
    __shared__ unsigned hist[256];
    __shared__ unsigned s_prefix;
    __shared__ int s_k;
    int tid = threadIdx.x;   // 256
    int lane = tid & 31;
    if (tid == 0) { s_prefix = 0u; s_k = NUMBLK; }
    for (int pass = 0; pass < 4; pass++) {
        int shift = 24 - pass*8;
        hist[tid] = 0u;
        __syncthreads();
        unsigned pref = s_prefix;
        for (int i = tid; i < NBR*NBR; i += 256) {
            unsigned u = f2ord(pr[i]);
            bool ok = (pass == 0) ? true : (((u ^ pref) >> (shift + 8)) == 0u);
            unsigned bin = ok ? ((u >> shift) & 255u) : 0xFFFFFFFFu;
            unsigned mm = __match_any_sync(0xffffffffu, bin);
            if (bin != 0xFFFFFFFFu && (__ffs(mm) - 1) == lane)
                atomicAdd(&hist[bin], __popc(mm));
        }
        __syncthreads();
        if (tid == 0) {
            int k = s_k; unsigned cum = 0u; int sel = 0;
            for (int bbin = 255; bbin >= 0; bbin--) {
                unsigned h = hist[bbin];
                if (cum + h >= (unsigned)k) { sel = bbin; break; }
                cum += h;
            }
            s_k = k - (int)cum;
            s_prefix = pref | ((unsigned)sel << shift);
        }
        __syncthreads();
    }
    if (tid == 0) {
        unsigned u = s_prefix;
        unsigned raw = (u & 0x80000000u) ? (u & 0x7FFFFFFFu) : ~u;
        g_thresh[mb] = __uint_as_float(raw);
    }
}

// ---------------- kernel 5: deterministic per-(mb,q) selected k-block lists ----------------
__global__ void select_kernel()
{
    int mb = blockIdx.x;
    int n = threadIdx.x;           // 128
    float t = g_thresh[mb];
    const float* pr = g_prior + ((size_t)mb*NBR + n)*NBR;
    int* lst = g_list + ((size_t)mb*NBR + n)*NBR;
    int c = 0;
    for (int m = 0; m < NBR; m++)
        if (pr[m] >= t) lst[c++] = m;
    g_cnt[mb*NBR + n] = c;
}

// ---------------- kernel 6: high-res sparse attention (warp-local online softmax) ----------------
__global__ __launch_bounds__(256) void highres_kernel(const float* __restrict__ mask)
{
    const int mbn = blockIdx.x;                 // MB*NBR
    const int mb = mbn >> 7, q = mbn & 127;
    const int bb = mb / Hh;
    const int tid = threadIdx.x;                // 256
    const int row = tid >> 3, g8 = tid & 7;
    const int c0 = g8*4, d0 = g8*8;

    __shared__ __align__(16) float Qs[32][68];
    __shared__ __align__(16) float Kt[64][36];
    __shared__ __align__(16) float Vs[32][68];
    __shared__ __align__(16) float Ps[32][33];
    __shared__ float km[32];

    const int nb = g_cnt[mbn];
    const int* lst = g_list + (size_t)mbn*NBR;

    for (int i = tid; i < 512; i += 256) {
        int r = i >> 4, c4 = i & 15;
        *(float4*)&Qs[r][c4*4] = *(const float4*)&g_Q[((size_t)mb*Ss + q*BLKSZ + r)*HD + c4*4];
    }
    float rmv = -1e30f, nrmv = 0.f;
    ull o[4];
    #pragma unroll
    for (int j = 0; j < 4; j++) o[j] = 0ull;
    __syncthreads();

    for (int it = 0; it < nb; it++) {
        const int kb = lst[it];
        if (it) __syncthreads();   // all warps done reading previous K/V
        for (int i = tid; i < 512; i += 256) {
            int r = i >> 4, c4 = i & 15;
            float4 kv = *(const float4*)&g_K[((size_t)mb*Ss + kb*BLKSZ + r)*HD + c4*4];
            Kt[c4*4+0][r] = kv.x; Kt[c4*4+1][r] = kv.y;
            Kt[c4*4+2][r] = kv.z; Kt[c4*4+3][r] = kv.w;
            *(float4*)&Vs[r][c4*4] = *(const float4*)&g_V[((size_t)mb*Ss + kb*BLKSZ + r)*HD + c4*4];
        }
        if (tid < 32) km[tid] = mask[(size_t)bb*Ss + kb*BLKSZ + tid];
        __syncthreads();

        ull accp[2] = {0ull, 0ull};
        #pragma unroll
        for (int d4 = 0; d4 < 64; d4 += 4) {
            const float4 qv = *(const float4*)&Qs[row][d4];
            const float qf[4] = {qv.x, qv.y, qv.z, qv.w};
            #pragma unroll
            for (int dd = 0; dd < 4; dd++) {
                const ulonglong2 kk2 = *(const ulonglong2*)&Kt[d4+dd][c0];
                const ull qd = pack2(qf[dd], qf[dd]);
                ffma2(accp[0], qd, kk2.x);
                ffma2(accp[1], qd, kk2.y);
            }
        }
        float s01a, s01b, s23a, s23b;
        unpack2(accp[0], s01a, s01b);
        unpack2(accp[1], s23a, s23b);
        float sj[4] = {s01a*0.125f, s01b*0.125f, s23a*0.125f, s23b*0.125f};

        // warp-local (8-lane group) online softmax state
        float tm = fmaxf(fmaxf(sj[0], sj[1]), fmaxf(sj[2], sj[3]));
        #pragma unroll
        for (int off = 4; off >= 1; off >>= 1)
            tm = fmaxf(tm, __shfl_xor_sync(0xffffffffu, tm, off, 8));
        const float nm = fmaxf(rmv, tm);
        const float scv = __expf(rmv - nm);
        rmv = nm;
        const ull c2 = pack2(scv, scv);
        #pragma unroll
        for (int j = 0; j < 4; j++) o[j] = fmul2(o[j], c2);
        float ps = 0.f;
        #pragma unroll
        for (int j = 0; j < 4; j++) {
            float p = __expf(sj[j] - rmv - 1e4f*(1.0f - km[c0+j]));
            Ps[row][c0+j] = p;
            ps += p;
        }
        #pragma unroll
        for (int off = 4; off >= 1; off >>= 1)
            ps += __shfl_xor_sync(0xffffffffu, ps, off, 8);
        nrmv = nrmv*scv + ps;
        __syncwarp();   // Ps row visible to all 8 lanes (same warp)

        #pragma unroll 8
        for (int kk = 0; kk < BLKSZ; kk++) {
            const float pv = Ps[row][kk];
            const ull p2 = pack2(pv, pv);
            const ulonglong2 v0 = *(const ulonglong2*)&Vs[kk][d0];
            const ulonglong2 v1 = *(const ulonglong2*)&Vs[kk][d0+4];
            ffma2(o[0], p2, v0.x); ffma2(o[1], p2, v0.y);
            ffma2(o[2], p2, v1.x); ffma2(o[3], p2, v1.y);
        }
    }

    float of[8];
    unpack2(o[0], of[0], of[1]); unpack2(o[1], of[2], of[3]);
    unpack2(o[2], of[4], of[5]); unpack2(o[3], of[6], of[7]);
    float* op = &g_high_out[((size_t)mb*Ss + q*BLKSZ + row)*HD + d0];
    *(float4*)(op)     = make_float4(of[0], of[1], of[2], of[3]);
    *(float4*)(op + 4) = make_float4(of[4], of[5], of[6], of[7]);
    if (g8 == 0) {
        g_maxrows[(size_t)mb*Ss + q*BLKSZ + row] = fmaxf(rmv, -1e6f);
        g_high_norm[(size_t)mb*Ss + q*BLKSZ + row] = nrmv;
    }
}

// ---------------- kernel 7: low-res attention over non-selected blocks ----------------
__global__ void lowres_kernel()
{
    int mb = blockIdx.y, n = blockIdx.x, tid = threadIdx.x;   // 128
    int bb = mb / Hh;
    __shared__ float a_sh[NBR];
    __shared__ float red[NBR];
    float rmv = g_rowmax[mb*NBR + n];
    float t = g_thresh[mb];
    size_t idx = ((size_t)mb*NBR + n)*NBR + tid;
    float ll = g_ll[idx];
    float sel = (g_prior[idx] >= t) ? 1e4f : 0.f;
    float a = __expf(ll - rmv - sel) * g_tcb[bb*NBR + tid];
    a_sh[tid] = a; red[tid] = a;
    __syncthreads();
    for (int off = 64; off >= 1; off >>= 1) {
        if (tid < off) red[tid] += red[tid + off];
        __syncthreads();
    }
    if (tid == 0) g_low_norm[mb*NBR + n] = red[0];
    if (tid < HD) {
        float s = 0.f;
        #pragma unroll 8
        for (int m = 0; m < NBR; m++)
            s += a_sh[m] * g_Vh[((size_t)mb*NBR + m)*HD + tid];
        g_low_out[((size_t)mb*NBR + n)*HD + tid] = s;
    }
}

// ---------------- kernel 8: combine + final layout ----------------
__global__ void combine_kernel(const float* __restrict__ mask, float* __restrict__ out)
{
    int mb = blockIdx.y;
    int tid = threadIdx.x;                 // 256 = 4 tokens x 64 dims
    int s = blockIdx.x*4 + (tid >> 6);
    int hd = tid & 63;
    int bb = mb / Hh, h = mb % Hh;
    int blk = s >> 5;
    float mval = mask[(size_t)bb*Ss + s];
    float lcl = (g_rowmax[mb*NBR + blk] - g_maxrows[(size_t)mb*Ss + s]) * mval;
    float lcorr = __expf(fminf(lcl, 0.f));
    float hcorr = __expf(-fmaxf(lcl, 0.f));
    float hn = g_high_norm[(size_t)mb*Ss + s];
    float ln = g_low_norm[mb*NBR + blk];
    float inv = 1.0f / (hn*hcorr + ln*lcorr + 1e-6f);
    float val = (g_high_out[((size_t)mb*Ss + s)*HD + hd]*hcorr
               + g_low_out[((size_t)mb*NBR + blk)*HD + hd]*lcorr) * inv;
    out[((size_t)bb*Ss + s)*Dm + h*HD + hd] = val;
}

// ---------------- launch ----------------
extern "C" void kernel_launch(void* const* d_in, const int* in_sizes, int n_in,
                              void* d_out, int out_size)
{
    const float* X    = (const float*)d_in[0];
    const float* mask = (const float*)d_in[1];
    const float* Wq   = (const float*)d_in[2];
    const float* bq   = (const float*)d_in[3];
    const float* Wk   = (const float*)d_in[4];
    const float* bk   = (const float*)d_in[5];
    const float* Wv   = (const float*)d_in[6];
    const float* bv   = (const float*)d_in[7];
    float* out = (float*)d_out;

    cudaFuncSetAttribute(qkv_mma_kernel, cudaFuncAttributeMaxDynamicSharedMemorySize, GEMM_SMEM);

    convX_kernel<<<MROWS*Dm/1024, 256>>>(X);                       // 1
    convW_kernel<<<dim3(Dm*Dm/1024, 3), 256>>>(Wq, Wk, Wv);        // 2
    xbar_kernel<<<Bb*NBR, Dm>>>(X, mask);                          // 3
    qkv_mma_kernel<<<dim3(MROWS/128, 9), 256, GEMM_SMEM>>>(mask, bq, bk, bv);  // 4
    hmean_gemm_kernel<<<dim3(2, 6, 3), 256>>>(Wq, Wk, Wv, bq, bk, bv);         // 5
    lowlogit_kernel<<<dim3(NBR, MBT), 128>>>();                    // 6
    thresh_kernel<<<MBT, 256>>>();                                 // 7
    select_kernel<<<MBT, 128>>>();                                 // 8
    highres_kernel<<<MBT*NBR, 256>>>(mask);                        // 9
    lowres_kernel<<<dim3(NBR, MBT), 128>>>();                      // 10
    combine_kernel<<<dim3(Ss/4, MBT), 256>>>(mask, out);           // 11
}

// round 7
// speedup vs baseline: 1.1334x; 1.0995x over previous
#include <cuda_runtime.h>
#include <cuda_bf16.h>
#include <cstdint>

// ---------------- problem constants ----------------
#define Bb 2
#define Ss 4096
#define Dm 768
#define Hh 12
#define HD 64
#define BLKSZ 32
#define NBR 128
#define NUMBLK 1024
#define MBT (Bb*Hh)        // 24
#define MROWS (Bb*Ss)      // 8192

typedef unsigned long long ull;

// ---------------- f32x2 helpers ----------------
__device__ __forceinline__ void ffma2(ull &d, ull a, ull b) {
    asm("fma.rn.f32x2 %0, %1, %2, %0;" : "+l"(d) : "l"(a), "l"(b));
}
__device__ __forceinline__ ull fmul2(ull a, ull b) {
    ull d; asm("mul.rn.f32x2 %0, %1, %2;" : "=l"(d) : "l"(a), "l"(b)); return d;
}
__device__ __forceinline__ ull pack2(float x, float y) {
    ull r; asm("mov.b64 %0, {%1, %2};" : "=l"(r) : "f"(x), "f"(y)); return r;
}
__device__ __forceinline__ void unpack2(ull v, float &x, float &y) {
    asm("mov.b64 {%0, %1}, %2;" : "=f"(x), "=f"(y) : "l"(v));
}

__device__ __forceinline__ uint32_t smem_u32(const void* p) {
    uint32_t a;
    asm("{ .reg .u64 t; cvta.to.shared.u64 t, %1; cvt.u32.u64 %0, t; }" : "=r"(a) : "l"(p));
    return a;
}
#define CP_ASYNC16(dst, src) \
    asm volatile("cp.async.cg.shared.global [%0], [%1], 16;" :: "r"(dst), "l"(src))
#define CP_COMMIT() asm volatile("cp.async.commit_group;" ::: "memory")

// ---------------- mma.sync helpers ----------------
__device__ __forceinline__ void ldsm4(uint32_t &r0, uint32_t &r1, uint32_t &r2, uint32_t &r3, uint32_t addr) {
    asm volatile("ldmatrix.sync.aligned.m8n8.x4.shared.b16 {%0,%1,%2,%3}, [%4];"
        : "=r"(r0), "=r"(r1), "=r"(r2), "=r"(r3) : "r"(addr));
}
__device__ __forceinline__ void mma16816(float* c,
    uint32_t a0, uint32_t a1, uint32_t a2, uint32_t a3, uint32_t b0, uint32_t b1) {
    asm volatile("mma.sync.aligned.m16n8k16.row.col.f32.bf16.bf16.f32 "
        "{%0,%1,%2,%3}, {%4,%5,%6,%7}, {%8,%9}, {%0,%1,%2,%3};"
        : "+f"(c[0]), "+f"(c[1]), "+f"(c[2]), "+f"(c[3])
        : "r"(a0), "r"(a1), "r"(a2), "r"(a3), "r"(b0), "r"(b1));
}

// ---------------- device scratch ----------------
__device__ float g_Q[MBT*Ss*HD];
__device__ float g_K[MBT*Ss*HD];
__device__ float g_V[MBT*Ss*HD];
__device__ __nv_bfloat16 g_Xh[MROWS*Dm];
__device__ __nv_bfloat16 g_Xl[MROWS*Dm];
__device__ __nv_bfloat16 g_Wh[3*Dm*Dm];
__device__ __nv_bfloat16 g_Wl[3*Dm*Dm];
__device__ float g_Xbar[Bb*NBR*Dm];
__device__ float g_tcb[Bb*NBR];
__device__ float g_tcf[Bb*NBR];
__device__ float g_Qh[MBT*NBR*HD];
__device__ float g_Kh[MBT*NBR*HD];
__device__ float g_Vh[MBT*NBR*HD];
__device__ float g_ll[MBT*NBR*NBR];
__device__ float g_prior[MBT*NBR*NBR];
__device__ float g_rowmax[MBT*NBR];
__device__ float g_thresh[MBT];
__device__ int   g_cnt[MBT*NBR];
__device__ int   g_list[MBT*NBR*NBR];
__device__ float g_high_out[MBT*Ss*HD];
__device__ float g_high_norm[MBT*Ss];
__device__ float g_maxrows[MBT*Ss];
__device__ float g_low_out[MBT*NBR*HD];
__device__ float g_low_norm[MBT*NBR];

__device__ __forceinline__ unsigned f2ord(float f) {
    unsigned u = __float_as_uint(f);
    return (u & 0x80000000u) ? ~u : (u | 0x80000000u);
}

// ---------------- kernel 0a: split X into bf16 hi/lo ----------------
__global__ void convX_kernel(const float* __restrict__ X)
{
    int i = (blockIdx.x*256 + threadIdx.x)*4;
    float4 v = *(const float4*)(X + i);
    float vf[4] = {v.x, v.y, v.z, v.w};
    __nv_bfloat16 h[4], l[4];
    #pragma unroll
    for (int j = 0; j < 4; j++) {
        h[j] = __float2bfloat16(vf[j]);
        l[j] = __float2bfloat16(vf[j] - __bfloat162float(h[j]));
    }
    *(ull*)(g_Xh + i) = *(ull*)h;
    *(ull*)(g_Xl + i) = *(ull*)l;
}

// ---------------- kernel 0b: split W into bf16 hi/lo ----------------
__global__ void convW_kernel(const float* __restrict__ Wq,
                             const float* __restrict__ Wk,
                             const float* __restrict__ Wv)
{
    int mat = blockIdx.y;
    const float* W = (mat == 0) ? Wq : (mat == 1) ? Wk : Wv;
    int i = (blockIdx.x*256 + threadIdx.x)*4;
    float4 v = *(const float4*)(W + i);
    float vf[4] = {v.x, v.y, v.z, v.w};
    __nv_bfloat16 h[4], l[4];
    #pragma unroll
    for (int j = 0; j < 4; j++) {
        h[j] = __float2bfloat16(vf[j]);
        l[j] = __float2bfloat16(vf[j] - __bfloat162float(h[j]));
    }
    size_t o = (size_t)mat*Dm*Dm + i;
    *(ull*)(g_Wh + o) = *(ull*)h;
    *(ull*)(g_Wl + o) = *(ull*)l;
}

// ---------------- kernel 0c: masked block-mean of X ----------------
__global__ void xbar_kernel(const float* __restrict__ X, const float* __restrict__ mask)
{
    int bn = blockIdx.x;             // Bb*NBR
    int bb = bn >> 7, n = bn & 127;
    int d = threadIdx.x;             // 768
    const float* mrow = mask + (size_t)bb*Ss + n*BLKSZ;
    float tc = 0.f;
    #pragma unroll
    for (int t = 0; t < BLKSZ; t++) tc += mrow[t];
    float denom = tc + 1e-6f;
    const float* xp = X + ((size_t)bb*Ss + n*BLKSZ)*Dm + d;
    float s = 0.f;
    #pragma unroll 4
    for (int t = 0; t < BLKSZ; t++) s += mrow[t]*xp[(size_t)t*Dm];
    g_Xbar[(size_t)bn*Dm + d] = s/denom;
    if (d == 0) { g_tcb[bn] = tc; g_tcf[bn] = tc/denom; }
}

// ---------------- kernel 1: QKV projection via mma.sync bf16 (3-term split) ----------------
// 512 threads, 16 warps of 32(m)x64(n), CTA tile 128x256, BK=32, 3-stage cp.async.
#define BUFA_L 10240
#define BUFB_H 20480
#define BUFB_L 40960
#define BUF_STRIDE 61440
#define GEMM_SMEM (3*BUF_STRIDE)

__global__ __launch_bounds__(512, 1) void qkv_mma_kernel(
    const float* __restrict__ mask,
    const float* __restrict__ bq, const float* __restrict__ bk, const float* __restrict__ bv)
{
    extern __shared__ __align__(16) char smem[];
    const uint32_t sb = smem_u32(smem);
    const int tid = threadIdx.x, lane = tid & 31, wid = tid >> 5;
    const int m0 = blockIdx.x * 128;
    const int tile = blockIdx.y;          // 0..8
    const int mat = tile / 3;
    const int n0 = (tile % 3) * 256;
    const int wm = wid & 3;               // m strip of 32
    const int wn = wid >> 2;              // n strip of 64

    const uint4* XH = (const uint4*)g_Xh;
    const uint4* XL = (const uint4*)g_Xl;
    const uint4* WH = (const uint4*)(g_Wh + (size_t)mat*Dm*Dm);
    const uint4* WL = (const uint4*)(g_Wl + (size_t)mat*Dm*Dm);
    const float* bias = (mat == 0) ? bq : (mat == 1) ? bk : bv;
    float* out = (mat == 0) ? g_Q : (mat == 1) ? g_K : g_V;

    float acc[2][8][4];
    #pragma unroll
    for (int a = 0; a < 2; a++)
        #pragma unroll
        for (int b = 0; b < 8; b++)
            #pragma unroll
            for (int c = 0; c < 4; c++) acc[a][b][c] = 0.f;

    const int arow = tid >> 2, ac = tid & 3;    // arow 0..127

    #define ISSUE_STAGE(s) do { \
        const int _buf = (s) % 3; \
        const uint32_t _bb = sb + _buf*BUF_STRIDE; \
        const int _kc4 = (s)*4; \
        { \
            uint32_t _so = _bb + arow*80 + ac*16; \
            CP_ASYNC16(_so, &XH[(size_t)(m0 + arow)*96 + _kc4 + ac]); \
            CP_ASYNC16(_so + BUFA_L, &XL[(size_t)(m0 + arow)*96 + _kc4 + ac]); \
        } \
        _Pragma("unroll") \
        for (int _i = 0; _i < 2; _i++) { \
            int _row = arow + _i*128; \
            uint32_t _so = _bb + BUFB_H + _row*80 + ac*16; \
            CP_ASYNC16(_so, &WH[(size_t)(n0 + _row)*96 + _kc4 + ac]); \
            CP_ASYNC16(_so + (BUFB_L - BUFB_H), &WL[(size_t)(n0 + _row)*96 + _kc4 + ac]); \
        } \
        CP_COMMIT(); \
    } while (0)

    ISSUE_STAGE(0);
    ISSUE_STAGE(1);

    for (int s = 0; s < 24; s++) {
        if (s < 23) { asm volatile("cp.async.wait_group 1;" ::: "memory"); }
        else        { asm volatile("cp.async.wait_group 0;" ::: "memory"); }
        __syncthreads();
        if (s + 2 < 24) ISSUE_STAGE(s + 2);
        const uint32_t base = sb + (s % 3)*BUF_STRIDE;

        #pragma unroll
        for (int kk = 0; kk < 2; kk++) {
            const uint32_t koff = kk*32;
            uint32_t ah[2][4], al[2][4];
            #pragma unroll
            for (int mt = 0; mt < 2; mt++) {
                int row = wm*32 + mt*16 + (lane & 7) + ((lane >> 3) & 1)*8;
                uint32_t ad = base + row*80 + koff + (lane >> 4)*16;
                ldsm4(ah[mt][0], ah[mt][1], ah[mt][2], ah[mt][3], ad);
                ldsm4(al[mt][0], al[mt][1], al[mt][2], al[mt][3], ad + BUFA_L);
            }
            #pragma unroll
            for (int np = 0; np < 4; np++) {
                int n = wn*64 + np*16 + (lane & 7) + (lane >> 4)*8;
                uint32_t bd = base + BUFB_H + n*80 + koff + ((lane >> 3) & 1)*16;
                uint32_t b0, b1, b2, b3;
                ldsm4(b0, b1, b2, b3, bd);
                #pragma unroll
                for (int mt = 0; mt < 2; mt++) {
                    mma16816(acc[mt][np*2],   ah[mt][0], ah[mt][1], ah[mt][2], ah[mt][3], b0, b1);
                    mma16816(acc[mt][np*2+1], ah[mt][0], ah[mt][1], ah[mt][2], ah[mt][3], b2, b3);
                    mma16816(acc[mt][np*2],   al[mt][0], al[mt][1], al[mt][2], al[mt][3], b0, b1);
                    mma16816(acc[mt][np*2+1], al[mt][0], al[mt][1], al[mt][2], al[mt][3], b2, b3);
                }
            }
            #pragma unroll
            for (int np = 0; np < 4; np++) {
                int n = wn*64 + np*16 + (lane & 7) + (lane >> 4)*8;
                uint32_t bd = base + BUFB_L + n*80 + koff + ((lane >> 3) & 1)*16;
                uint32_t b0, b1, b2, b3;
                ldsm4(b0, b1, b2, b3, bd);
                #pragma unroll
                for (int mt = 0; mt < 2; mt++) {
                    mma16816(acc[mt][np*2],   ah[mt][0], ah[mt][1], ah[mt][2], ah[mt][3], b0, b1);
                    mma16816(acc[mt][np*2+1], ah[mt][0], ah[mt][1], ah[mt][2], ah[mt][3], b2, b3);
                }
            }
        }
    }

    const int h = (n0 + wn*64) >> 6;
    const float* bp = bias + n0 + wn*64;
    float2 bias2[8];
    #pragma unroll
    for (int nt = 0; nt < 8; nt++) bias2[nt] = *(const float2*)(bp + nt*8 + (lane & 3)*2);

    #pragma unroll
    for (int mt = 0; mt < 2; mt++) {
        #pragma unroll
        for (int half = 0; half < 2; half++) {
            int m = m0 + wm*32 + mt*16 + (lane >> 2) + half*8;
            int bbm = m >> 12, sx = m & 4095;
            float mv = mask[(size_t)bbm*Ss + sx];
            float* op = out + ((size_t)(bbm*Hh + h)*Ss + sx)*HD;
            #pragma unroll
            for (int nt = 0; nt < 8; nt++) {
                int col = nt*8 + (lane & 3)*2;
                float2 w;
                w.x = (acc[mt][nt][half*2+0] + bias2[nt].x)*mv;
                w.y = (acc[mt][nt][half*2+1] + bias2[nt].y)*mv;
                *(float2*)(op + col) = w;
            }
        }
    }
}

// ---------------- kernel 1b: exact fp32 block-mean projection (fine-grained tiles) ----------------
// Tile 32(m) x 128(n), BK=32, grid (8, 6, 3) = 144 CTAs (one wave).
__global__ __launch_bounds__(256) void hmean_gemm_kernel(
    const float* __restrict__ Wq, const float* __restrict__ Wk, const float* __restrict__ Wv,
    const float* __restrict__ bq, const float* __restrict__ bk, const float* __restrict__ bv)
{
    __shared__ float As[32][33];
    __shared__ float Bs[128][33];

    const int mat = blockIdx.z;
    const float* W = (mat == 0) ? Wq : (mat == 1) ? Wk : Wv;
    const float* bias = (mat == 0) ? bq : (mat == 1) ? bk : bv;
    float* out = (mat == 0) ? g_Qh : (mat == 1) ? g_Kh : g_Vh;

    const int tid = threadIdx.x;
    const int r0 = blockIdx.x * 32;
    const int e0 = blockIdx.y * 128;
    const int tn = tid >> 4;     // 0..15 col group of 8
    const int tm2 = tid & 15;    // 0..15 row pair

    float acc0[8], acc1[8];
    #pragma unroll
    for (int j = 0; j < 8; j++) { acc0[j] = 0.f; acc1[j] = 0.f; }

    for (int k0 = 0; k0 < Dm; k0 += 32) {
        // A: 32x32 = 256 float4, 1 per thread
        {
            int r = tid >> 3, kq = tid & 7;
            float4 v = *(const float4*)&g_Xbar[(size_t)(r0 + r)*Dm + k0 + kq*4];
            As[r][kq*4+0] = v.x; As[r][kq*4+1] = v.y; As[r][kq*4+2] = v.z; As[r][kq*4+3] = v.w;
        }
        // B: 128x32 = 1024 float4, 4 per thread
        #pragma unroll
        for (int t = 0; t < 4; t++) {
            int idx = tid + t*256;
            int r = idx >> 3, kq = idx & 7;
            float4 v = *(const float4*)&W[(size_t)(e0 + r)*Dm + k0 + kq*4];
            Bs[r][kq*4+0] = v.x; Bs[r][kq*4+1] = v.y; Bs[r][kq*4+2] = v.z; Bs[r][kq*4+3] = v.w;
        }
        __syncthreads();
        #pragma unroll 8
        for (int k = 0; k < 32; k++) {
            float a0 = As[tm2*2][k], a1 = As[tm2*2+1][k];
            #pragma unroll
            for (int j = 0; j < 8; j++) {
                float b = Bs[tn*8+j][k];
                acc0[j] += a0*b;
                acc1[j] += a1*b;
            }
        }
        __syncthreads();
    }

    #pragma unroll
    for (int i = 0; i < 2; i++) {
        const int r = r0 + tm2*2 + i;
        const int bb2 = r >> 7, n = r & 127;
        const float tcf = g_tcf[r];
        const float* av = i ? acc1 : acc0;
        #pragma unroll
        for (int j = 0; j < 8; j++) {
            int e = e0 + tn*8 + j;
            int hh = e >> 6, hd = e & 63;
            out[(((size_t)(bb2*Hh + hh))*NBR + n)*HD + hd] = av[j] + bias[e]*tcf;
        }
    }
}

// ---------------- kernel 3: low-res logits + row max + prior ----------------
__global__ void lowlogit_kernel()
{
    int mb = blockIdx.y, n = blockIdx.x, tid = threadIdx.x;   // 128 threads
    int bb = mb / Hh;
    __shared__ float Khs[NBR][65];
    __shared__ float qv[HD];
    __shared__ float red[NBR];
    for (int i = tid; i < NBR*HD; i += 128) {
        int r = i >> 6, d = i & 63;
        Khs[r][d] = g_Kh[((size_t)mb*NBR + r)*HD + d];
    }
    if (tid < HD) qv[tid] = g_Qh[((size_t)mb*NBR + n)*HD + tid];
    __syncthreads();

    int m = tid;
    float s = 0.f;
    #pragma unroll 8
    for (int d = 0; d < HD; d++) s += qv[d]*Khs[m][d];
    s *= 0.125f;
    red[m] = s;
    __syncthreads();
    for (int off = 64; off >= 1; off >>= 1) {
        if (tid < off) red[tid] = fmaxf(red[tid], red[tid + off]);
        __syncthreads();
    }
    float rm = red[0];

    float tcn = g_tcb[bb*NBR + n], tcm = g_tcb[bb*NBR + m];
    float pe = (tcn*tcm < 0.5f) ? 1.0f : 0.0f;
    float ll = s - 1e4f*pe;
    float prior = ll - rm;
    int dif = n - m; if (dif < 0) dif = -dif;
    if (dif <= 1) prior += 5e3f;    // DIAG_N=3 -> off=1; FIRST_N=0
    size_t idx = ((size_t)mb*NBR + n)*NBR + m;
    g_ll[idx] = ll;
    g_prior[idx] = prior;
    if (m == 0) g_rowmax[mb*NBR + n] = rm;
}

// ---------------- kernel 4: exact 1024-th largest via byte radix select ----------------
__global__ void thresh_kernel()
{
    int mb = blockIdx.x;
    const float* pr = g_prior + (size_t)mb*NBR*NBR;
    __shared__ unsigned hist[256];
    __shared__ unsigned s_prefix;
    __shared__ int s_k;
    int tid = threadIdx.x;   // 256
    int lane = tid & 31;
    if (tid == 0) { s_prefix = 0u; s_k = NUMBLK; }
    for (int pass = 0; pass < 4; pass++) {
        int shift = 24 - pass*8;
        hist[tid] = 0u;
        __syncthreads();
        unsigned pref = s_prefix;
        for (int i = tid; i < NBR*NBR; i += 256) {
            unsigned u = f2ord(pr[i]);
            bool ok = (pass == 0) ? true : (((u ^ pref) >> (shift + 8)) == 0u);
            unsigned bin = ok ? ((u >> shift) & 255u) : 0xFFFFFFFFu;
            unsigned mm = __match_any_sync(0xffffffffu, bin);
            if (bin != 0xFFFFFFFFu && (__ffs(mm) - 1) == lane)
                atomicAdd(&hist[bin], __popc(mm));
        }
        __syncthreads();
        if (tid == 0) {
            int k = s_k; unsigned cum = 0u; int sel = 0;
            for (int bbin = 255; bbin >= 0; bbin--) {
                unsigned h = hist[bbin];
                if (cum + h >= (unsigned)k) { sel = bbin; break; }
                cum += h;
            }
            s_k = k - (int)cum;
            s_prefix = pref | ((unsigned)sel << shift);
        }
        __syncthreads();
    }
    if (tid == 0) {
        unsigned u = s_prefix;
        unsigned raw = (u & 0x80000000u) ? (u & 0x7FFFFFFFu) : ~u;
        g_thresh[mb] = __uint_as_float(raw);
    }
}

// ---------------- kernel 5: deterministic per-(mb,q) selected k-block lists ----------------
__global__ void select_kernel()
{
    int mb = blockIdx.x;
    int n = threadIdx.x;           // 128
    float t = g_thresh[mb];
    const float* pr = g_prior + ((size_t)mb*NBR + n)*NBR;
    int* lst = g_list + ((size_t)mb*NBR + n)*NBR;
    int c = 0;
    for (int m = 0; m < NBR; m++)
        if (pr[m] >= t) lst[c++] = m;
    g_cnt[mb*NBR + n] = c;
}

// ---------------- kernel 6: high-res sparse attention v2 ----------------
// cp.async double-buffered K/V, XOR-swizzled K (no transpose, conflict-free),
// warp-local online softmax. Thread (row, g8) owns cols {g8, g8+8, g8+16, g8+24}
// and output dims d0 = g8*8 .. +7.
__global__ __launch_bounds__(256) void highres_kernel(const float* __restrict__ mask)
{
    const int mbn = blockIdx.x;                 // MB*NBR
    const int mb = mbn >> 7, q = mbn & 127;
    const int bb = mb / Hh;
    const int tid = threadIdx.x;                // 256
    const int row = tid >> 3, g8 = tid & 7;
    const int d0 = g8*8;

    __shared__ __align__(16) float4 Ks[2][32][16];  // [buf][k-row][col4 ^ (r&7)]
    __shared__ __align__(16) float  Vs[2][32][68];
    __shared__ float km[2][32];
    __shared__ __align__(16) float Qs[32][68];
    __shared__ float Ps[32][33];

    const int nb = g_cnt[mbn];
    const int* lst = g_list + (size_t)mbn*NBR;

    for (int i = tid; i < 512; i += 256) {
        int r = i >> 4, c4 = i & 15;
        *(float4*)&Qs[r][c4*4] = *(const float4*)&g_Q[((size_t)mb*Ss + q*BLKSZ + r)*HD + c4*4];
    }

    float rmv = -1e30f, nrmv = 0.f;
    ull o[4];
    #pragma unroll
    for (int j = 0; j < 4; j++) o[j] = 0ull;

    #define HR_LOAD(st, kb) do { \
        _Pragma("unroll") \
        for (int _i = tid; _i < 512; _i += 256) { \
            int _r = _i >> 4, _g = _i & 15; \
            const float4* _ks = (const float4*)&g_K[((size_t)mb*Ss + (kb)*BLKSZ + _r)*HD] + _g; \
            CP_ASYNC16(smem_u32(&Ks[st][_r][_g ^ (_r & 7)]), _ks); \
            const float4* _vsd = (const float4*)&g_V[((size_t)mb*Ss + (kb)*BLKSZ + _r)*HD] + _g; \
            CP_ASYNC16(smem_u32(&Vs[st][_r][_g*4]), _vsd); \
        } \
        if (tid < 8) CP_ASYNC16(smem_u32(&km[st][tid*4]), &mask[(size_t)bb*Ss + (kb)*BLKSZ + tid*4]); \
        CP_COMMIT(); \
    } while (0)

    if (nb > 0) HR_LOAD(0, lst[0]);

    for (int it = 0; it < nb; it++) {
        const int cur = it & 1;
        if (it + 1 < nb) {
            HR_LOAD((it+1) & 1, lst[it+1]);
            asm volatile("cp.async.wait_group 1;" ::: "memory");
        } else {
            asm volatile("cp.async.wait_group 0;" ::: "memory");
        }
        __syncthreads();   // buffer `cur` visible (also covers Qs on first iter)

        // QK: cols c_j = g8 + 8j from swizzled K
        float sj[4] = {0.f, 0.f, 0.f, 0.f};
        #pragma unroll
        for (int d4 = 0; d4 < 16; d4++) {
            const float4 qv = *(const float4*)&Qs[row][d4*4];
            #pragma unroll
            for (int j = 0; j < 4; j++) {
                const float4 kv = Ks[cur][g8 + 8*j][d4 ^ g8];
                sj[j] += qv.x*kv.x + qv.y*kv.y + qv.z*kv.z + qv.w*kv.w;
            }
        }
        #pragma unroll
        for (int j = 0; j < 4; j++) sj[j] *= 0.125f;

        // warp-local (8-lane) online softmax
        float tm = fmaxf(fmaxf(sj[0], sj[1]), fmaxf(sj[2], sj[3]));
        #pragma unroll
        for (int off = 4; off >= 1; off >>= 1)
            tm = fmaxf(tm, __shfl_xor_sync(0xffffffffu, tm, off, 8));
        const float nm = fmaxf(rmv, tm);
        const float scv = __expf(rmv - nm);
        rmv = nm;
        const ull c2 = pack2(scv, scv);
        #pragma unroll
        for (int j = 0; j < 4; j++) o[j] = fmul2(o[j], c2);
        float ps = 0.f;
        #pragma unroll
        for (int j = 0; j < 4; j++) {
            int c = g8 + 8*j;
            float p = __expf(sj[j] - rmv - 1e4f*(1.0f - km[cur][c]));
            Ps[row][c] = p;
            ps += p;
        }
        #pragma unroll
        for (int off = 4; off >= 1; off >>= 1)
            ps += __shfl_xor_sync(0xffffffffu, ps, off, 8);
        nrmv = nrmv*scv + ps;
        __syncwarp();   // Ps row shared among the 8 lanes of this row (same warp)

        // AV
        #pragma unroll 8
        for (int kk = 0; kk < BLKSZ; kk++) {
            const float pv = Ps[row][kk];
            const ull p2 = pack2(pv, pv);
            const ulonglong2 v0 = *(const ulonglong2*)&Vs[cur][kk][d0];
            const ulonglong2 v1 = *(const ulonglong2*)&Vs[cur][kk][d0+4];
            ffma2(o[0], p2, v0.x); ffma2(o[1], p2, v0.y);
            ffma2(o[2], p2, v1.x); ffma2(o[3], p2, v1.y);
        }
        __syncthreads();   // all threads done with buffer `cur` before it's reloaded
    }

    float of[8];
    unpack2(o[0], of[0], of[1]); unpack2(o[1], of[2], of[3]);
    unpack2(o[2], of[4], of[5]); unpack2(o[3], of[6], of[7]);
    float* op = &g_high_out[((size_t)mb*Ss + q*BLKSZ + row)*HD + d0];
    *(float4*)(op)     = make_float4(of[0], of[1], of[2], of[3]);
    *(float4*)(op + 4) = make_float4(of[4], of[5], of[6], of[7]);
    if (g8 == 0) {
        g_maxrows[(size_t)mb*Ss + q*BLKSZ + row] = fmaxf(rmv, -1e6f);
        g_high_norm[(size_t)mb*Ss + q*BLKSZ + row] = nrmv;
    }
}

// ---------------- kernel 7: low-res attention over non-selected blocks ----------------
__global__ void lowres_kernel()
{
    int mb = blockIdx.y, n = blockIdx.x, tid = threadIdx.x;   // 128
    int bb = mb / Hh;
    __shared__ float a_sh[NBR];
    __shared__ float red[NBR];
    float rmv = g_rowmax[mb*NBR + n];
    float t = g_thresh[mb];
    size_t idx = ((size_t)mb*NBR + n)*NBR + tid;
    float ll = g_ll[idx];
    float sel = (g_prior[idx] >= t) ? 1e4f : 0.f;
    float a = __expf(ll - rmv - sel) * g_tcb[bb*NBR + tid];
    a_sh[tid] = a; red[tid] = a;
    __syncthreads();
    for (int off = 64; off >= 1; off >>= 1) {
        if (tid < off) red[tid] += red[tid + off];
        __syncthreads();
    }
    if (tid == 0) g_low_norm[mb*NBR + n] = red[0];
    if (tid < HD) {
        float s = 0.f;
        #pragma unroll 8
        for (int m = 0; m < NBR; m++)
            s += a_sh[m] * g_Vh[((size_t)mb*NBR + m)*HD + tid];
        g_low_out[((size_t)mb*NBR + n)*HD + tid] = s;
    }
}

// ---------------- kernel 8: combine + final layout ----------------
__global__ void combine_kernel(const float* __restrict__ mask, float* __restrict__ out)
{
    int mb = blockIdx.y;
    int tid = threadIdx.x;                 // 256 = 4 tokens x 64 dims
    int s = blockIdx.x*4 + (tid >> 6);
    int hd = tid & 63;
    int bb = mb / Hh, h = mb % Hh;
    int blk = s >> 5;
    float mval = mask[(size_t)bb*Ss + s];
    float lcl = (g_rowmax[mb*NBR + blk] - g_maxrows[(size_t)mb*Ss + s]) * mval;
    float lcorr = __expf(fminf(lcl, 0.f));
    float hcorr = __expf(-fmaxf(lcl, 0.f));
    float hn = g_high_norm[(size_t)mb*Ss + s];
    float ln = g_low_norm[mb*NBR + blk];
    float inv = 1.0f / (hn*hcorr + ln*lcorr + 1e-6f);
    float val = (g_high_out[((size_t)mb*Ss + s)*HD + hd]*hcorr
               + g_low_out[((size_t)mb*NBR + blk)*HD + hd]*lcorr) * inv;
    out[((size_t)bb*Ss + s)*Dm + h*HD + hd] = val;
}

// ---------------- launch ----------------
extern "C" void kernel_launch(void* const* d_in, const int* in_sizes, int n_in,
                              void* d_out, int out_size)
{
    const float* X    = (const float*)d_in[0];
    const float* mask = (const float*)d_in[1];
    const float* Wq   = (const float*)d_in[2];
    const float* bq   = (const float*)d_in[3];
    const float* Wk   = (const float*)d_in[4];
    const float* bk   = (const float*)d_in[5];
    const float* Wv   = (const float*)d_in[6];
    const float* bv   = (const float*)d_in[7];
    float* out = (float*)d_out;

    cudaFuncSetAttribute(qkv_mma_kernel, cudaFuncAttributeMaxDynamicSharedMemorySize, GEMM_SMEM);

    convX_kernel<<<MROWS*Dm/1024, 256>>>(X);                       // 1
    convW_kernel<<<dim3(Dm*Dm/1024, 3), 256>>>(Wq, Wk, Wv);        // 2
    xbar_kernel<<<Bb*NBR, Dm>>>(X, mask);                          // 3
    qkv_mma_kernel<<<dim3(MROWS/128, 9), 512, GEMM_SMEM>>>(mask, bq, bk, bv);  // 4 (profiled slot)
    hmean_gemm_kernel<<<dim3(8, 6, 3), 256>>>(Wq, Wk, Wv, bq, bk, bv);         // 5
    lowlogit_kernel<<<dim3(NBR, MBT), 128>>>();                    // 6
    thresh_kernel<<<MBT, 256>>>();                                 // 7
    select_kernel<<<MBT, 128>>>();                                 // 8
    highres_kernel<<<MBT*NBR, 256>>>(mask);                        // 9
    lowres_kernel<<<dim3(NBR, MBT), 128>>>();                      // 10
    combine_kernel<<<dim3(Ss/4, MBT), 256>>>(mask, out);           // 11
}

// round 8
// speedup vs baseline: 2.1924x; 1.9343x over previous
#include <cuda_runtime.h>
#include <cuda_bf16.h>
#include <cstdint>

// ---------------- problem constants ----------------
#define Bb 2
#define Ss 4096
#define Dm 768
#define Hh 12
#define HD 64
#define BLKSZ 32
#define NBR 128
#define NUMBLK 1024
#define MBT (Bb*Hh)        // 24
#define MROWS (Bb*Ss)      // 8192

typedef unsigned long long ull;

// ---------------- f32x2 helpers ----------------
__device__ __forceinline__ void ffma2(ull &d, ull a, ull b) {
    asm("fma.rn.f32x2 %0, %1, %2, %0;" : "+l"(d) : "l"(a), "l"(b));
}
__device__ __forceinline__ ull pack2(float x, float y) {
    ull r; asm("mov.b64 %0, {%1, %2};" : "=l"(r) : "f"(x), "f"(y)); return r;
}
__device__ __forceinline__ void unpack2(ull v, float &x, float &y) {
    asm("mov.b64 {%0, %1}, %2;" : "=f"(x), "=f"(y) : "l"(v));
}

__device__ __forceinline__ uint32_t smem_u32(const void* p) {
    uint32_t a;
    asm("{ .reg .u64 t; cvta.to.shared.u64 t, %1; cvt.u32.u64 %0, t; }" : "=r"(a) : "l"(p));
    return a;
}
#define CP_ASYNC16(dst, src) \
    asm volatile("cp.async.cg.shared.global [%0], [%1], 16;" :: "r"(dst), "l"(src))
#define CP_COMMIT() asm volatile("cp.async.commit_group;" ::: "memory")

// ---------------- mma.sync helpers ----------------
__device__ __forceinline__ void ldsm4(uint32_t &r0, uint32_t &r1, uint32_t &r2, uint32_t &r3, uint32_t addr) {
    asm volatile("ldmatrix.sync.aligned.m8n8.x4.shared.b16 {%0,%1,%2,%3}, [%4];"
        : "=r"(r0), "=r"(r1), "=r"(r2), "=r"(r3) : "r"(addr));
}
__device__ __forceinline__ void ldsm2(uint32_t &r0, uint32_t &r1, uint32_t addr) {
    asm volatile("ldmatrix.sync.aligned.m8n8.x2.shared.b16 {%0,%1}, [%2];"
        : "=r"(r0), "=r"(r1) : "r"(addr));
}
__device__ __forceinline__ void ldsm4t(uint32_t &r0, uint32_t &r1, uint32_t &r2, uint32_t &r3, uint32_t addr) {
    asm volatile("ldmatrix.sync.aligned.m8n8.x4.trans.shared.b16 {%0,%1,%2,%3}, [%4];"
        : "=r"(r0), "=r"(r1), "=r"(r2), "=r"(r3) : "r"(addr));
}
__device__ __forceinline__ void mma16816(float* c,
    uint32_t a0, uint32_t a1, uint32_t a2, uint32_t a3, uint32_t b0, uint32_t b1) {
    asm volatile("mma.sync.aligned.m16n8k16.row.col.f32.bf16.bf16.f32 "
        "{%0,%1,%2,%3}, {%4,%5,%6,%7}, {%8,%9}, {%0,%1,%2,%3};"
        : "+f"(c[0]), "+f"(c[1]), "+f"(c[2]), "+f"(c[3])
        : "r"(a0), "r"(a1), "r"(a2), "r"(a3), "r"(b0), "r"(b1));
}

// ---------------- device scratch ----------------
__device__ __nv_bfloat16 g_Qbh[MBT*Ss*HD];
__device__ __nv_bfloat16 g_Qbl[MBT*Ss*HD];
__device__ __nv_bfloat16 g_Kbh[MBT*Ss*HD];
__device__ __nv_bfloat16 g_Kbl[MBT*Ss*HD];
__device__ __nv_bfloat16 g_Vbh[MBT*Ss*HD];
__device__ __nv_bfloat16 g_Vbl[MBT*Ss*HD];
__device__ __nv_bfloat16 g_Xh[MROWS*Dm];
__device__ __nv_bfloat16 g_Xl[MROWS*Dm];
__device__ __nv_bfloat16 g_Wh[3*Dm*Dm];
__device__ __nv_bfloat16 g_Wl[3*Dm*Dm];
__device__ float g_Xbar[Bb*NBR*Dm];
__device__ float g_tcb[Bb*NBR];
__device__ float g_tcf[Bb*NBR];
__device__ float g_Qh[MBT*NBR*HD];
__device__ float g_Kh[MBT*NBR*HD];
__device__ float g_Vh[MBT*NBR*HD];
__device__ float g_ll[MBT*NBR*NBR];
__device__ float g_prior[MBT*NBR*NBR];
__device__ float g_rowmax[MBT*NBR];
__device__ float g_thresh[MBT];
__device__ int   g_cnt[MBT*NBR];
__device__ int   g_list[MBT*NBR*NBR];
__device__ float g_high_out[MBT*Ss*HD];
__device__ float g_high_norm[MBT*Ss];
__device__ float g_maxrows[MBT*Ss];
__device__ float g_low_out[MBT*NBR*HD];
__device__ float g_low_norm[MBT*NBR];

__device__ __forceinline__ unsigned f2ord(float f) {
    unsigned u = __float_as_uint(f);
    return (u & 0x80000000u) ? ~u : (u | 0x80000000u);
}

// ---------------- kernel 0a: split X into bf16 hi/lo ----------------
__global__ void convX_kernel(const float* __restrict__ X)
{
    int i = (blockIdx.x*256 + threadIdx.x)*4;
    float4 v = *(const float4*)(X + i);
    float vf[4] = {v.x, v.y, v.z, v.w};
    __nv_bfloat16 h[4], l[4];
    #pragma unroll
    for (int j = 0; j < 4; j++) {
        h[j] = __float2bfloat16(vf[j]);
        l[j] = __float2bfloat16(vf[j] - __bfloat162float(h[j]));
    }
    *(ull*)(g_Xh + i) = *(ull*)h;
    *(ull*)(g_Xl + i) = *(ull*)l;
}

// ---------------- kernel 0b: split W into bf16 hi/lo ----------------
__global__ void convW_kernel(const float* __restrict__ Wq,
                             const float* __restrict__ Wk,
                             const float* __restrict__ Wv)
{
    int mat = blockIdx.y;
    const float* W = (mat == 0) ? Wq : (mat == 1) ? Wk : Wv;
    int i = (blockIdx.x*256 + threadIdx.x)*4;
    float4 v = *(const float4*)(W + i);
    float vf[4] = {v.x, v.y, v.z, v.w};
    __nv_bfloat16 h[4], l[4];
    #pragma unroll
    for (int j = 0; j < 4; j++) {
        h[j] = __float2bfloat16(vf[j]);
        l[j] = __float2bfloat16(vf[j] - __bfloat162float(h[j]));
    }
    size_t o = (size_t)mat*Dm*Dm + i;
    *(ull*)(g_Wh + o) = *(ull*)h;
    *(ull*)(g_Wl + o) = *(ull*)l;
}

// ---------------- kernel 0c: masked block-mean of X ----------------
__global__ void xbar_kernel(const float* __restrict__ X, const float* __restrict__ mask)
{
    int bn = blockIdx.x;             // Bb*NBR
    int bb = bn >> 7, n = bn & 127;
    int d = threadIdx.x;             // 768
    const float* mrow = mask + (size_t)bb*Ss + n*BLKSZ;
    float tc = 0.f;
    #pragma unroll
    for (int t = 0; t < BLKSZ; t++) tc += mrow[t];
    float denom = tc + 1e-6f;
    const float* xp = X + ((size_t)bb*Ss + n*BLKSZ)*Dm + d;
    float s = 0.f;
    #pragma unroll 4
    for (int t = 0; t < BLKSZ; t++) s += mrow[t]*xp[(size_t)t*Dm];
    g_Xbar[(size_t)bn*Dm + d] = s/denom;
    if (d == 0) { g_tcb[bn] = tc; g_tcf[bn] = tc/denom; }
}

// ---------------- kernel 1: QKV projection via mma.sync bf16 (3-term split) ----------------
// 512 threads, 16 warps of 32(m)x64(n), CTA tile 128x256, BK=32, 3-stage cp.async.
// Epilogue writes split-bf16 hi/lo outputs (consumed by highres mma kernel).
#define BUFA_L 10240
#define BUFB_H 20480
#define BUFB_L 40960
#define BUF_STRIDE 61440
#define GEMM_SMEM (3*BUF_STRIDE)

__global__ __launch_bounds__(512, 1) void qkv_mma_kernel(
    const float* __restrict__ mask,
    const float* __restrict__ bq, const float* __restrict__ bk, const float* __restrict__ bv)
{
    extern __shared__ __align__(16) char smem[];
    const uint32_t sb = smem_u32(smem);
    const int tid = threadIdx.x, lane = tid & 31, wid = tid >> 5;
    const int m0 = blockIdx.x * 128;
    const int tile = blockIdx.y;          // 0..8
    const int mat = tile / 3;
    const int n0 = (tile % 3) * 256;
    const int wm = wid & 3;               // m strip of 32
    const int wn = wid >> 2;              // n strip of 64

    const uint4* XH = (const uint4*)g_Xh;
    const uint4* XL = (const uint4*)g_Xl;
    const uint4* WH = (const uint4*)(g_Wh + (size_t)mat*Dm*Dm);
    const uint4* WL = (const uint4*)(g_Wl + (size_t)mat*Dm*Dm);
    const float* bias = (mat == 0) ? bq : (mat == 1) ? bk : bv;
    __nv_bfloat16* outH = (mat == 0) ? g_Qbh : (mat == 1) ? g_Kbh : g_Vbh;
    __nv_bfloat16* outL = (mat == 0) ? g_Qbl : (mat == 1) ? g_Kbl : g_Vbl;

    float acc[2][8][4];
    #pragma unroll
    for (int a = 0; a < 2; a++)
        #pragma unroll
        for (int b = 0; b < 8; b++)
            #pragma unroll
            for (int c = 0; c < 4; c++) acc[a][b][c] = 0.f;

    const int arow = tid >> 2, ac = tid & 3;    // arow 0..127

    #define ISSUE_STAGE(s) do { \
        const int _buf = (s) % 3; \
        const uint32_t _bb = sb + _buf*BUF_STRIDE; \
        const int _kc4 = (s)*4; \
        { \
            uint32_t _so = _bb + arow*80 + ac*16; \
            CP_ASYNC16(_so, &XH[(size_t)(m0 + arow)*96 + _kc4 + ac]); \
            CP_ASYNC16(_so + BUFA_L, &XL[(size_t)(m0 + arow)*96 + _kc4 + ac]); \
        } \
        _Pragma("unroll") \
        for (int _i = 0; _i < 2; _i++) { \
            int _row = arow + _i*128; \
            uint32_t _so = _bb + BUFB_H + _row*80 + ac*16; \
            CP_ASYNC16(_so, &WH[(size_t)(n0 + _row)*96 + _kc4 + ac]); \
            CP_ASYNC16(_so + (BUFB_L - BUFB_H), &WL[(size_t)(n0 + _row)*96 + _kc4 + ac]); \
        } \
        CP_COMMIT(); \
    } while (0)

    ISSUE_STAGE(0);
    ISSUE_STAGE(1);

    for (int s = 0; s < 24; s++) {
        if (s < 23) { asm volatile("cp.async.wait_group 1;" ::: "memory"); }
        else        { asm volatile("cp.async.wait_group 0;" ::: "memory"); }
        __syncthreads();
        if (s + 2 < 24) ISSUE_STAGE(s + 2);
        const uint32_t base = sb + (s % 3)*BUF_STRIDE;

        #pragma unroll
        for (int kk = 0; kk < 2; kk++) {
            const uint32_t koff = kk*32;
            uint32_t ah[2][4], al[2][4];
            #pragma unroll
            for (int mt = 0; mt < 2; mt++) {
                int row = wm*32 + mt*16 + (lane & 7) + ((lane >> 3) & 1)*8;
                uint32_t ad = base + row*80 + koff + (lane >> 4)*16;
                ldsm4(ah[mt][0], ah[mt][1], ah[mt][2], ah[mt][3], ad);
                ldsm4(al[mt][0], al[mt][1], al[mt][2], al[mt][3], ad + BUFA_L);
            }
            #pragma unroll
            for (int np = 0; np < 4; np++) {
                int n = wn*64 + np*16 + (lane & 7) + (lane >> 4)*8;
                uint32_t bd = base + BUFB_H + n*80 + koff + ((lane >> 3) & 1)*16;
                uint32_t b0, b1, b2, b3;
                ldsm4(b0, b1, b2, b3, bd);
                #pragma unroll
                for (int mt = 0; mt < 2; mt++) {
                    mma16816(acc[mt][np*2],   ah[mt][0], ah[mt][1], ah[mt][2], ah[mt][3], b0, b1);
                    mma16816(acc[mt][np*2+1], ah[mt][0], ah[mt][1], ah[mt][2], ah[mt][3], b2, b3);
                    mma16816(acc[mt][np*2],   al[mt][0], al[mt][1], al[mt][2], al[mt][3], b0, b1);
                    mma16816(acc[mt][np*2+1], al[mt][0], al[mt][1], al[mt][2], al[mt][3], b2, b3);
                }
            }
            #pragma unroll
            for (int np = 0; np < 4; np++) {
                int n = wn*64 + np*16 + (lane & 7) + (lane >> 4)*8;
                uint32_t bd = base + BUFB_L + n*80 + koff + ((lane >> 3) & 1)*16;
                uint32_t b0, b1, b2, b3;
                ldsm4(b0, b1, b2, b3, bd);
                #pragma unroll
                for (int mt = 0; mt < 2; mt++) {
                    mma16816(acc[mt][np*2],   ah[mt][0], ah[mt][1], ah[mt][2], ah[mt][3], b0, b1);
                    mma16816(acc[mt][np*2+1], ah[mt][0], ah[mt][1], ah[mt][2], ah[mt][3], b2, b3);
                }
            }
        }
    }

    const int h = (n0 + wn*64) >> 6;
    const float* bp = bias + n0 + wn*64;
    float2 bias2[8];
    #pragma unroll
    for (int nt = 0; nt < 8; nt++) bias2[nt] = *(const float2*)(bp + nt*8 + (lane & 3)*2);

    #pragma unroll
    for (int mt = 0; mt < 2; mt++) {
        #pragma unroll
        for (int half = 0; half < 2; half++) {
            int m = m0 + wm*32 + mt*16 + (lane >> 2) + half*8;
            int bbm = m >> 12, sx = m & 4095;
            float mv = mask[(size_t)bbm*Ss + sx];
            size_t ob = ((size_t)(bbm*Hh + h)*Ss + sx)*HD;
            #pragma unroll
            for (int nt = 0; nt < 8; nt++) {
                int col = nt*8 + (lane & 3)*2;
                float wx = (acc[mt][nt][half*2+0] + bias2[nt].x)*mv;
                float wy = (acc[mt][nt][half*2+1] + bias2[nt].y)*mv;
                __nv_bfloat162 hv = __floats2bfloat162_rn(wx, wy);
                float hx = __bfloat162float(__low2bfloat16(hv));
                float hy = __bfloat162float(__high2bfloat16(hv));
                __nv_bfloat162 lv = __floats2bfloat162_rn(wx - hx, wy - hy);
                *(__nv_bfloat162*)(outH + ob + col) = hv;
                *(__nv_bfloat162*)(outL + ob + col) = lv;
            }
        }
    }
}

// ---------------- kernel 1b: exact fp32 block-mean projection (fine-grained tiles) ----------------
__global__ __launch_bounds__(256) void hmean_gemm_kernel(
    const float* __restrict__ Wq, const float* __restrict__ Wk, const float* __restrict__ Wv,
    const float* __restrict__ bq, const float* __restrict__ bk, const float* __restrict__ bv)
{
    __shared__ float As[32][33];
    __shared__ float Bs[128][33];

    const int mat = blockIdx.z;
    const float* W = (mat == 0) ? Wq : (mat == 1) ? Wk : Wv;
    const float* bias = (mat == 0) ? bq : (mat == 1) ? bk : bv;
    float* out = (mat == 0) ? g_Qh : (mat == 1) ? g_Kh : g_Vh;

    const int tid = threadIdx.x;
    const int r0 = blockIdx.x * 32;
    const int e0 = blockIdx.y * 128;
    const int tn = tid >> 4;
    const int tm2 = tid & 15;

    float acc0[8], acc1[8];
    #pragma unroll
    for (int j = 0; j < 8; j++) { acc0[j] = 0.f; acc1[j] = 0.f; }

    for (int k0 = 0; k0 < Dm; k0 += 32) {
        {
            int r = tid >> 3, kq = tid & 7;
            float4 v = *(const float4*)&g_Xbar[(size_t)(r0 + r)*Dm + k0 + kq*4];
            As[r][kq*4+0] = v.x; As[r][kq*4+1] = v.y; As[r][kq*4+2] = v.z; As[r][kq*4+3] = v.w;
        }
        #pragma unroll
        for (int t = 0; t < 4; t++) {
            int idx = tid + t*256;
            int r = idx >> 3, kq = idx & 7;
            float4 v = *(const float4*)&W[(size_t)(e0 + r)*Dm + k0 + kq*4];
            Bs[r][kq*4+0] = v.x; Bs[r][kq*4+1] = v.y; Bs[r][kq*4+2] = v.z; Bs[r][kq*4+3] = v.w;
        }
        __syncthreads();
        #pragma unroll 8
        for (int k = 0; k < 32; k++) {
            float a0 = As[tm2*2][k], a1 = As[tm2*2+1][k];
            #pragma unroll
            for (int j = 0; j < 8; j++) {
                float b = Bs[tn*8+j][k];
                acc0[j] += a0*b;
                acc1[j] += a1*b;
            }
        }
        __syncthreads();
    }

    #pragma unroll
    for (int i = 0; i < 2; i++) {
        const int r = r0 + tm2*2 + i;
        const int bb2 = r >> 7, n = r & 127;
        const float tcf = g_tcf[r];
        const float* av = i ? acc1 : acc0;
        #pragma unroll
        for (int j = 0; j < 8; j++) {
            int e = e0 + tn*8 + j;
            int hh = e >> 6, hd = e & 63;
            out[(((size_t)(bb2*Hh + hh))*NBR + n)*HD + hd] = av[j] + bias[e]*tcf;
        }
    }
}

// ---------------- kernel 3: low-res logits + row max + prior ----------------
__global__ void lowlogit_kernel()
{
    int mb = blockIdx.y, n = blockIdx.x, tid = threadIdx.x;   // 128 threads
    int bb = mb / Hh;
    __shared__ float Khs[NBR][65];
    __shared__ float qv[HD];
    __shared__ float red[NBR];
    for (int i = tid; i < NBR*HD; i += 128) {
        int r = i >> 6, d = i & 63;
        Khs[r][d] = g_Kh[((size_t)mb*NBR + r)*HD + d];
    }
    if (tid < HD) qv[tid] = g_Qh[((size_t)mb*NBR + n)*HD + tid];
    __syncthreads();

    int m = tid;
    float s = 0.f;
    #pragma unroll 8
    for (int d = 0; d < HD; d++) s += qv[d]*Khs[m][d];
    s *= 0.125f;
    red[m] = s;
    __syncthreads();
    for (int off = 64; off >= 1; off >>= 1) {
        if (tid < off) red[tid] = fmaxf(red[tid], red[tid + off]);
        __syncthreads();
    }
    float rm = red[0];

    float tcn = g_tcb[bb*NBR + n], tcm = g_tcb[bb*NBR + m];
    float pe = (tcn*tcm < 0.5f) ? 1.0f : 0.0f;
    float ll = s - 1e4f*pe;
    float prior = ll - rm;
    int dif = n - m; if (dif < 0) dif = -dif;
    if (dif <= 1) prior += 5e3f;    // DIAG_N=3 -> off=1; FIRST_N=0
    size_t idx = ((size_t)mb*NBR + n)*NBR + m;
    g_ll[idx] = ll;
    g_prior[idx] = prior;
    if (m == 0) g_rowmax[mb*NBR + n] = rm;
}

// ---------------- kernel 4: exact 1024-th largest via byte radix select ----------------
__global__ void thresh_kernel()
{
    int mb = blockIdx.x;
    const float* pr = g_prior + (size_t)mb*NBR*NBR;
    __shared__ unsigned hist[256];
    __shared__ unsigned s_prefix;
    __shared__ int s_k;
    int tid = threadIdx.x;   // 256
    int lane = tid & 31;
    if (tid == 0) { s_prefix = 0u; s_k = NUMBLK; }
    for (int pass = 0; pass < 4; pass++) {
        int shift = 24 - pass*8;
        hist[tid] = 0u;
        __syncthreads();
        unsigned pref = s_prefix;
        for (int i = tid; i < NBR*NBR; i += 256) {
            unsigned u = f2ord(pr[i]);
            bool ok = (pass == 0) ? true : (((u ^ pref) >> (shift + 8)) == 0u);
            unsigned bin = ok ? ((u >> shift) & 255u) : 0xFFFFFFFFu;
            unsigned mm = __match_any_sync(0xffffffffu, bin);
            if (bin != 0xFFFFFFFFu && (__ffs(mm) - 1) == lane)
                atomicAdd(&hist[bin], __popc(mm));
        }
        __syncthreads();
        if (tid == 0) {
            int k = s_k; unsigned cum = 0u; int sel = 0;
            for (int bbin = 255; bbin >= 0; bbin--) {
                unsigned h = hist[bbin];
                if (cum + h >= (unsigned)k) { sel = bbin; break; }
                cum += h;
            }
            s_k = k - (int)cum;
            s_prefix = pref | ((unsigned)sel << shift);
        }
        __syncthreads();
    }
    if (tid == 0) {
        unsigned u = s_prefix;
        unsigned raw = (u & 0x80000000u) ? (u & 0x7FFFFFFFu) : ~u;
        g_thresh[mb] = __uint_as_float(raw);
    }
}

// ---------------- kernel 5: deterministic per-(mb,q) selected k-block lists ----------------
__global__ void select_kernel()
{
    int mb = blockIdx.x;
    int n = threadIdx.x;           // 128
    float t = g_thresh[mb];
    const float* pr = g_prior + ((size_t)mb*NBR + n)*NBR;
    int* lst = g_list + ((size_t)mb*NBR + n)*NBR;
    int c = 0;
    for (int m = 0; m < NBR; m++)
        if (pr[m] >= t) lst[c++] = m;
    g_cnt[mb*NBR + n] = c;
}

// ---------------- kernel 6: high-res sparse attention via mma.sync (split bf16) ----------------
// 128 threads (4 warps). S-phase: warp w computes S cols 8w..8w+7 for all 32 rows.
// AV-phase: warp w computes output dims 16w..16w+15 for all 32 rows.
#define OKH 0
#define OKL 9216
#define OVH 18432
#define OVL 27648
#define OKM 36864
#define OPH 37120
#define OPL 39680
#define OMAXP 42240
#define OSUMP 42752
#define ORM 43264
#define OSC 43392
#define ONRM 43520
#define HR_SMEM 43648

__global__ __launch_bounds__(128) void highres_kernel(const float* __restrict__ mask)
{
    __shared__ __align__(16) char sm[HR_SMEM];
    const uint32_t sb = smem_u32(sm);
    const int mbn = blockIdx.x;
    const int mb = mbn >> 7, q = mbn & 127;
    const int bb = mb / Hh;
    const int tid = threadIdx.x;
    const int lane = tid & 31, w = tid >> 5;

    const int nb = g_cnt[mbn];
    const int* lst = g_list + (size_t)mbn*NBR;
    const size_t qrow = (size_t)mb*Ss + q*BLKSZ;

    float* RM  = (float*)(sm + ORM);
    float* SC  = (float*)(sm + OSC);
    float* NRM = (float*)(sm + ONRM);
    float* MAXP = (float*)(sm + OMAXP);
    float* SUMP = (float*)(sm + OSUMP);

    // ---- stage Q hi/lo into (temporarily) K-buffer area, ldmatrix to regs ----
    for (int i = tid; i < 256; i += 128) {
        int r = i >> 3, ch = i & 7;
        *(uint4*)(sm + OKH + r*144 + ch*16)        = ((const uint4*)(g_Qbh + (qrow + r)*HD))[ch];
        *(uint4*)(sm + OKH + 4608 + r*144 + ch*16) = ((const uint4*)(g_Qbl + (qrow + r)*HD))[ch];
    }
    if (tid < 32) { RM[tid] = -1e30f; NRM[tid] = 0.f; }
    __syncthreads();

    uint32_t aQh[2][4][4], aQl[2][4][4];
    #pragma unroll
    for (int mt = 0; mt < 2; mt++) {
        int row = mt*16 + (lane & 7) + ((lane >> 3) & 1)*8;
        #pragma unroll
        for (int ks = 0; ks < 4; ks++) {
            uint32_t ad = sb + OKH + row*144 + (ks*2 + (lane >> 4))*16;
            ldsm4(aQh[mt][ks][0], aQh[mt][ks][1], aQh[mt][ks][2], aQh[mt][ks][3], ad);
            ldsm4(aQl[mt][ks][0], aQl[mt][ks][1], aQl[mt][ks][2], aQl[mt][ks][3], ad + 4608);
        }
    }
    __syncthreads();   // staging area free for pipeline use

    float o[2][2][4];
    #pragma unroll
    for (int mt = 0; mt < 2; mt++)
        #pragma unroll
        for (int nt = 0; nt < 2; nt++)
            #pragma unroll
            for (int j = 0; j < 4; j++) o[mt][nt][j] = 0.f;

    #define HR_LOAD(st, kb) do { \
        size_t _rb = (size_t)mb*Ss + (size_t)(kb)*BLKSZ; \
        for (int _i = tid; _i < 256; _i += 128) { \
            int _r = _i >> 3, _ch = _i & 7; \
            uint32_t _so = (st)*4608 + _r*144 + _ch*16; \
            CP_ASYNC16(sb + OKH + _so, ((const uint4*)(g_Kbh + (_rb + _r)*HD)) + _ch); \
            CP_ASYNC16(sb + OKL + _so, ((const uint4*)(g_Kbl + (_rb + _r)*HD)) + _ch); \
            CP_ASYNC16(sb + OVH + _so, ((const uint4*)(g_Vbh + (_rb + _r)*HD)) + _ch); \
            CP_ASYNC16(sb + OVL + _so, ((const uint4*)(g_Vbl + (_rb + _r)*HD)) + _ch); \
        } \
        if (tid < 8) CP_ASYNC16(sb + OKM + (st)*128 + tid*16, &mask[(size_t)bb*Ss + (size_t)(kb)*BLKSZ + tid*4]); \
        CP_COMMIT(); \
    } while (0)

    if (nb > 0) HR_LOAD(0, lst[0]);

    for (int it = 0; it < nb; it++) {
        const int cur = it & 1;
        if (it + 1 < nb) {
            HR_LOAD((it+1) & 1, lst[it+1]);
            asm volatile("cp.async.wait_group 1;" ::: "memory");
        } else {
            asm volatile("cp.async.wait_group 0;" ::: "memory");
        }
        __syncthreads();   // buffer `cur` ready

        // ---- S = Qh*Kh + Qh*Kl + Ql*Kh ----
        float sacc[2][4];
        #pragma unroll
        for (int mt = 0; mt < 2; mt++)
            #pragma unroll
            for (int j = 0; j < 4; j++) sacc[mt][j] = 0.f;

        const uint32_t khb = sb + OKH + cur*4608;
        #pragma unroll
        for (int ks = 0; ks < 4; ks++) {
            uint32_t baddr = khb + (8*w + (lane & 7))*144 + (ks*2 + ((lane >> 3) & 1))*16;
            uint32_t bh0, bh1, bl0, bl1;
            ldsm2(bh0, bh1, baddr);
            ldsm2(bl0, bl1, baddr + (OKL - OKH));
            #pragma unroll
            for (int mt = 0; mt < 2; mt++) {
                mma16816(sacc[mt], aQh[mt][ks][0], aQh[mt][ks][1], aQh[mt][ks][2], aQh[mt][ks][3], bh0, bh1);
                mma16816(sacc[mt], aQh[mt][ks][0], aQh[mt][ks][1], aQh[mt][ks][2], aQh[mt][ks][3], bl0, bl1);
                mma16816(sacc[mt], aQl[mt][ks][0], aQl[mt][ks][1], aQl[mt][ks][2], aQl[mt][ks][3], bh0, bh1);
            }
        }
        #pragma unroll
        for (int mt = 0; mt < 2; mt++)
            #pragma unroll
            for (int j = 0; j < 4; j++) sacc[mt][j] *= 0.125f;

        // ---- per-warp partial row max (8 cols each) ----
        #pragma unroll
        for (int mt = 0; mt < 2; mt++) {
            float m1 = fmaxf(sacc[mt][0], sacc[mt][1]);
            float m2 = fmaxf(sacc[mt][2], sacc[mt][3]);
            m1 = fmaxf(m1, __shfl_xor_sync(0xffffffffu, m1, 1, 4));
            m1 = fmaxf(m1, __shfl_xor_sync(0xffffffffu, m1, 2, 4));
            m2 = fmaxf(m2, __shfl_xor_sync(0xffffffffu, m2, 1, 4));
            m2 = fmaxf(m2, __shfl_xor_sync(0xffffffffu, m2, 2, 4));
            if ((lane & 3) == 0) {
                int r1 = mt*16 + (lane >> 2);
                MAXP[r1*4 + w] = m1;
                MAXP[(r1+8)*4 + w] = m2;
            }
        }
        __syncthreads();
        if (tid < 32) {
            float tm = fmaxf(fmaxf(MAXP[tid*4], MAXP[tid*4+1]), fmaxf(MAXP[tid*4+2], MAXP[tid*4+3]));
            float old = RM[tid];
            float nm = fmaxf(old, tm);
            SC[tid] = __expf(old - nm);
            RM[tid] = nm;
        }
        __syncthreads();

        // ---- rescale O, P = exp, store Ph/Pl, partial sums ----
        const float kmv0 = ((const float*)(sm + OKM + cur*128))[8*w + (lane & 3)*2];
        const float kmv1 = ((const float*)(sm + OKM + cur*128))[8*w + (lane & 3)*2 + 1];
        const float pen0 = 1e4f*(1.f - kmv0), pen1 = 1e4f*(1.f - kmv1);
        const int colb = (8*w + (lane & 3)*2)*2;   // byte offset in P row

        #pragma unroll
        for (int mt = 0; mt < 2; mt++) {
            int r1 = mt*16 + (lane >> 2), r2 = r1 + 8;
            float sc1 = SC[r1], sc2 = SC[r2];
            float rm1 = RM[r1], rm2 = RM[r2];
            #pragma unroll
            for (int nt = 0; nt < 2; nt++) {
                o[mt][nt][0] *= sc1; o[mt][nt][1] *= sc1;
                o[mt][nt][2] *= sc2; o[mt][nt][3] *= sc2;
            }
            float p00 = __expf(sacc[mt][0] - rm1 - pen0);
            float p01 = __expf(sacc[mt][1] - rm1 - pen1);
            float p10 = __expf(sacc[mt][2] - rm2 - pen0);
            float p11 = __expf(sacc[mt][3] - rm2 - pen1);

            __nv_bfloat162 ph0 = __floats2bfloat162_rn(p00, p01);
            __nv_bfloat162 pl0 = __floats2bfloat162_rn(
                p00 - __bfloat162float(__low2bfloat16(ph0)),
                p01 - __bfloat162float(__high2bfloat16(ph0)));
            __nv_bfloat162 ph1 = __floats2bfloat162_rn(p10, p11);
            __nv_bfloat162 pl1 = __floats2bfloat162_rn(
                p10 - __bfloat162float(__low2bfloat16(ph1)),
                p11 - __bfloat162float(__high2bfloat16(ph1)));
            *(__nv_bfloat162*)(sm + OPH + r1*80 + colb) = ph0;
            *(__nv_bfloat162*)(sm + OPL + r1*80 + colb) = pl0;
            *(__nv_bfloat162*)(sm + OPH + r2*80 + colb) = ph1;
            *(__nv_bfloat162*)(sm + OPL + r2*80 + colb) = pl1;

            float s1 = p00 + p01, s2 = p10 + p11;
            s1 += __shfl_xor_sync(0xffffffffu, s1, 1, 4);
            s1 += __shfl_xor_sync(0xffffffffu, s1, 2, 4);
            s2 += __shfl_xor_sync(0xffffffffu, s2, 1, 4);
            s2 += __shfl_xor_sync(0xffffffffu, s2, 2, 4);
            if ((lane & 3) == 0) {
                SUMP[r1*4 + w] = s1;
                SUMP[r2*4 + w] = s2;
            }
        }
        __syncthreads();
        if (tid < 32) {
            float s = SUMP[tid*4] + SUMP[tid*4+1] + SUMP[tid*4+2] + SUMP[tid*4+3];
            NRM[tid] = NRM[tid]*SC[tid] + s;
        }

        // ---- AV: O += Ph*Vh + Ph*Vl + Pl*Vh ----
        const uint32_t vhb = sb + OVH + cur*4608;
        #pragma unroll
        for (int ks = 0; ks < 2; ks++) {
            uint32_t aPh[2][4], aPl[2][4];
            #pragma unroll
            for (int mt = 0; mt < 2; mt++) {
                int row = mt*16 + (lane & 7) + ((lane >> 3) & 1)*8;
                uint32_t pad = sb + OPH + row*80 + (ks*2 + (lane >> 4))*16;
                ldsm4(aPh[mt][0], aPh[mt][1], aPh[mt][2], aPh[mt][3], pad);
                ldsm4(aPl[mt][0], aPl[mt][1], aPl[mt][2], aPl[mt][3], pad + (OPL - OPH));
            }
            int vrow = ks*16 + (lane & 7) + ((lane >> 3) & 1)*8;
            uint32_t vad = vhb + vrow*144 + (2*w + (lane >> 4))*16;
            uint32_t bh0, bh1, bh2, bh3, bl0, bl1, bl2, bl3;
            ldsm4t(bh0, bh1, bh2, bh3, vad);
            ldsm4t(bl0, bl1, bl2, bl3, vad + (OVL - OVH));
            #pragma unroll
            for (int mt = 0; mt < 2; mt++) {
                mma16816(o[mt][0], aPh[mt][0], aPh[mt][1], aPh[mt][2], aPh[mt][3], bh0, bh1);
                mma16816(o[mt][1], aPh[mt][0], aPh[mt][1], aPh[mt][2], aPh[mt][3], bh2, bh3);
                mma16816(o[mt][0], aPh[mt][0], aPh[mt][1], aPh[mt][2], aPh[mt][3], bl0, bl1);
                mma16816(o[mt][1], aPh[mt][0], aPh[mt][1], aPh[mt][2], aPh[mt][3], bl2, bl3);
                mma16816(o[mt][0], aPl[mt][0], aPl[mt][1], aPl[mt][2], aPl[mt][3], bh0, bh1);
                mma16816(o[mt][1], aPl[mt][0], aPl[mt][1], aPl[mt][2], aPl[mt][3], bh2, bh3);
            }
        }
        __syncthreads();   // P/stats reusable, buffer `cur` reload safe next iter
    }

    // ---- epilogue ----
    #pragma unroll
    for (int mt = 0; mt < 2; mt++) {
        int r1 = mt*16 + (lane >> 2), r2 = r1 + 8;
        #pragma unroll
        for (int nt = 0; nt < 2; nt++) {
            int col = 16*w + nt*8 + (lane & 3)*2;
            float2 w1 = make_float2(o[mt][nt][0], o[mt][nt][1]);
            float2 w2 = make_float2(o[mt][nt][2], o[mt][nt][3]);
            *(float2*)&g_high_out[(qrow + r1)*HD + col] = w1;
            *(float2*)&g_high_out[(qrow + r2)*HD + col] = w2;
        }
    }
    if (tid < 32) {
        g_maxrows[qrow + tid] = fmaxf(RM[tid], -1e6f);
        g_high_norm[qrow + tid] = NRM[tid];
    }
}

// ---------------- kernel 7: low-res attention over non-selected blocks ----------------
__global__ void lowres_kernel()
{
    int mb = blockIdx.y, n = blockIdx.x, tid = threadIdx.x;   // 128
    int bb = mb / Hh;
    __shared__ float a_sh[NBR];
    __shared__ float red[NBR];
    float rmv = g_rowmax[mb*NBR + n];
    float t = g_thresh[mb];
    size_t idx = ((size_t)mb*NBR + n)*NBR + tid;
    float ll = g_ll[idx];
    float sel = (g_prior[idx] >= t) ? 1e4f : 0.f;
    float a = __expf(ll - rmv - sel) * g_tcb[bb*NBR + tid];
    a_sh[tid] = a; red[tid] = a;
    __syncthreads();
    for (int off = 64; off >= 1; off >>= 1) {
        if (tid < off) red[tid] += red[tid + off];
        __syncthreads();
    }
    if (tid == 0) g_low_norm[mb*NBR + n] = red[0];
    if (tid < HD) {
        float s = 0.f;
        #pragma unroll 8
        for (int m = 0; m < NBR; m++)
            s += a_sh[m] * g_Vh[((size_t)mb*NBR + m)*HD + tid];
        g_low_out[((size_t)mb*NBR + n)*HD + tid] = s;
    }
}

// ---------------- kernel 8: combine + final layout ----------------
__global__ void combine_kernel(const float* __restrict__ mask, float* __restrict__ out)
{
    int mb = blockIdx.y;
    int tid = threadIdx.x;                 // 256 = 4 tokens x 64 dims
    int s = blockIdx.x*4 + (tid >> 6);
    int hd = tid & 63;
    int bb = mb / Hh, h = mb % Hh;
    int blk = s >> 5;
    float mval = mask[(size_t)bb*Ss + s];
    float lcl = (g_rowmax[mb*NBR + blk] - g_maxrows[(size_t)mb*Ss + s]) * mval;
    float lcorr = __expf(fminf(lcl, 0.f));
    float hcorr = __expf(-fmaxf(lcl, 0.f));
    float hn = g_high_norm[(size_t)mb*Ss + s];
    float ln = g_low_norm[mb*NBR + blk];
    float inv = 1.0f / (hn*hcorr + ln*lcorr + 1e-6f);
    float val = (g_high_out[((size_t)mb*Ss + s)*HD + hd]*hcorr
               + g_low_out[((size_t)mb*NBR + blk)*HD + hd]*lcorr) * inv;
    out[((size_t)bb*Ss + s)*Dm + h*HD + hd] = val;
}

// ---------------- launch ----------------
extern "C" void kernel_launch(void* const* d_in, const int* in_sizes, int n_in,
                              void* d_out, int out_size)
{
    const float* X    = (const float*)d_in[0];
    const float* mask = (const float*)d_in[1];
    const float* Wq   = (const float*)d_in[2];
    const float* bq   = (const float*)d_in[3];
    const float* Wk   = (const float*)d_in[4];
    const float* bk   = (const float*)d_in[5];
    const float* Wv   = (const float*)d_in[6];
    const float* bv   = (const float*)d_in[7];
    float* out = (float*)d_out;

    cudaFuncSetAttribute(qkv_mma_kernel, cudaFuncAttributeMaxDynamicSharedMemorySize, GEMM_SMEM);

    convX_kernel<<<MROWS*Dm/1024, 256>>>(X);                       // 1
    convW_kernel<<<dim3(Dm*Dm/1024, 3), 256>>>(Wq, Wk, Wv);        // 2
    xbar_kernel<<<Bb*NBR, Dm>>>(X, mask);                          // 3
    qkv_mma_kernel<<<dim3(MROWS/128, 9), 512, GEMM_SMEM>>>(mask, bq, bk, bv);  // 4 (profiled slot)
    hmean_gemm_kernel<<<dim3(8, 6, 3), 256>>>(Wq, Wk, Wv, bq, bk, bv);         // 5
    lowlogit_kernel<<<dim3(NBR, MBT), 128>>>();                    // 6
    thresh_kernel<<<MBT, 256>>>();                                 // 7
    select_kernel<<<MBT, 128>>>();                                 // 8
    highres_kernel<<<MBT*NBR, 128>>>(mask);                        // 9
    lowres_kernel<<<dim3(NBR, MBT), 128>>>();                      // 10
    combine_kernel<<<dim3(Ss/4, MBT), 256>>>(mask, out);           // 11
}

// round 9
// speedup vs baseline: 2.2585x; 1.0302x over previous
#include <cuda_runtime.h>
#include <cuda_bf16.h>
#include <cstdint>

// ---------------- problem constants ----------------
#define Bb 2
#define Ss 4096
#define Dm 768
#define Hh 12
#define HD 64
#define BLKSZ 32
#define NBR 128
#define NUMBLK 1024
#define MBT (Bb*Hh)        // 24
#define MROWS (Bb*Ss)      // 8192

typedef unsigned long long ull;

__device__ __forceinline__ uint32_t smem_u32(const void* p) {
    uint32_t a;
    asm("{ .reg .u64 t; cvta.to.shared.u64 t, %1; cvt.u32.u64 %0, t; }" : "=r"(a) : "l"(p));
    return a;
}
#define CP_ASYNC16(dst, src) \
    asm volatile("cp.async.cg.shared.global [%0], [%1], 16;" :: "r"(dst), "l"(src))
#define CP_COMMIT() asm volatile("cp.async.commit_group;" ::: "memory")

// ---------------- mma.sync helpers ----------------
__device__ __forceinline__ void ldsm4(uint32_t &r0, uint32_t &r1, uint32_t &r2, uint32_t &r3, uint32_t addr) {
    asm volatile("ldmatrix.sync.aligned.m8n8.x4.shared.b16 {%0,%1,%2,%3}, [%4];"
        : "=r"(r0), "=r"(r1), "=r"(r2), "=r"(r3) : "r"(addr));
}
__device__ __forceinline__ void ldsm2(uint32_t &r0, uint32_t &r1, uint32_t addr) {
    asm volatile("ldmatrix.sync.aligned.m8n8.x2.shared.b16 {%0,%1}, [%2];"
        : "=r"(r0), "=r"(r1) : "r"(addr));
}
__device__ __forceinline__ void ldsm4t(uint32_t &r0, uint32_t &r1, uint32_t &r2, uint32_t &r3, uint32_t addr) {
    asm volatile("ldmatrix.sync.aligned.m8n8.x4.trans.shared.b16 {%0,%1,%2,%3}, [%4];"
        : "=r"(r0), "=r"(r1), "=r"(r2), "=r"(r3) : "r"(addr));
}
__device__ __forceinline__ void mma16816(float* c,
    uint32_t a0, uint32_t a1, uint32_t a2, uint32_t a3, uint32_t b0, uint32_t b1) {
    asm volatile("mma.sync.aligned.m16n8k16.row.col.f32.bf16.bf16.f32 "
        "{%0,%1,%2,%3}, {%4,%5,%6,%7}, {%8,%9}, {%0,%1,%2,%3};"
        : "+f"(c[0]), "+f"(c[1]), "+f"(c[2]), "+f"(c[3])
        : "r"(a0), "r"(a1), "r"(a2), "r"(a3), "r"(b0), "r"(b1));
}

// ---------------- device scratch ----------------
__device__ __nv_bfloat16 g_Qbh[MBT*Ss*HD];
__device__ __nv_bfloat16 g_Qbl[MBT*Ss*HD];
__device__ __nv_bfloat16 g_Kbh[MBT*Ss*HD];
__device__ __nv_bfloat16 g_Kbl[MBT*Ss*HD];
__device__ __nv_bfloat16 g_Vbh[MBT*Ss*HD];
__device__ __nv_bfloat16 g_Vbl[MBT*Ss*HD];
__device__ __nv_bfloat16 g_Xh[MROWS*Dm];
__device__ __nv_bfloat16 g_Xl[MROWS*Dm];
__device__ __nv_bfloat16 g_Wh[3*Dm*Dm];
__device__ __nv_bfloat16 g_Wl[3*Dm*Dm];
__device__ float g_Xbar[Bb*NBR*Dm];
__device__ float g_tcb[Bb*NBR];
__device__ float g_tcf[Bb*NBR];
__device__ float g_Qh[MBT*NBR*HD];
__device__ float g_Kh[MBT*NBR*HD];
__device__ float g_Vh[MBT*NBR*HD];
__device__ float g_ll[MBT*NBR*NBR];
__device__ float g_prior[MBT*NBR*NBR];
__device__ float g_rowmax[MBT*NBR];
__device__ float g_thresh[MBT];
__device__ int   g_cnt[MBT*NBR];
__device__ int   g_list[MBT*NBR*NBR];
__device__ float g_high_out[MBT*Ss*HD];
__device__ float g_high_norm[MBT*Ss];
__device__ float g_maxrows[MBT*Ss];
__device__ float g_low_out[MBT*NBR*HD];
__device__ float g_low_norm[MBT*NBR];

__device__ __forceinline__ unsigned f2ord(float f) {
    unsigned u = __float_as_uint(f);
    return (u & 0x80000000u) ? ~u : (u | 0x80000000u);
}

// ---------------- kernel 0a: split X into bf16 hi/lo ----------------
__global__ void convX_kernel(const float* __restrict__ X)
{
    int i = (blockIdx.x*256 + threadIdx.x)*4;
    float4 v = *(const float4*)(X + i);
    float vf[4] = {v.x, v.y, v.z, v.w};
    __nv_bfloat16 h[4], l[4];
    #pragma unroll
    for (int j = 0; j < 4; j++) {
        h[j] = __float2bfloat16(vf[j]);
        l[j] = __float2bfloat16(vf[j] - __bfloat162float(h[j]));
    }
    *(ull*)(g_Xh + i) = *(ull*)h;
    *(ull*)(g_Xl + i) = *(ull*)l;
}

// ---------------- kernel 0b: split W into bf16 hi/lo ----------------
__global__ void convW_kernel(const float* __restrict__ Wq,
                             const float* __restrict__ Wk,
                             const float* __restrict__ Wv)
{
    int mat = blockIdx.y;
    const float* W = (mat == 0) ? Wq : (mat == 1) ? Wk : Wv;
    int i = (blockIdx.x*256 + threadIdx.x)*4;
    float4 v = *(const float4*)(W + i);
    float vf[4] = {v.x, v.y, v.z, v.w};
    __nv_bfloat16 h[4], l[4];
    #pragma unroll
    for (int j = 0; j < 4; j++) {
        h[j] = __float2bfloat16(vf[j]);
        l[j] = __float2bfloat16(vf[j] - __bfloat162float(h[j]));
    }
    size_t o = (size_t)mat*Dm*Dm + i;
    *(ull*)(g_Wh + o) = *(ull*)h;
    *(ull*)(g_Wl + o) = *(ull*)l;
}

// ---------------- kernel 0c: masked block-mean of X ----------------
__global__ void xbar_kernel(const float* __restrict__ X, const float* __restrict__ mask)
{
    int bn = blockIdx.x;             // Bb*NBR
    int bb = bn >> 7, n = bn & 127;
    int d = threadIdx.x;             // 768
    const float* mrow = mask + (size_t)bb*Ss + n*BLKSZ;
    float tc = 0.f;
    #pragma unroll
    for (int t = 0; t < BLKSZ; t++) tc += mrow[t];
    float denom = tc + 1e-6f;
    const float* xp = X + ((size_t)bb*Ss + n*BLKSZ)*Dm + d;
    float s = 0.f;
    #pragma unroll 4
    for (int t = 0; t < BLKSZ; t++) s += mrow[t]*xp[(size_t)t*Dm];
    g_Xbar[(size_t)bn*Dm + d] = s/denom;
    if (d == 0) { g_tcb[bn] = tc; g_tcf[bn] = tc/denom; }
}

// ---------------- kernel 1: QKV projection via mma.sync bf16 (3-term split, pipelined frags) ----------------
#define BUFA_L 10240
#define BUFB_H 20480
#define BUFB_L 40960
#define BUF_STRIDE 61440
#define GEMM_SMEM (3*BUF_STRIDE)

__global__ __launch_bounds__(512, 1) void qkv_mma_kernel(
    const float* __restrict__ mask,
    const float* __restrict__ bq, const float* __restrict__ bk, const float* __restrict__ bv)
{
    extern __shared__ __align__(16) char smem[];
    const uint32_t sb = smem_u32(smem);
    const int tid = threadIdx.x, lane = tid & 31, wid = tid >> 5;
    const int m0 = blockIdx.x * 128;
    const int tile = blockIdx.y;          // 0..8
    const int mat = tile / 3;
    const int n0 = (tile % 3) * 256;
    const int wm = wid & 3;               // m strip of 32
    const int wn = wid >> 2;              // n strip of 64

    const uint4* XH = (const uint4*)g_Xh;
    const uint4* XL = (const uint4*)g_Xl;
    const uint4* WH = (const uint4*)(g_Wh + (size_t)mat*Dm*Dm);
    const uint4* WL = (const uint4*)(g_Wl + (size_t)mat*Dm*Dm);
    const float* bias = (mat == 0) ? bq : (mat == 1) ? bk : bv;
    __nv_bfloat16* outH = (mat == 0) ? g_Qbh : (mat == 1) ? g_Kbh : g_Vbh;
    __nv_bfloat16* outL = (mat == 0) ? g_Qbl : (mat == 1) ? g_Kbl : g_Vbl;

    float acc[2][8][4];
    #pragma unroll
    for (int a = 0; a < 2; a++)
        #pragma unroll
        for (int b = 0; b < 8; b++)
            #pragma unroll
            for (int c = 0; c < 4; c++) acc[a][b][c] = 0.f;

    const int arow = tid >> 2, ac = tid & 3;    // arow 0..127

    #define ISSUE_STAGE(s) do { \
        const int _buf = (s) % 3; \
        const uint32_t _bb = sb + _buf*BUF_STRIDE; \
        const int _kc4 = (s)*4; \
        { \
            uint32_t _so = _bb + arow*80 + ac*16; \
            CP_ASYNC16(_so, &XH[(size_t)(m0 + arow)*96 + _kc4 + ac]); \
            CP_ASYNC16(_so + BUFA_L, &XL[(size_t)(m0 + arow)*96 + _kc4 + ac]); \
        } \
        _Pragma("unroll") \
        for (int _i = 0; _i < 2; _i++) { \
            int _row = arow + _i*128; \
            uint32_t _so = _bb + BUFB_H + _row*80 + ac*16; \
            CP_ASYNC16(_so, &WH[(size_t)(n0 + _row)*96 + _kc4 + ac]); \
            CP_ASYNC16(_so + (BUFB_L - BUFB_H), &WL[(size_t)(n0 + _row)*96 + _kc4 + ac]); \
        } \
        CP_COMMIT(); \
    } while (0)

    ISSUE_STAGE(0);
    ISSUE_STAGE(1);

    const int blrow = (lane & 7);
    const int bhalf = ((lane >> 3) & 1)*16;
    const int bhi = (lane >> 4)*8;

    for (int s = 0; s < 24; s++) {
        if (s < 23) { asm volatile("cp.async.wait_group 1;" ::: "memory"); }
        else        { asm volatile("cp.async.wait_group 0;" ::: "memory"); }
        __syncthreads();
        if (s + 2 < 24) ISSUE_STAGE(s + 2);
        const uint32_t base = sb + (s % 3)*BUF_STRIDE;

        #pragma unroll
        for (int kk = 0; kk < 2; kk++) {
            const uint32_t koff = kk*32;
            uint32_t ah[2][4], al[2][4];
            #pragma unroll
            for (int mt = 0; mt < 2; mt++) {
                int row = wm*32 + mt*16 + (lane & 7) + ((lane >> 3) & 1)*8;
                uint32_t ad = base + row*80 + koff + (lane >> 4)*16;
                ldsm4(ah[mt][0], ah[mt][1], ah[mt][2], ah[mt][3], ad);
                ldsm4(al[mt][0], al[mt][1], al[mt][2], al[mt][3], ad + BUFA_L);
            }
            // double-buffered B-hi fragments; B-lo loaded per-np ahead of its (last) consumers
            uint32_t bh[2][4], bl[4];
            {
                int n = wn*64 + blrow + bhi;
                uint32_t bd = base + BUFB_H + n*80 + koff + bhalf;
                ldsm4(bh[0][0], bh[0][1], bh[0][2], bh[0][3], bd);
            }
            #pragma unroll
            for (int np = 0; np < 4; np++) {
                const int cb = np & 1;
                {   // B-lo for this np (consumed last in the mma group)
                    int n = wn*64 + np*16 + blrow + bhi;
                    uint32_t bd = base + BUFB_L + n*80 + koff + bhalf;
                    ldsm4(bl[0], bl[1], bl[2], bl[3], bd);
                }
                if (np < 3) {   // B-hi for next np
                    int n = wn*64 + (np+1)*16 + blrow + bhi;
                    uint32_t bd = base + BUFB_H + n*80 + koff + bhalf;
                    ldsm4(bh[cb^1][0], bh[cb^1][1], bh[cb^1][2], bh[cb^1][3], bd);
                }
                #pragma unroll
                for (int mt = 0; mt < 2; mt++) {
                    mma16816(acc[mt][np*2],   ah[mt][0], ah[mt][1], ah[mt][2], ah[mt][3], bh[cb][0], bh[cb][1]);
                    mma16816(acc[mt][np*2+1], ah[mt][0], ah[mt][1], ah[mt][2], ah[mt][3], bh[cb][2], bh[cb][3]);
                    mma16816(acc[mt][np*2],   al[mt][0], al[mt][1], al[mt][2], al[mt][3], bh[cb][0], bh[cb][1]);
                    mma16816(acc[mt][np*2+1], al[mt][0], al[mt][1], al[mt][2], al[mt][3], bh[cb][2], bh[cb][3]);
                    mma16816(acc[mt][np*2],   ah[mt][0], ah[mt][1], ah[mt][2], ah[mt][3], bl[0], bl[1]);
                    mma16816(acc[mt][np*2+1], ah[mt][0], ah[mt][1], ah[mt][2], ah[mt][3], bl[2], bl[3]);
                }
            }
        }
    }

    const int h = (n0 + wn*64) >> 6;
    const float* bp = bias + n0 + wn*64;
    float2 bias2[8];
    #pragma unroll
    for (int nt = 0; nt < 8; nt++) bias2[nt] = *(const float2*)(bp + nt*8 + (lane & 3)*2);

    #pragma unroll
    for (int mt = 0; mt < 2; mt++) {
        #pragma unroll
        for (int half = 0; half < 2; half++) {
            int m = m0 + wm*32 + mt*16 + (lane >> 2) + half*8;
            int bbm = m >> 12, sx = m & 4095;
            float mv = mask[(size_t)bbm*Ss + sx];
            size_t ob = ((size_t)(bbm*Hh + h)*Ss + sx)*HD;
            #pragma unroll
            for (int nt = 0; nt < 8; nt++) {
                int col = nt*8 + (lane & 3)*2;
                float wx = (acc[mt][nt][half*2+0] + bias2[nt].x)*mv;
                float wy = (acc[mt][nt][half*2+1] + bias2[nt].y)*mv;
                __nv_bfloat162 hv = __floats2bfloat162_rn(wx, wy);
                float hx = __bfloat162float(__low2bfloat16(hv));
                float hy = __bfloat162float(__high2bfloat16(hv));
                __nv_bfloat162 lv = __floats2bfloat162_rn(wx - hx, wy - hy);
                *(__nv_bfloat162*)(outH + ob + col) = hv;
                *(__nv_bfloat162*)(outL + ob + col) = lv;
            }
        }
    }
}

// ---------------- kernel 1b: exact fp32 block-mean projection ----------------
__global__ __launch_bounds__(256) void hmean_gemm_kernel(
    const float* __restrict__ Wq, const float* __restrict__ Wk, const float* __restrict__ Wv,
    const float* __restrict__ bq, const float* __restrict__ bk, const float* __restrict__ bv)
{
    __shared__ float As[32][33];
    __shared__ float Bs[128][33];

    const int mat = blockIdx.z;
    const float* W = (mat == 0) ? Wq : (mat == 1) ? Wk : Wv;
    const float* bias = (mat == 0) ? bq : (mat == 1) ? bk : bv;
    float* out = (mat == 0) ? g_Qh : (mat == 1) ? g_Kh : g_Vh;

    const int tid = threadIdx.x;
    const int r0 = blockIdx.x * 32;
    const int e0 = blockIdx.y * 128;
    const int tn = tid >> 4;
    const int tm2 = tid & 15;

    float acc0[8], acc1[8];
    #pragma unroll
    for (int j = 0; j < 8; j++) { acc0[j] = 0.f; acc1[j] = 0.f; }

    for (int k0 = 0; k0 < Dm; k0 += 32) {
        {
            int r = tid >> 3, kq = tid & 7;
            float4 v = *(const float4*)&g_Xbar[(size_t)(r0 + r)*Dm + k0 + kq*4];
            As[r][kq*4+0] = v.x; As[r][kq*4+1] = v.y; As[r][kq*4+2] = v.z; As[r][kq*4+3] = v.w;
        }
        #pragma unroll
        for (int t = 0; t < 4; t++) {
            int idx = tid + t*256;
            int r = idx >> 3, kq = idx & 7;
            float4 v = *(const float4*)&W[(size_t)(e0 + r)*Dm + k0 + kq*4];
            Bs[r][kq*4+0] = v.x; Bs[r][kq*4+1] = v.y; Bs[r][kq*4+2] = v.z; Bs[r][kq*4+3] = v.w;
        }
        __syncthreads();
        #pragma unroll 8
        for (int k = 0; k < 32; k++) {
            float a0 = As[tm2*2][k], a1 = As[tm2*2+1][k];
            #pragma unroll
            for (int j = 0; j < 8; j++) {
                float b = Bs[tn*8+j][k];
                acc0[j] += a0*b;
                acc1[j] += a1*b;
            }
        }
        __syncthreads();
    }

    #pragma unroll
    for (int i = 0; i < 2; i++) {
        const int r = r0 + tm2*2 + i;
        const int bb2 = r >> 7, n = r & 127;
        const float tcf = g_tcf[r];
        const float* av = i ? acc1 : acc0;
        #pragma unroll
        for (int j = 0; j < 8; j++) {
            int e = e0 + tn*8 + j;
            int hh = e >> 6, hd = e & 63;
            out[(((size_t)(bb2*Hh + hh))*NBR + n)*HD + hd] = av[j] + bias[e]*tcf;
        }
    }
}

// ---------------- kernel 3: low-res logits (16 q-rows per CTA) ----------------
__global__ __launch_bounds__(256) void lowlogit_kernel()
{
    const int mb = blockIdx.y, q0 = blockIdx.x*16;
    const int bb = mb / Hh;
    const int tid = threadIdx.x;
    __shared__ float Kt[64][129];     // [d][m]
    __shared__ float Qhs[16][65];
    __shared__ float tcs[NBR];

    for (int i = tid; i < NBR*HD; i += 256) {
        int m = i >> 6, d = i & 63;
        Kt[d][m] = g_Kh[((size_t)mb*NBR + m)*HD + d];
    }
    for (int i = tid; i < 16*HD; i += 256) {
        int qq = i >> 6, d = i & 63;
        Qhs[qq][d] = g_Qh[((size_t)mb*NBR + q0 + qq)*HD + d];
    }
    if (tid < NBR) tcs[tid] = g_tcb[bb*NBR + tid];
    __syncthreads();

    const int q = tid >> 4, mg = tid & 15;
    float s[8];
    #pragma unroll
    for (int k = 0; k < 8; k++) s[k] = 0.f;
    for (int d = 0; d < HD; d++) {
        float qv = Qhs[q][d];
        const float* kr = &Kt[d][mg];
        #pragma unroll
        for (int k = 0; k < 8; k++) s[k] += qv*kr[16*k];
    }
    #pragma unroll
    for (int k = 0; k < 8; k++) s[k] *= 0.125f;

    // row max (pre empty-pair mask)
    float mx = s[0];
    #pragma unroll
    for (int k = 1; k < 8; k++) mx = fmaxf(mx, s[k]);
    #pragma unroll
    for (int off = 8; off >= 1; off >>= 1)
        mx = fmaxf(mx, __shfl_xor_sync(0xffffffffu, mx, off, 16));
    const int n = q0 + q;
    if (mg == 0) g_rowmax[mb*NBR + n] = mx;

    const float tcn = tcs[n];
    float* llr = g_ll + ((size_t)mb*NBR + n)*NBR;
    float* prr = g_prior + ((size_t)mb*NBR + n)*NBR;
    #pragma unroll
    for (int k = 0; k < 8; k++) {
        int m = mg + 16*k;
        float pe = (tcn*tcs[m] < 0.5f) ? 1.0f : 0.0f;
        float ll = s[k] - 1e4f*pe;
        float prior = ll - mx;
        int dif = n - m; if (dif < 0) dif = -dif;
        if (dif <= 1) prior += 5e3f;
        llr[m] = ll;
        prr[m] = prior;
    }
}

// ---------------- kernel 4: exact 1024-th largest via byte radix select ----------------
__global__ void thresh_kernel()
{
    int mb = blockIdx.x;
    const float* pr = g_prior + (size_t)mb*NBR*NBR;
    __shared__ unsigned hist[256];
    __shared__ unsigned s_prefix;
    __shared__ int s_k;
    int tid = threadIdx.x;   // 256
    int lane = tid & 31;
    if (tid == 0) { s_prefix = 0u; s_k = NUMBLK; }
    for (int pass = 0; pass < 4; pass++) {
        int shift = 24 - pass*8;
        hist[tid] = 0u;
        __syncthreads();
        unsigned pref = s_prefix;
        for (int i = tid; i < NBR*NBR; i += 256) {
            unsigned u = f2ord(pr[i]);
            bool ok = (pass == 0) ? true : (((u ^ pref) >> (shift + 8)) == 0u);
            unsigned bin = ok ? ((u >> shift) & 255u) : 0xFFFFFFFFu;
            unsigned mm = __match_any_sync(0xffffffffu, bin);
            if (bin != 0xFFFFFFFFu && (__ffs(mm) - 1) == lane)
                atomicAdd(&hist[bin], __popc(mm));
        }
        __syncthreads();
        if (tid == 0) {
            int k = s_k; unsigned cum = 0u; int sel = 0;
            for (int bbin = 255; bbin >= 0; bbin--) {
                unsigned h = hist[bbin];
                if (cum + h >= (unsigned)k) { sel = bbin; break; }
                cum += h;
            }
            s_k = k - (int)cum;
            s_prefix = pref | ((unsigned)sel << shift);
        }
        __syncthreads();
    }
    if (tid == 0) {
        unsigned u = s_prefix;
        unsigned raw = (u & 0x80000000u) ? (u & 0x7FFFFFFFu) : ~u;
        g_thresh[mb] = __uint_as_float(raw);
    }
}

// ---------------- kernel 5: deterministic per-(mb,q) selected k-block lists ----------------
__global__ void select_kernel()
{
    int mb = blockIdx.x;
    int n = threadIdx.x;           // 128
    float t = g_thresh[mb];
    const float* pr = g_prior + ((size_t)mb*NBR + n)*NBR;
    int* lst = g_list + ((size_t)mb*NBR + n)*NBR;
    int c = 0;
    for (int m = 0; m < NBR; m++)
        if (pr[m] >= t) lst[c++] = m;
    g_cnt[mb*NBR + n] = c;
}

// ---------------- kernel 6: high-res sparse attention via mma.sync (split bf16) ----------------
#define OKH 0
#define OKL 9216
#define OVH 18432
#define OVL 27648
#define OKM 36864
#define OPH 37120
#define OPL 39680
#define OMAXP 42240
#define OSUMP 42752
#define ORM 43264
#define OSC 43392
#define ONRM 43520
#define HR_SMEM 43648

__global__ __launch_bounds__(128) void highres_kernel(const float* __restrict__ mask)
{
    __shared__ __align__(16) char sm[HR_SMEM];
    const uint32_t sb = smem_u32(sm);
    const int mbn = blockIdx.x;
    const int mb = mbn >> 7, q = mbn & 127;
    const int bb = mb / Hh;
    const int tid = threadIdx.x;
    const int lane = tid & 31, w = tid >> 5;

    const int nb = g_cnt[mbn];
    const int* lst = g_list + (size_t)mbn*NBR;
    const size_t qrow = (size_t)mb*Ss + q*BLKSZ;

    float* RM  = (float*)(sm + ORM);
    float* SC  = (float*)(sm + OSC);
    float* NRM = (float*)(sm + ONRM);
    float* MAXP = (float*)(sm + OMAXP);
    float* SUMP = (float*)(sm + OSUMP);

    for (int i = tid; i < 256; i += 128) {
        int r = i >> 3, ch = i & 7;
        *(uint4*)(sm + OKH + r*144 + ch*16)        = ((const uint4*)(g_Qbh + (qrow + r)*HD))[ch];
        *(uint4*)(sm + OKH + 4608 + r*144 + ch*16) = ((const uint4*)(g_Qbl + (qrow + r)*HD))[ch];
    }
    if (tid < 32) { RM[tid] = -1e30f; NRM[tid] = 0.f; }
    __syncthreads();

    uint32_t aQh[2][4][4], aQl[2][4][4];
    #pragma unroll
    for (int mt = 0; mt < 2; mt++) {
        int row = mt*16 + (lane & 7) + ((lane >> 3) & 1)*8;
        #pragma unroll
        for (int ks = 0; ks < 4; ks++) {
            uint32_t ad = sb + OKH + row*144 + (ks*2 + (lane >> 4))*16;
            ldsm4(aQh[mt][ks][0], aQh[mt][ks][1], aQh[mt][ks][2], aQh[mt][ks][3], ad);
            ldsm4(aQl[mt][ks][0], aQl[mt][ks][1], aQl[mt][ks][2], aQl[mt][ks][3], ad + 4608);
        }
    }
    __syncthreads();

    float o[2][2][4];
    #pragma unroll
    for (int mt = 0; mt < 2; mt++)
        #pragma unroll
        for (int nt = 0; nt < 2; nt++)
            #pragma unroll
            for (int j = 0; j < 4; j++) o[mt][nt][j] = 0.f;

    #define HR_LOAD(st, kb) do { \
        size_t _rb = (size_t)mb*Ss + (size_t)(kb)*BLKSZ; \
        for (int _i = tid; _i < 256; _i += 128) { \
            int _r = _i >> 3, _ch = _i & 7; \
            uint32_t _so = (st)*4608 + _r*144 + _ch*16; \
            CP_ASYNC16(sb + OKH + _so, ((const uint4*)(g_Kbh + (_rb + _r)*HD)) + _ch); \
            CP_ASYNC16(sb + OKL + _so, ((const uint4*)(g_Kbl + (_rb + _r)*HD)) + _ch); \
            CP_ASYNC16(sb + OVH + _so, ((const uint4*)(g_Vbh + (_rb + _r)*HD)) + _ch); \
            CP_ASYNC16(sb + OVL + _so, ((const uint4*)(g_Vbl + (_rb + _r)*HD)) + _ch); \
        } \
        if (tid < 8) CP_ASYNC16(sb + OKM + (st)*128 + tid*16, &mask[(size_t)bb*Ss + (size_t)(kb)*BLKSZ + tid*4]); \
        CP_COMMIT(); \
    } while (0)

    if (nb > 0) HR_LOAD(0, lst[0]);

    for (int it = 0; it < nb; it++) {
        const int cur = it & 1;
        if (it + 1 < nb) {
            HR_LOAD((it+1) & 1, lst[it+1]);
            asm volatile("cp.async.wait_group 1;" ::: "memory");
        } else {
            asm volatile("cp.async.wait_group 0;" ::: "memory");
        }
        __syncthreads();

        // ---- S = Qh*Kh + Qh*Kl + Ql*Kh  (K frags hoisted before mma chain) ----
        float sacc[2][4];
        #pragma unroll
        for (int mt = 0; mt < 2; mt++)
            #pragma unroll
            for (int j = 0; j < 4; j++) sacc[mt][j] = 0.f;

        const uint32_t khb = sb + OKH + cur*4608;
        uint32_t kbh[4][2], kbl[4][2];
        #pragma unroll
        for (int ks = 0; ks < 4; ks++) {
            uint32_t baddr = khb + (8*w + (lane & 7))*144 + (ks*2 + ((lane >> 3) & 1))*16;
            ldsm2(kbh[ks][0], kbh[ks][1], baddr);
            ldsm2(kbl[ks][0], kbl[ks][1], baddr + (OKL - OKH));
        }
        #pragma unroll
        for (int ks = 0; ks < 4; ks++) {
            #pragma unroll
            for (int mt = 0; mt < 2; mt++) {
                mma16816(sacc[mt], aQh[mt][ks][0], aQh[mt][ks][1], aQh[mt][ks][2], aQh[mt][ks][3], kbh[ks][0], kbh[ks][1]);
                mma16816(sacc[mt], aQh[mt][ks][0], aQh[mt][ks][1], aQh[mt][ks][2], aQh[mt][ks][3], kbl[ks][0], kbl[ks][1]);
                mma16816(sacc[mt], aQl[mt][ks][0], aQl[mt][ks][1], aQl[mt][ks][2], aQl[mt][ks][3], kbh[ks][0], kbh[ks][1]);
            }
        }
        #pragma unroll
        for (int mt = 0; mt < 2; mt++)
            #pragma unroll
            for (int j = 0; j < 4; j++) sacc[mt][j] *= 0.125f;

        #pragma unroll
        for (int mt = 0; mt < 2; mt++) {
            float m1 = fmaxf(sacc[mt][0], sacc[mt][1]);
            float m2 = fmaxf(sacc[mt][2], sacc[mt][3]);
            m1 = fmaxf(m1, __shfl_xor_sync(0xffffffffu, m1, 1, 4));
            m1 = fmaxf(m1, __shfl_xor_sync(0xffffffffu, m1, 2, 4));
            m2 = fmaxf(m2, __shfl_xor_sync(0xffffffffu, m2, 1, 4));
            m2 = fmaxf(m2, __shfl_xor_sync(0xffffffffu, m2, 2, 4));
            if ((lane & 3) == 0) {
                int r1 = mt*16 + (lane >> 2);
                MAXP[r1*4 + w] = m1;
                MAXP[(r1+8)*4 + w] = m2;
            }
        }
        __syncthreads();
        if (tid < 32) {
            float tm = fmaxf(fmaxf(MAXP[tid*4], MAXP[tid*4+1]), fmaxf(MAXP[tid*4+2], MAXP[tid*4+3]));
            float old = RM[tid];
            float nm = fmaxf(old, tm);
            SC[tid] = __expf(old - nm);
            RM[tid] = nm;
        }
        __syncthreads();

        const float kmv0 = ((const float*)(sm + OKM + cur*128))[8*w + (lane & 3)*2];
        const float kmv1 = ((const float*)(sm + OKM + cur*128))[8*w + (lane & 3)*2 + 1];
        const float pen0 = 1e4f*(1.f - kmv0), pen1 = 1e4f*(1.f - kmv1);
        const int colb = (8*w + (lane & 3)*2)*2;

        #pragma unroll
        for (int mt = 0; mt < 2; mt++) {
            int r1 = mt*16 + (lane >> 2), r2 = r1 + 8;
            float sc1 = SC[r1], sc2 = SC[r2];
            float rm1 = RM[r1], rm2 = RM[r2];
            #pragma unroll
            for (int nt = 0; nt < 2; nt++) {
                o[mt][nt][0] *= sc1; o[mt][nt][1] *= sc1;
                o[mt][nt][2] *= sc2; o[mt][nt][3] *= sc2;
            }
            float p00 = __expf(sacc[mt][0] - rm1 - pen0);
            float p01 = __expf(sacc[mt][1] - rm1 - pen1);
            float p10 = __expf(sacc[mt][2] - rm2 - pen0);
            float p11 = __expf(sacc[mt][3] - rm2 - pen1);

            __nv_bfloat162 ph0 = __floats2bfloat162_rn(p00, p01);
            __nv_bfloat162 pl0 = __floats2bfloat162_rn(
                p00 - __bfloat162float(__low2bfloat16(ph0)),
                p01 - __bfloat162float(__high2bfloat16(ph0)));
            __nv_bfloat162 ph1 = __floats2bfloat162_rn(p10, p11);
            __nv_bfloat162 pl1 = __floats2bfloat162_rn(
                p10 - __bfloat162float(__low2bfloat16(ph1)),
                p11 - __bfloat162float(__high2bfloat16(ph1)));
            *(__nv_bfloat162*)(sm + OPH + r1*80 + colb) = ph0;
            *(__nv_bfloat162*)(sm + OPL + r1*80 + colb) = pl0;
            *(__nv_bfloat162*)(sm + OPH + r2*80 + colb) = ph1;
            *(__nv_bfloat162*)(sm + OPL + r2*80 + colb) = pl1;

            float s1 = p00 + p01, s2 = p10 + p11;
            s1 += __shfl_xor_sync(0xffffffffu, s1, 1, 4);
            s1 += __shfl_xor_sync(0xffffffffu, s1, 2, 4);
            s2 += __shfl_xor_sync(0xffffffffu, s2, 1, 4);
            s2 += __shfl_xor_sync(0xffffffffu, s2, 2, 4);
            if ((lane & 3) == 0) {
                SUMP[r1*4 + w] = s1;
                SUMP[r2*4 + w] = s2;
            }
        }
        __syncthreads();
        if (tid < 32) {
            float s = SUMP[tid*4] + SUMP[tid*4+1] + SUMP[tid*4+2] + SUMP[tid*4+3];
            NRM[tid] = NRM[tid]*SC[tid] + s;
        }

        const uint32_t vhb = sb + OVH + cur*4608;
        #pragma unroll
        for (int ks = 0; ks < 2; ks++) {
            uint32_t aPh[2][4], aPl[2][4];
            #pragma unroll
            for (int mt = 0; mt < 2; mt++) {
                int row = mt*16 + (lane & 7) + ((lane >> 3) & 1)*8;
                uint32_t pad = sb + OPH + row*80 + (ks*2 + (lane >> 4))*16;
                ldsm4(aPh[mt][0], aPh[mt][1], aPh[mt][2], aPh[mt][3], pad);
                ldsm4(aPl[mt][0], aPl[mt][1], aPl[mt][2], aPl[mt][3], pad + (OPL - OPH));
            }
            int vrow = ks*16 + (lane & 7) + ((lane >> 3) & 1)*8;
            uint32_t vad = vhb + vrow*144 + (2*w + (lane >> 4))*16;
            uint32_t bh0, bh1, bh2, bh3, bl0, bl1, bl2, bl3;
            ldsm4t(bh0, bh1, bh2, bh3, vad);
            ldsm4t(bl0, bl1, bl2, bl3, vad + (OVL - OVH));
            #pragma unroll
            for (int mt = 0; mt < 2; mt++) {
                mma16816(o[mt][0], aPh[mt][0], aPh[mt][1], aPh[mt][2], aPh[mt][3], bh0, bh1);
                mma16816(o[mt][1], aPh[mt][0], aPh[mt][1], aPh[mt][2], aPh[mt][3], bh2, bh3);
                mma16816(o[mt][0], aPh[mt][0], aPh[mt][1], aPh[mt][2], aPh[mt][3], bl0, bl1);
                mma16816(o[mt][1], aPh[mt][0], aPh[mt][1], aPh[mt][2], aPh[mt][3], bl2, bl3);
                mma16816(o[mt][0], aPl[mt][0], aPl[mt][1], aPl[mt][2], aPl[mt][3], bh0, bh1);
                mma16816(o[mt][1], aPl[mt][0], aPl[mt][1], aPl[mt][2], aPl[mt][3], bh2, bh3);
            }
        }
        __syncthreads();
    }

    #pragma unroll
    for (int mt = 0; mt < 2; mt++) {
        int r1 = mt*16 + (lane >> 2), r2 = r1 + 8;
        #pragma unroll
        for (int nt = 0; nt < 2; nt++) {
            int col = 16*w + nt*8 + (lane & 3)*2;
            float2 w1 = make_float2(o[mt][nt][0], o[mt][nt][1]);
            float2 w2 = make_float2(o[mt][nt][2], o[mt][nt][3]);
            *(float2*)&g_high_out[(qrow + r1)*HD + col] = w1;
            *(float2*)&g_high_out[(qrow + r2)*HD + col] = w2;
        }
    }
    if (tid < 32) {
        g_maxrows[qrow + tid] = fmaxf(RM[tid], -1e6f);
        g_high_norm[qrow + tid] = NRM[tid];
    }
}

// ---------------- kernel 7: low-res attention (16 n-rows per CTA) ----------------
__global__ __launch_bounds__(256) void lowres_kernel()
{
    const int mb = blockIdx.y, n0 = blockIdx.x*16;
    const int bb = mb / Hh;
    const int tid = threadIdx.x;
    __shared__ float4 V4[NBR][16];
    __shared__ float a_sh[16][129];
    __shared__ float tcs[NBR];

    for (int i = tid; i < NBR*16; i += 256) {
        int m = i >> 4, dg = i & 15;
        V4[m][dg] = *(const float4*)&g_Vh[((size_t)mb*NBR + m)*HD + dg*4];
    }
    if (tid < NBR) tcs[tid] = g_tcb[bb*NBR + tid];
    __syncthreads();

    const int nn = tid >> 4, mg = tid & 15;
    const int n = n0 + nn;
    const float rmv = g_rowmax[mb*NBR + n];
    const float t = g_thresh[mb];
    const float* llr = g_ll + ((size_t)mb*NBR + n)*NBR;
    const float* prr = g_prior + ((size_t)mb*NBR + n)*NBR;
    float psum = 0.f;
    #pragma unroll
    for (int k = 0; k < 8; k++) {
        int m = mg + 16*k;
        float sel = (prr[m] >= t) ? 1e4f : 0.f;
        float a = __expf(llr[m] - rmv - sel) * tcs[m];
        a_sh[nn][m] = a;
        psum += a;
    }
    #pragma unroll
    for (int off = 8; off >= 1; off >>= 1)
        psum += __shfl_xor_sync(0xffffffffu, psum, off, 16);
    if (mg == 0) g_low_norm[mb*NBR + n] = psum;
    __syncthreads();

    // matvec: thread (nn, dg) computes dims dg*4..+3 for row nn (m sequential)
    {
        const int dg = tid & 15;
        const float* ar = a_sh[tid >> 4];
        float4 acc = make_float4(0.f, 0.f, 0.f, 0.f);
        #pragma unroll 8
        for (int m = 0; m < NBR; m++) {
            float av = ar[m];
            float4 v = V4[m][dg];
            acc.x += av*v.x; acc.y += av*v.y; acc.z += av*v.z; acc.w += av*v.w;
        }
        *(float4*)&g_low_out[((size_t)mb*NBR + n0 + (tid >> 4))*HD + dg*4] = acc;
    }
}

// ---------------- kernel 8: combine + final layout ----------------
__global__ void combine_kernel(const float* __restrict__ mask, float* __restrict__ out)
{
    int mb = blockIdx.y;
    int tid = threadIdx.x;                 // 256 = 4 tokens x 64 dims
    int s = blockIdx.x*4 + (tid >> 6);
    int hd = tid & 63;
    int bb = mb / Hh, h = mb % Hh;
    int blk = s >> 5;
    float mval = mask[(size_t)bb*Ss + s];
    float lcl = (g_rowmax[mb*NBR + blk] - g_maxrows[(size_t)mb*Ss + s]) * mval;
    float lcorr = __expf(fminf(lcl, 0.f));
    float hcorr = __expf(-fmaxf(lcl, 0.f));
    float hn = g_high_norm[(size_t)mb*Ss + s];
    float ln = g_low_norm[mb*NBR + blk];
    float inv = 1.0f / (hn*hcorr + ln*lcorr + 1e-6f);
    float val = (g_high_out[((size_t)mb*Ss + s)*HD + hd]*hcorr
               + g_low_out[((size_t)mb*NBR + blk)*HD + hd]*lcorr) * inv;
    out[((size_t)bb*Ss + s)*Dm + h*HD + hd] = val;
}

// ---------------- launch ----------------
extern "C" void kernel_launch(void* const* d_in, const int* in_sizes, int n_in,
                              void* d_out, int out_size)
{
    const float* X    = (const float*)d_in[0];
    const float* mask = (const float*)d_in[1];
    const float* Wq   = (const float*)d_in[2];
    const float* bq   = (const float*)d_in[3];
    const float* Wk   = (const float*)d_in[4];
    const float* bk   = (const float*)d_in[5];
    const float* Wv   = (const float*)d_in[6];
    const float* bv   = (const float*)d_in[7];
    float* out = (float*)d_out;

    cudaFuncSetAttribute(qkv_mma_kernel, cudaFuncAttributeMaxDynamicSharedMemorySize, GEMM_SMEM);

    convX_kernel<<<MROWS*Dm/1024, 256>>>(X);                       // 1
    convW_kernel<<<dim3(Dm*Dm/1024, 3), 256>>>(Wq, Wk, Wv);        // 2
    xbar_kernel<<<Bb*NBR, Dm>>>(X, mask);                          // 3
    qkv_mma_kernel<<<dim3(MROWS/128, 9), 512, GEMM_SMEM>>>(mask, bq, bk, bv);  // 4 (profiled slot)
    hmean_gemm_kernel<<<dim3(8, 6, 3), 256>>>(Wq, Wk, Wv, bq, bk, bv);         // 5
    lowlogit_kernel<<<dim3(8, MBT), 256>>>();                      // 6
    thresh_kernel<<<MBT, 256>>>();                                 // 7
    select_kernel<<<MBT, 128>>>();                                 // 8
    highres_kernel<<<MBT*NBR, 128>>>(mask);                        // 9
    lowres_kernel<<<dim3(8, MBT), 256>>>();                        // 10
    combine_kernel<<<dim3(Ss/4, MBT), 256>>>(mask, out);           // 11
}

// round 10
// speedup vs baseline: 2.3127x; 1.0240x over previous
#include <cuda_runtime.h>
#include <cuda_bf16.h>
#include <cstdint>

// ---------------- problem constants ----------------
#define Bb 2
#define Ss 4096
#define Dm 768
#define Hh 12
#define HD 64
#define BLKSZ 32
#define NBR 128
#define NUMBLK 1024
#define MBT (Bb*Hh)        // 24
#define MROWS (Bb*Ss)      // 8192

typedef unsigned long long ull;

__device__ __forceinline__ uint32_t smem_u32(const void* p) {
    uint32_t a;
    asm("{ .reg .u64 t; cvta.to.shared.u64 t, %1; cvt.u32.u64 %0, t; }" : "=r"(a) : "l"(p));
    return a;
}
#define CP_ASYNC16(dst, src) \
    asm volatile("cp.async.cg.shared.global [%0], [%1], 16;" :: "r"(dst), "l"(src))
#define CP_COMMIT() asm volatile("cp.async.commit_group;" ::: "memory")

// ---------------- mma.sync helpers ----------------
__device__ __forceinline__ void ldsm4(uint32_t &r0, uint32_t &r1, uint32_t &r2, uint32_t &r3, uint32_t addr) {
    asm volatile("ldmatrix.sync.aligned.m8n8.x4.shared.b16 {%0,%1,%2,%3}, [%4];"
        : "=r"(r0), "=r"(r1), "=r"(r2), "=r"(r3) : "r"(addr));
}
__device__ __forceinline__ void ldsm2(uint32_t &r0, uint32_t &r1, uint32_t addr) {
    asm volatile("ldmatrix.sync.aligned.m8n8.x2.shared.b16 {%0,%1}, [%2];"
        : "=r"(r0), "=r"(r1) : "r"(addr));
}
__device__ __forceinline__ void ldsm4t(uint32_t &r0, uint32_t &r1, uint32_t &r2, uint32_t &r3, uint32_t addr) {
    asm volatile("ldmatrix.sync.aligned.m8n8.x4.trans.shared.b16 {%0,%1,%2,%3}, [%4];"
        : "=r"(r0), "=r"(r1), "=r"(r2), "=r"(r3) : "r"(addr));
}
__device__ __forceinline__ void mma16816(float* c,
    uint32_t a0, uint32_t a1, uint32_t a2, uint32_t a3, uint32_t b0, uint32_t b1) {
    asm volatile("mma.sync.aligned.m16n8k16.row.col.f32.bf16.bf16.f32 "
        "{%0,%1,%2,%3}, {%4,%5,%6,%7}, {%8,%9}, {%0,%1,%2,%3};"
        : "+f"(c[0]), "+f"(c[1]), "+f"(c[2]), "+f"(c[3])
        : "r"(a0), "r"(a1), "r"(a2), "r"(a3), "r"(b0), "r"(b1));
}

// fast exp on the fma/alu pipes (keeps MUFU free): exp(x) = 2^(x*log2e),
// magic-number round, 2^f Taylor deg-5 on [-0.5,0.5] (rel err ~2.4e-6).
__device__ __forceinline__ float fexp_poly(float x) {
    float z = x * 1.4426950408889634f;
    z = fmaxf(z, -120.f);
    float m = z + 12582912.0f;               // 1.5*2^23: round-to-nearest int
    int n = __float_as_int(m) - 0x4B400000;  // exact in-binade bit arithmetic
    float f = z - (m - 12582912.0f);
    float p = 1.3333558e-3f;
    p = fmaf(p, f, 9.6181291e-3f);
    p = fmaf(p, f, 5.5504109e-2f);
    p = fmaf(p, f, 2.4022651e-1f);
    p = fmaf(p, f, 6.9314718e-1f);
    p = fmaf(p, f, 1.0f);
    float r = __int_as_float(__float_as_int(p) + (n << 23));
    return (x < -80.f) ? 0.f : r;
}

// ---------------- device scratch ----------------
__device__ __nv_bfloat16 g_Qbh[MBT*Ss*HD];
__device__ __nv_bfloat16 g_Qbl[MBT*Ss*HD];
__device__ __nv_bfloat16 g_Kbh[MBT*Ss*HD];
__device__ __nv_bfloat16 g_Kbl[MBT*Ss*HD];
__device__ __nv_bfloat16 g_Vbh[MBT*Ss*HD];
__device__ __nv_bfloat16 g_Vbl[MBT*Ss*HD];
__device__ __nv_bfloat16 g_Xh[MROWS*Dm];
__device__ __nv_bfloat16 g_Xl[MROWS*Dm];
__device__ __nv_bfloat16 g_Wh[3*Dm*Dm];
__device__ __nv_bfloat16 g_Wl[3*Dm*Dm];
__device__ float g_Xbar[Bb*NBR*Dm];
__device__ float g_tcb[Bb*NBR];
__device__ float g_tcf[Bb*NBR];
__device__ float g_Qh[MBT*NBR*HD];
__device__ float g_Kh[MBT*NBR*HD];
__device__ float g_Vh[MBT*NBR*HD];
__device__ float g_ll[MBT*NBR*NBR];
__device__ float g_prior[MBT*NBR*NBR];
__device__ float g_rowmax[MBT*NBR];
__device__ float g_thresh[MBT];
__device__ int   g_cnt[MBT*NBR];
__device__ int   g_list[MBT*NBR*NBR];
__device__ float g_high_out[MBT*Ss*HD];
__device__ float g_high_norm[MBT*Ss];
__device__ float g_maxrows[MBT*Ss];
__device__ float g_low_out[MBT*NBR*HD];
__device__ float g_low_norm[MBT*NBR];

__device__ __forceinline__ unsigned f2ord(float f) {
    unsigned u = __float_as_uint(f);
    return (u & 0x80000000u) ? ~u : (u | 0x80000000u);
}

// ---------------- kernel 0a: split X into bf16 hi/lo ----------------
__global__ void convX_kernel(const float* __restrict__ X)
{
    int i = (blockIdx.x*256 + threadIdx.x)*4;
    float4 v = *(const float4*)(X + i);
    float vf[4] = {v.x, v.y, v.z, v.w};
    __nv_bfloat16 h[4], l[4];
    #pragma unroll
    for (int j = 0; j < 4; j++) {
        h[j] = __float2bfloat16(vf[j]);
        l[j] = __float2bfloat16(vf[j] - __bfloat162float(h[j]));
    }
    *(ull*)(g_Xh + i) = *(ull*)h;
    *(ull*)(g_Xl + i) = *(ull*)l;
}

// ---------------- kernel 0b: split W into bf16 hi/lo ----------------
__global__ void convW_kernel(const float* __restrict__ Wq,
                             const float* __restrict__ Wk,
                             const float* __restrict__ Wv)
{
    int mat = blockIdx.y;
    const float* W = (mat == 0) ? Wq : (mat == 1) ? Wk : Wv;
    int i = (blockIdx.x*256 + threadIdx.x)*4;
    float4 v = *(const float4*)(W + i);
    float vf[4] = {v.x, v.y, v.z, v.w};
    __nv_bfloat16 h[4], l[4];
    #pragma unroll
    for (int j = 0; j < 4; j++) {
        h[j] = __float2bfloat16(vf[j]);
        l[j] = __float2bfloat16(vf[j] - __bfloat162float(h[j]));
    }
    size_t o = (size_t)mat*Dm*Dm + i;
    *(ull*)(g_Wh + o) = *(ull*)h;
    *(ull*)(g_Wl + o) = *(ull*)l;
}

// ---------------- kernel 0c: masked block-mean of X ----------------
__global__ void xbar_kernel(const float* __restrict__ X, const float* __restrict__ mask)
{
    int bn = blockIdx.x;             // Bb*NBR
    int bb = bn >> 7, n = bn & 127;
    int d = threadIdx.x;             // 768
    const float* mrow = mask + (size_t)bb*Ss + n*BLKSZ;
    float tc = 0.f;
    #pragma unroll
    for (int t = 0; t < BLKSZ; t++) tc += mrow[t];
    float denom = tc + 1e-6f;
    const float* xp = X + ((size_t)bb*Ss + n*BLKSZ)*Dm + d;
    float s = 0.f;
    #pragma unroll 4
    for (int t = 0; t < BLKSZ; t++) s += mrow[t]*xp[(size_t)t*Dm];
    g_Xbar[(size_t)bn*Dm + d] = s/denom;
    if (d == 0) { g_tcb[bn] = tc; g_tcf[bn] = tc/denom; }
}

// ---------------- kernel 1: QKV projection via mma.sync bf16 (3-term split) ----------------
#define BUFA_L 10240
#define BUFB_H 20480
#define BUFB_L 40960
#define BUF_STRIDE 61440
#define GEMM_SMEM (3*BUF_STRIDE)

__global__ __launch_bounds__(512, 1) void qkv_mma_kernel(
    const float* __restrict__ mask,
    const float* __restrict__ bq, const float* __restrict__ bk, const float* __restrict__ bv)
{
    extern __shared__ __align__(16) char smem[];
    const uint32_t sb = smem_u32(smem);
    const int tid = threadIdx.x, lane = tid & 31, wid = tid >> 5;
    const int m0 = blockIdx.x * 128;
    const int tile = blockIdx.y;          // 0..8
    const int mat = tile / 3;
    const int n0 = (tile % 3) * 256;
    const int wm = wid & 3;               // m strip of 32
    const int wn = wid >> 2;              // n strip of 64

    const uint4* XH = (const uint4*)g_Xh;
    const uint4* XL = (const uint4*)g_Xl;
    const uint4* WH = (const uint4*)(g_Wh + (size_t)mat*Dm*Dm);
    const uint4* WL = (const uint4*)(g_Wl + (size_t)mat*Dm*Dm);
    const float* bias = (mat == 0) ? bq : (mat == 1) ? bk : bv;
    __nv_bfloat16* outH = (mat == 0) ? g_Qbh : (mat == 1) ? g_Kbh : g_Vbh;
    __nv_bfloat16* outL = (mat == 0) ? g_Qbl : (mat == 1) ? g_Kbl : g_Vbl;

    float acc[2][8][4];
    #pragma unroll
    for (int a = 0; a < 2; a++)
        #pragma unroll
        for (int b = 0; b < 8; b++)
            #pragma unroll
            for (int c = 0; c < 4; c++) acc[a][b][c] = 0.f;

    const int arow = tid >> 2, ac = tid & 3;    // arow 0..127

    #define ISSUE_STAGE(s) do { \
        const int _buf = (s) % 3; \
        const uint32_t _bb = sb + _buf*BUF_STRIDE; \
        const int _kc4 = (s)*4; \
        { \
            uint32_t _so = _bb + arow*80 + ac*16; \
            CP_ASYNC16(_so, &XH[(size_t)(m0 + arow)*96 + _kc4 + ac]); \
            CP_ASYNC16(_so + BUFA_L, &XL[(size_t)(m0 + arow)*96 + _kc4 + ac]); \
        } \
        _Pragma("unroll") \
        for (int _i = 0; _i < 2; _i++) { \
            int _row = arow + _i*128; \
            uint32_t _so = _bb + BUFB_H + _row*80 + ac*16; \
            CP_ASYNC16(_so, &WH[(size_t)(n0 + _row)*96 + _kc4 + ac]); \
            CP_ASYNC16(_so + (BUFB_L - BUFB_H), &WL[(size_t)(n0 + _row)*96 + _kc4 + ac]); \
        } \
        CP_COMMIT(); \
    } while (0)

    ISSUE_STAGE(0);
    ISSUE_STAGE(1);

    const int blrow = (lane & 7);
    const int bhalf = ((lane >> 3) & 1)*16;
    const int bhi = (lane >> 4)*8;

    for (int s = 0; s < 24; s++) {
        if (s < 23) { asm volatile("cp.async.wait_group 1;" ::: "memory"); }
        else        { asm volatile("cp.async.wait_group 0;" ::: "memory"); }
        __syncthreads();
        if (s + 2 < 24) ISSUE_STAGE(s + 2);
        const uint32_t base = sb + (s % 3)*BUF_STRIDE;

        #pragma unroll
        for (int kk = 0; kk < 2; kk++) {
            const uint32_t koff = kk*32;
            uint32_t ah[2][4], al[2][4];
            #pragma unroll
            for (int mt = 0; mt < 2; mt++) {
                int row = wm*32 + mt*16 + (lane & 7) + ((lane >> 3) & 1)*8;
                uint32_t ad = base + row*80 + koff + (lane >> 4)*16;
                ldsm4(ah[mt][0], ah[mt][1], ah[mt][2], ah[mt][3], ad);
                ldsm4(al[mt][0], al[mt][1], al[mt][2], al[mt][3], ad + BUFA_L);
            }
            uint32_t bh[2][4], bl[4];
            {
                int n = wn*64 + blrow + bhi;
                uint32_t bd = base + BUFB_H + n*80 + koff + bhalf;
                ldsm4(bh[0][0], bh[0][1], bh[0][2], bh[0][3], bd);
            }
            #pragma unroll
            for (int np = 0; np < 4; np++) {
                const int cb = np & 1;
                {
                    int n = wn*64 + np*16 + blrow + bhi;
                    uint32_t bd = base + BUFB_L + n*80 + koff + bhalf;
                    ldsm4(bl[0], bl[1], bl[2], bl[3], bd);
                }
                if (np < 3) {
                    int n = wn*64 + (np+1)*16 + blrow + bhi;
                    uint32_t bd = base + BUFB_H + n*80 + koff + bhalf;
                    ldsm4(bh[cb^1][0], bh[cb^1][1], bh[cb^1][2], bh[cb^1][3], bd);
                }
                #pragma unroll
                for (int mt = 0; mt < 2; mt++) {
                    mma16816(acc[mt][np*2],   ah[mt][0], ah[mt][1], ah[mt][2], ah[mt][3], bh[cb][0], bh[cb][1]);
                    mma16816(acc[mt][np*2+1], ah[mt][0], ah[mt][1], ah[mt][2], ah[mt][3], bh[cb][2], bh[cb][3]);
                    mma16816(acc[mt][np*2],   al[mt][0], al[mt][1], al[mt][2], al[mt][3], bh[cb][0], bh[cb][1]);
                    mma16816(acc[mt][np*2+1], al[mt][0], al[mt][1], al[mt][2], al[mt][3], bh[cb][2], bh[cb][3]);
                    mma16816(acc[mt][np*2],   ah[mt][0], ah[mt][1], ah[mt][2], ah[mt][3], bl[0], bl[1]);
                    mma16816(acc[mt][np*2+1], ah[mt][0], ah[mt][1], ah[mt][2], ah[mt][3], bl[2], bl[3]);
                }
            }
        }
    }

    const int h = (n0 + wn*64) >> 6;
    const float* bp = bias + n0 + wn*64;
    float2 bias2[8];
    #pragma unroll
    for (int nt = 0; nt < 8; nt++) bias2[nt] = *(const float2*)(bp + nt*8 + (lane & 3)*2);

    #pragma unroll
    for (int mt = 0; mt < 2; mt++) {
        #pragma unroll
        for (int half = 0; half < 2; half++) {
            int m = m0 + wm*32 + mt*16 + (lane >> 2) + half*8;
            int bbm = m >> 12, sx = m & 4095;
            float mv = mask[(size_t)bbm*Ss + sx];
            size_t ob = ((size_t)(bbm*Hh + h)*Ss + sx)*HD;
            #pragma unroll
            for (int nt = 0; nt < 8; nt++) {
                int col = nt*8 + (lane & 3)*2;
                float wx = (acc[mt][nt][half*2+0] + bias2[nt].x)*mv;
                float wy = (acc[mt][nt][half*2+1] + bias2[nt].y)*mv;
                __nv_bfloat162 hv = __floats2bfloat162_rn(wx, wy);
                float hx = __bfloat162float(__low2bfloat16(hv));
                float hy = __bfloat162float(__high2bfloat16(hv));
                __nv_bfloat162 lv = __floats2bfloat162_rn(wx - hx, wy - hy);
                *(__nv_bfloat162*)(outH + ob + col) = hv;
                *(__nv_bfloat162*)(outL + ob + col) = lv;
            }
        }
    }
}

// ---------------- kernel 1b: exact fp32 block-mean projection ----------------
__global__ __launch_bounds__(256) void hmean_gemm_kernel(
    const float* __restrict__ Wq, const float* __restrict__ Wk, const float* __restrict__ Wv,
    const float* __restrict__ bq, const float* __restrict__ bk, const float* __restrict__ bv)
{
    __shared__ float As[32][33];
    __shared__ float Bs[128][33];

    const int mat = blockIdx.z;
    const float* W = (mat == 0) ? Wq : (mat == 1) ? Wk : Wv;
    const float* bias = (mat == 0) ? bq : (mat == 1) ? bk : bv;
    float* out = (mat == 0) ? g_Qh : (mat == 1) ? g_Kh : g_Vh;

    const int tid = threadIdx.x;
    const int r0 = blockIdx.x * 32;
    const int e0 = blockIdx.y * 128;
    const int tn = tid >> 4;
    const int tm2 = tid & 15;

    float acc0[8], acc1[8];
    #pragma unroll
    for (int j = 0; j < 8; j++) { acc0[j] = 0.f; acc1[j] = 0.f; }

    for (int k0 = 0; k0 < Dm; k0 += 32) {
        {
            int r = tid >> 3, kq = tid & 7;
            float4 v = *(const float4*)&g_Xbar[(size_t)(r0 + r)*Dm + k0 + kq*4];
            As[r][kq*4+0] = v.x; As[r][kq*4+1] = v.y; As[r][kq*4+2] = v.z; As[r][kq*4+3] = v.w;
        }
        #pragma unroll
        for (int t = 0; t < 4; t++) {
            int idx = tid + t*256;
            int r = idx >> 3, kq = idx & 7;
            float4 v = *(const float4*)&W[(size_t)(e0 + r)*Dm + k0 + kq*4];
            Bs[r][kq*4+0] = v.x; Bs[r][kq*4+1] = v.y; Bs[r][kq*4+2] = v.z; Bs[r][kq*4+3] = v.w;
        }
        __syncthreads();
        #pragma unroll 8
        for (int k = 0; k < 32; k++) {
            float a0 = As[tm2*2][k], a1 = As[tm2*2+1][k];
            #pragma unroll
            for (int j = 0; j < 8; j++) {
                float b = Bs[tn*8+j][k];
                acc0[j] += a0*b;
                acc1[j] += a1*b;
            }
        }
        __syncthreads();
    }

    #pragma unroll
    for (int i = 0; i < 2; i++) {
        const int r = r0 + tm2*2 + i;
        const int bb2 = r >> 7, n = r & 127;
        const float tcf = g_tcf[r];
        const float* av = i ? acc1 : acc0;
        #pragma unroll
        for (int j = 0; j < 8; j++) {
            int e = e0 + tn*8 + j;
            int hh = e >> 6, hd = e & 63;
            out[(((size_t)(bb2*Hh + hh))*NBR + n)*HD + hd] = av[j] + bias[e]*tcf;
        }
    }
}

// ---------------- kernel 3: low-res logits (16 q-rows per CTA) ----------------
__global__ __launch_bounds__(256) void lowlogit_kernel()
{
    const int mb = blockIdx.y, q0 = blockIdx.x*16;
    const int bb = mb / Hh;
    const int tid = threadIdx.x;
    __shared__ float Kt[64][129];     // [d][m]
    __shared__ float Qhs[16][65];
    __shared__ float tcs[NBR];

    for (int i = tid; i < NBR*HD; i += 256) {
        int m = i >> 6, d = i & 63;
        Kt[d][m] = g_Kh[((size_t)mb*NBR + m)*HD + d];
    }
    for (int i = tid; i < 16*HD; i += 256) {
        int qq = i >> 6, d = i & 63;
        Qhs[qq][d] = g_Qh[((size_t)mb*NBR + q0 + qq)*HD + d];
    }
    if (tid < NBR) tcs[tid] = g_tcb[bb*NBR + tid];
    __syncthreads();

    const int q = tid >> 4, mg = tid & 15;
    float s[8];
    #pragma unroll
    for (int k = 0; k < 8; k++) s[k] = 0.f;
    for (int d = 0; d < HD; d++) {
        float qv = Qhs[q][d];
        const float* kr = &Kt[d][mg];
        #pragma unroll
        for (int k = 0; k < 8; k++) s[k] += qv*kr[16*k];
    }
    #pragma unroll
    for (int k = 0; k < 8; k++) s[k] *= 0.125f;

    float mx = s[0];
    #pragma unroll
    for (int k = 1; k < 8; k++) mx = fmaxf(mx, s[k]);
    #pragma unroll
    for (int off = 8; off >= 1; off >>= 1)
        mx = fmaxf(mx, __shfl_xor_sync(0xffffffffu, mx, off, 16));
    const int n = q0 + q;
    if (mg == 0) g_rowmax[mb*NBR + n] = mx;

    const float tcn = tcs[n];
    float* llr = g_ll + ((size_t)mb*NBR + n)*NBR;
    float* prr = g_prior + ((size_t)mb*NBR + n)*NBR;
    #pragma unroll
    for (int k = 0; k < 8; k++) {
        int m = mg + 16*k;
        float pe = (tcn*tcs[m] < 0.5f) ? 1.0f : 0.0f;
        float ll = s[k] - 1e4f*pe;
        float prior = ll - mx;
        int dif = n - m; if (dif < 0) dif = -dif;
        if (dif <= 1) prior += 5e3f;
        llr[m] = ll;
        prr[m] = prior;
    }
}

// ---------------- kernel 4+5 merged: radix threshold + deterministic select ----------------
#define TS_SMEM (NBR*NBR*4 + 256*4 + 16)
__global__ __launch_bounds__(256) void threshsel_kernel()
{
    extern __shared__ __align__(16) float ts_sm[];
    float* prs = ts_sm;                                  // 16384 floats
    unsigned* hist = (unsigned*)(ts_sm + NBR*NBR);
    unsigned* ctrl = hist + 256;

    const int mb = blockIdx.x;
    const int tid = threadIdx.x;   // 256
    const int lane = tid & 31;
    const float* pr = g_prior + (size_t)mb*NBR*NBR;
    for (int i = tid; i < NBR*NBR; i += 256) prs[i] = pr[i];
    if (tid == 0) { ctrl[0] = 0u; ctrl[1] = NUMBLK; }
    __syncthreads();

    for (int pass = 0; pass < 4; pass++) {
        int shift = 24 - pass*8;
        hist[tid] = 0u;
        __syncthreads();
        unsigned pref = ctrl[0];
        for (int i = tid; i < NBR*NBR; i += 256) {
            unsigned u = f2ord(prs[i]);
            bool ok = (pass == 0) ? true : (((u ^ pref) >> (shift + 8)) == 0u);
            unsigned bin = ok ? ((u >> shift) & 255u) : 0xFFFFFFFFu;
            unsigned mm = __match_any_sync(0xffffffffu, bin);
            if (bin != 0xFFFFFFFFu && (__ffs(mm) - 1) == lane)
                atomicAdd(&hist[bin], __popc(mm));
        }
        __syncthreads();
        if (tid == 0) {
            int k = (int)ctrl[1]; unsigned cum = 0u; int sel = 0;
            for (int bbin = 255; bbin >= 0; bbin--) {
                unsigned h = hist[bbin];
                if (cum + h >= (unsigned)k) { sel = bbin; break; }
                cum += h;
            }
            ctrl[1] = (unsigned)(k - (int)cum);
            ctrl[0] = pref | ((unsigned)sel << shift);
        }
        __syncthreads();
    }
    float t;
    {
        unsigned u = ctrl[0];
        unsigned raw = (u & 0x80000000u) ? (u & 0x7FFFFFFFu) : ~u;
        t = __uint_as_float(raw);
    }
    if (tid == 0) g_thresh[mb] = t;

    if (tid < 128) {
        const int n = tid;
        const float* prow = prs + n*NBR;
        int* lst = g_list + ((size_t)mb*NBR + n)*NBR;
        int c = 0;
        for (int m = 0; m < NBR; m++)
            if (prow[m] >= t) lst[c++] = m;
        g_cnt[mb*NBR + n] = c;
    }
}

// ---------------- kernel 6: high-res sparse attention via mma.sync (split bf16) ----------------
#define OKH 0
#define OKL 9216
#define OVH 18432
#define OVL 27648
#define OKM 36864
#define OPH 37120
#define OPL 39680
#define OMAXP 42240
#define OSUMP 42752
#define ORM 43264
#define OSC 43392
#define ONRM 43520
#define HR_SMEM 43648

__global__ __launch_bounds__(128) void highres_kernel(const float* __restrict__ mask)
{
    __shared__ __align__(16) char sm[HR_SMEM];
    const uint32_t sb = smem_u32(sm);
    const int mbn = blockIdx.x;
    const int mb = mbn >> 7, q = mbn & 127;
    const int bb = mb / Hh;
    const int tid = threadIdx.x;
    const int lane = tid & 31, w = tid >> 5;

    const int nb = g_cnt[mbn];
    const int* lst = g_list + (size_t)mbn*NBR;
    const size_t qrow = (size_t)mb*Ss + q*BLKSZ;

    float* RM  = (float*)(sm + ORM);
    float* SC  = (float*)(sm + OSC);
    float* NRM = (float*)(sm + ONRM);
    float* MAXP = (float*)(sm + OMAXP);
    float* SUMP = (float*)(sm + OSUMP);

    for (int i = tid; i < 256; i += 128) {
        int r = i >> 3, ch = i & 7;
        *(uint4*)(sm + OKH + r*144 + ch*16)        = ((const uint4*)(g_Qbh + (qrow + r)*HD))[ch];
        *(uint4*)(sm + OKH + 4608 + r*144 + ch*16) = ((const uint4*)(g_Qbl + (qrow + r)*HD))[ch];
    }
    if (tid < 32) { RM[tid] = -1e30f; NRM[tid] = 0.f; }
    __syncthreads();

    uint32_t aQh[2][4][4], aQl[2][4][4];
    #pragma unroll
    for (int mt = 0; mt < 2; mt++) {
        int row = mt*16 + (lane & 7) + ((lane >> 3) & 1)*8;
        #pragma unroll
        for (int ks = 0; ks < 4; ks++) {
            uint32_t ad = sb + OKH + row*144 + (ks*2 + (lane >> 4))*16;
            ldsm4(aQh[mt][ks][0], aQh[mt][ks][1], aQh[mt][ks][2], aQh[mt][ks][3], ad);
            ldsm4(aQl[mt][ks][0], aQl[mt][ks][1], aQl[mt][ks][2], aQl[mt][ks][3], ad + 4608);
        }
    }
    __syncthreads();

    float o[2][2][4];
    #pragma unroll
    for (int mt = 0; mt < 2; mt++)
        #pragma unroll
        for (int nt = 0; nt < 2; nt++)
            #pragma unroll
            for (int j = 0; j < 4; j++) o[mt][nt][j] = 0.f;

    #define HR_LOAD(st, kb) do { \
        size_t _rb = (size_t)mb*Ss + (size_t)(kb)*BLKSZ; \
        for (int _i = tid; _i < 256; _i += 128) { \
            int _r = _i >> 3, _ch = _i & 7; \
            uint32_t _so = (st)*4608 + _r*144 + _ch*16; \
            CP_ASYNC16(sb + OKH + _so, ((const uint4*)(g_Kbh + (_rb + _r)*HD)) + _ch); \
            CP_ASYNC16(sb + OKL + _so, ((const uint4*)(g_Kbl + (_rb + _r)*HD)) + _ch); \
            CP_ASYNC16(sb + OVH + _so, ((const uint4*)(g_Vbh + (_rb + _r)*HD)) + _ch); \
            CP_ASYNC16(sb + OVL + _so, ((const uint4*)(g_Vbl + (_rb + _r)*HD)) + _ch); \
        } \
        if (tid < 8) CP_ASYNC16(sb + OKM + (st)*128 + tid*16, &mask[(size_t)bb*Ss + (size_t)(kb)*BLKSZ + tid*4]); \
        CP_COMMIT(); \
    } while (0)

    if (nb > 0) HR_LOAD(0, lst[0]);

    for (int it = 0; it < nb; it++) {
        const int cur = it & 1;
        if (it + 1 < nb) {
            HR_LOAD((it+1) & 1, lst[it+1]);
            asm volatile("cp.async.wait_group 1;" ::: "memory");
        } else {
            asm volatile("cp.async.wait_group 0;" ::: "memory");
        }
        __syncthreads();

        float sacc[2][4];
        #pragma unroll
        for (int mt = 0; mt < 2; mt++)
            #pragma unroll
            for (int j = 0; j < 4; j++) sacc[mt][j] = 0.f;

        const uint32_t khb = sb + OKH + cur*4608;
        uint32_t kbh[4][2], kbl[4][2];
        #pragma unroll
        for (int ks = 0; ks < 4; ks++) {
            uint32_t baddr = khb + (8*w + (lane & 7))*144 + (ks*2 + ((lane >> 3) & 1))*16;
            ldsm2(kbh[ks][0], kbh[ks][1], baddr);
            ldsm2(kbl[ks][0], kbl[ks][1], baddr + (OKL - OKH));
        }
        #pragma unroll
        for (int ks = 0; ks < 4; ks++) {
            #pragma unroll
            for (int mt = 0; mt < 2; mt++) {
                mma16816(sacc[mt], aQh[mt][ks][0], aQh[mt][ks][1], aQh[mt][ks][2], aQh[mt][ks][3], kbh[ks][0], kbh[ks][1]);
                mma16816(sacc[mt], aQh[mt][ks][0], aQh[mt][ks][1], aQh[mt][ks][2], aQh[mt][ks][3], kbl[ks][0], kbl[ks][1]);
                mma16816(sacc[mt], aQl[mt][ks][0], aQl[mt][ks][1], aQl[mt][ks][2], aQl[mt][ks][3], kbh[ks][0], kbh[ks][1]);
            }
        }
        #pragma unroll
        for (int mt = 0; mt < 2; mt++)
            #pragma unroll
            for (int j = 0; j < 4; j++) sacc[mt][j] *= 0.125f;

        #pragma unroll
        for (int mt = 0; mt < 2; mt++) {
            float m1 = fmaxf(sacc[mt][0], sacc[mt][1]);
            float m2 = fmaxf(sacc[mt][2], sacc[mt][3]);
            m1 = fmaxf(m1, __shfl_xor_sync(0xffffffffu, m1, 1, 4));
            m1 = fmaxf(m1, __shfl_xor_sync(0xffffffffu, m1, 2, 4));
            m2 = fmaxf(m2, __shfl_xor_sync(0xffffffffu, m2, 1, 4));
            m2 = fmaxf(m2, __shfl_xor_sync(0xffffffffu, m2, 2, 4));
            if ((lane & 3) == 0) {
                int r1 = mt*16 + (lane >> 2);
                MAXP[r1*4 + w] = m1;
                MAXP[(r1+8)*4 + w] = m2;
            }
        }
        __syncthreads();
        if (tid < 32) {
            float tm = fmaxf(fmaxf(MAXP[tid*4], MAXP[tid*4+1]), fmaxf(MAXP[tid*4+2], MAXP[tid*4+3]));
            float old = RM[tid];
            float nm = fmaxf(old, tm);
            SC[tid] = __expf(old - nm);
            RM[tid] = nm;
        }
        __syncthreads();

        const float kmv0 = ((const float*)(sm + OKM + cur*128))[8*w + (lane & 3)*2];
        const float kmv1 = ((const float*)(sm + OKM + cur*128))[8*w + (lane & 3)*2 + 1];
        const float pen0 = 1e4f*(1.f - kmv0), pen1 = 1e4f*(1.f - kmv1);
        const int colb = (8*w + (lane & 3)*2)*2;

        #pragma unroll
        for (int mt = 0; mt < 2; mt++) {
            int r1 = mt*16 + (lane >> 2), r2 = r1 + 8;
            float sc1 = SC[r1], sc2 = SC[r2];
            float rm1 = RM[r1], rm2 = RM[r2];
            #pragma unroll
            for (int nt = 0; nt < 2; nt++) {
                o[mt][nt][0] *= sc1; o[mt][nt][1] *= sc1;
                o[mt][nt][2] *= sc2; o[mt][nt][3] *= sc2;
            }
            // exp split across pipes: 5 via MUFU, 3 via FFMA polynomial (per thread per iter)
            float p00, p01, p10, p11;
            if (mt == 0) {
                p00 = __expf(sacc[mt][0] - rm1 - pen0);
                p01 = __expf(sacc[mt][1] - rm1 - pen1);
                p10 = __expf(sacc[mt][2] - rm2 - pen0);
                p11 = fexp_poly(sacc[mt][3] - rm2 - pen1);
            } else {
                p00 = __expf(sacc[mt][0] - rm1 - pen0);
                p01 = __expf(sacc[mt][1] - rm1 - pen1);
                p10 = fexp_poly(sacc[mt][2] - rm2 - pen0);
                p11 = fexp_poly(sacc[mt][3] - rm2 - pen1);
            }

            __nv_bfloat162 ph0 = __floats2bfloat162_rn(p00, p01);
            __nv_bfloat162 pl0 = __floats2bfloat162_rn(
                p00 - __bfloat162float(__low2bfloat16(ph0)),
                p01 - __bfloat162float(__high2bfloat16(ph0)));
            __nv_bfloat162 ph1 = __floats2bfloat162_rn(p10, p11);
            __nv_bfloat162 pl1 = __floats2bfloat162_rn(
                p10 - __bfloat162float(__low2bfloat16(ph1)),
                p11 - __bfloat162float(__high2bfloat16(ph1)));
            *(__nv_bfloat162*)(sm + OPH + r1*80 + colb) = ph0;
            *(__nv_bfloat162*)(sm + OPL + r1*80 + colb) = pl0;
            *(__nv_bfloat162*)(sm + OPH + r2*80 + colb) = ph1;
            *(__nv_bfloat162*)(sm + OPL + r2*80 + colb) = pl1;

            float s1 = p00 + p01, s2 = p10 + p11;
            s1 += __shfl_xor_sync(0xffffffffu, s1, 1, 4);
            s1 += __shfl_xor_sync(0xffffffffu, s1, 2, 4);
            s2 += __shfl_xor_sync(0xffffffffu, s2, 1, 4);
            s2 += __shfl_xor_sync(0xffffffffu, s2, 2, 4);
            if ((lane & 3) == 0) {
                SUMP[r1*4 + w] = s1;
                SUMP[r2*4 + w] = s2;
            }
        }
        __syncthreads();
        if (tid < 32) {
            float s = SUMP[tid*4] + SUMP[tid*4+1] + SUMP[tid*4+2] + SUMP[tid*4+3];
            NRM[tid] = NRM[tid]*SC[tid] + s;
        }

        const uint32_t vhb = sb + OVH + cur*4608;
        #pragma unroll
        for (int ks = 0; ks < 2; ks++) {
            uint32_t aPh[2][4], aPl[2][4];
            #pragma unroll
            for (int mt = 0; mt < 2; mt++) {
                int row = mt*16 + (lane & 7) + ((lane >> 3) & 1)*8;
                uint32_t pad = sb + OPH + row*80 + (ks*2 + (lane >> 4))*16;
                ldsm4(aPh[mt][0], aPh[mt][1], aPh[mt][2], aPh[mt][3], pad);
                ldsm4(aPl[mt][0], aPl[mt][1], aPl[mt][2], aPl[mt][3], pad + (OPL - OPH));
            }
            int vrow = ks*16 + (lane & 7) + ((lane >> 3) & 1)*8;
            uint32_t vad = vhb + vrow*144 + (2*w + (lane >> 4))*16;
            uint32_t bh0, bh1, bh2, bh3, bl0, bl1, bl2, bl3;
            ldsm4t(bh0, bh1, bh2, bh3, vad);
            ldsm4t(bl0, bl1, bl2, bl3, vad + (OVL - OVH));
            #pragma unroll
            for (int mt = 0; mt < 2; mt++) {
                mma16816(o[mt][0], aPh[mt][0], aPh[mt][1], aPh[mt][2], aPh[mt][3], bh0, bh1);
                mma16816(o[mt][1], aPh[mt][0], aPh[mt][1], aPh[mt][2], aPh[mt][3], bh2, bh3);
                mma16816(o[mt][0], aPh[mt][0], aPh[mt][1], aPh[mt][2], aPh[mt][3], bl0, bl1);
                mma16816(o[mt][1], aPh[mt][0], aPh[mt][1], aPh[mt][2], aPh[mt][3], bl2, bl3);
                mma16816(o[mt][0], aPl[mt][0], aPl[mt][1], aPl[mt][2], aPl[mt][3], bh0, bh1);
                mma16816(o[mt][1], aPl[mt][0], aPl[mt][1], aPl[mt][2], aPl[mt][3], bh2, bh3);
            }
        }
        __syncthreads();
    }

    #pragma unroll
    for (int mt = 0; mt < 2; mt++) {
        int r1 = mt*16 + (lane >> 2), r2 = r1 + 8;
        #pragma unroll
        for (int nt = 0; nt < 2; nt++) {
            int col = 16*w + nt*8 + (lane & 3)*2;
            float2 w1 = make_float2(o[mt][nt][0], o[mt][nt][1]);
            float2 w2 = make_float2(o[mt][nt][2], o[mt][nt][3]);
            *(float2*)&g_high_out[(qrow + r1)*HD + col] = w1;
            *(float2*)&g_high_out[(qrow + r2)*HD + col] = w2;
        }
    }
    if (tid < 32) {
        g_maxrows[qrow + tid] = fmaxf(RM[tid], -1e6f);
        g_high_norm[qrow + tid] = NRM[tid];
    }
}

// ---------------- kernel 7: low-res attention (16 n-rows per CTA) ----------------
__global__ __launch_bounds__(256) void lowres_kernel()
{
    const int mb = blockIdx.y, n0 = blockIdx.x*16;
    const int bb = mb / Hh;
    const int tid = threadIdx.x;
    __shared__ float4 V4[NBR][16];
    __shared__ float a_sh[16][129];
    __shared__ float tcs[NBR];

    for (int i = tid; i < NBR*16; i += 256) {
        int m = i >> 4, dg = i & 15;
        V4[m][dg] = *(const float4*)&g_Vh[((size_t)mb*NBR + m)*HD + dg*4];
    }
    if (tid < NBR) tcs[tid] = g_tcb[bb*NBR + tid];
    __syncthreads();

    const int nn = tid >> 4, mg = tid & 15;
    const int n = n0 + nn;
    const float rmv = g_rowmax[mb*NBR + n];
    const float t = g_thresh[mb];
    const float* llr = g_ll + ((size_t)mb*NBR + n)*NBR;
    const float* prr = g_prior + ((size_t)mb*NBR + n)*NBR;
    float psum = 0.f;
    #pragma unroll
    for (int k = 0; k < 8; k++) {
        int m = mg + 16*k;
        float sel = (prr[m] >= t) ? 1e4f : 0.f;
        float a = __expf(llr[m] - rmv - sel) * tcs[m];
        a_sh[nn][m] = a;
        psum += a;
    }
    #pragma unroll
    for (int off = 8; off >= 1; off >>= 1)
        psum += __shfl_xor_sync(0xffffffffu, psum, off, 16);
    if (mg == 0) g_low_norm[mb*NBR + n] = psum;
    __syncthreads();

    {
        const int dg = tid & 15;
        const float* ar = a_sh[tid >> 4];
        float4 acc = make_float4(0.f, 0.f, 0.f, 0.f);
        #pragma unroll 8
        for (int m = 0; m < NBR; m++) {
            float av = ar[m];
            float4 v = V4[m][dg];
            acc.x += av*v.x; acc.y += av*v.y; acc.z += av*v.z; acc.w += av*v.w;
        }
        *(float4*)&g_low_out[((size_t)mb*NBR + n0 + (tid >> 4))*HD + dg*4] = acc;
    }
}

// ---------------- kernel 8: combine + final layout ----------------
__global__ void combine_kernel(const float* __restrict__ mask, float* __restrict__ out)
{
    int mb = blockIdx.y;
    int tid = threadIdx.x;                 // 256 = 4 tokens x 64 dims
    int s = blockIdx.x*4 + (tid >> 6);
    int hd = tid & 63;
    int bb = mb / Hh, h = mb % Hh;
    int blk = s >> 5;
    float mval = mask[(size_t)bb*Ss + s];
    float lcl = (g_rowmax[mb*NBR + blk] - g_maxrows[(size_t)mb*Ss + s]) * mval;
    float lcorr = __expf(fminf(lcl, 0.f));
    float hcorr = __expf(-fmaxf(lcl, 0.f));
    float hn = g_high_norm[(size_t)mb*Ss + s];
    float ln = g_low_norm[mb*NBR + blk];
    float inv = 1.0f / (hn*hcorr + ln*lcorr + 1e-6f);
    float val = (g_high_out[((size_t)mb*Ss + s)*HD + hd]*hcorr
               + g_low_out[((size_t)mb*NBR + blk)*HD + hd]*lcorr) * inv;
    out[((size_t)bb*Ss + s)*Dm + h*HD + hd] = val;
}

// ---------------- launch ----------------
extern "C" void kernel_launch(void* const* d_in, const int* in_sizes, int n_in,
                              void* d_out, int out_size)
{
    const float* X    = (const float*)d_in[0];
    const float* mask = (const float*)d_in[1];
    const float* Wq   = (const float*)d_in[2];
    const float* bq   = (const float*)d_in[3];
    const float* Wk   = (const float*)d_in[4];
    const float* bk   = (const float*)d_in[5];
    const float* Wv   = (const float*)d_in[6];
    const float* bv   = (const float*)d_in[7];
    float* out = (float*)d_out;

    cudaFuncSetAttribute(qkv_mma_kernel, cudaFuncAttributeMaxDynamicSharedMemorySize, GEMM_SMEM);
    cudaFuncSetAttribute(threshsel_kernel, cudaFuncAttributeMaxDynamicSharedMemorySize, TS_SMEM);

    convX_kernel<<<MROWS*Dm/1024, 256>>>(X);                       // 1
    convW_kernel<<<dim3(Dm*Dm/1024, 3), 256>>>(Wq, Wk, Wv);        // 2
    xbar_kernel<<<Bb*NBR, Dm>>>(X, mask);                          // 3
    qkv_mma_kernel<<<dim3(MROWS/128, 9), 512, GEMM_SMEM>>>(mask, bq, bk, bv);  // 4 (profiled slot)
    hmean_gemm_kernel<<<dim3(8, 6, 3), 256>>>(Wq, Wk, Wv, bq, bk, bv);         // 5
    lowlogit_kernel<<<dim3(8, MBT), 256>>>();                      // 6
    threshsel_kernel<<<MBT, 256, TS_SMEM>>>();                     // 7
    highres_kernel<<<MBT*NBR, 128>>>(mask);                        // 8
    lowres_kernel<<<dim3(8, MBT), 256>>>();                        // 9
    combine_kernel<<<dim3(Ss/4, MBT), 256>>>(mask, out);           // 10
}

// round 11
// speedup vs baseline: 2.4050x; 1.0399x over previous
#include <cuda_runtime.h>
#include <cuda_bf16.h>
#include <cstdint>

// ---------------- problem constants ----------------
#define Bb 2
#define Ss 4096
#define Dm 768
#define Hh 12
#define HD 64
#define BLKSZ 32
#define NBR 128
#define NUMBLK 1024
#define MBT (Bb*Hh)        // 24
#define MROWS (Bb*Ss)      // 8192

typedef unsigned long long ull;

__device__ __forceinline__ uint32_t smem_u32(const void* p) {
    uint32_t a;
    asm("{ .reg .u64 t; cvta.to.shared.u64 t, %1; cvt.u32.u64 %0, t; }" : "=r"(a) : "l"(p));
    return a;
}
#define CP_ASYNC16(dst, src) \
    asm volatile("cp.async.cg.shared.global [%0], [%1], 16;" :: "r"(dst), "l"(src))
#define CP_COMMIT() asm volatile("cp.async.commit_group;" ::: "memory")

// ---------------- f32x2 helpers ----------------
__device__ __forceinline__ void ffma2(ull &d, ull a, ull b) {
    asm("fma.rn.f32x2 %0, %1, %2, %0;" : "+l"(d) : "l"(a), "l"(b));
}
__device__ __forceinline__ ull pack2(float x, float y) {
    ull r; asm("mov.b64 %0, {%1, %2};" : "=l"(r) : "f"(x), "f"(y)); return r;
}
__device__ __forceinline__ void unpack2(ull v, float &x, float &y) {
    asm("mov.b64 {%0, %1}, %2;" : "=f"(x), "=f"(y) : "l"(v));
}

// ---------------- mma.sync helpers ----------------
__device__ __forceinline__ void ldsm4(uint32_t &r0, uint32_t &r1, uint32_t &r2, uint32_t &r3, uint32_t addr) {
    asm volatile("ldmatrix.sync.aligned.m8n8.x4.shared.b16 {%0,%1,%2,%3}, [%4];"
        : "=r"(r0), "=r"(r1), "=r"(r2), "=r"(r3) : "r"(addr));
}
__device__ __forceinline__ void ldsm2(uint32_t &r0, uint32_t &r1, uint32_t addr) {
    asm volatile("ldmatrix.sync.aligned.m8n8.x2.shared.b16 {%0,%1}, [%2];"
        : "=r"(r0), "=r"(r1) : "r"(addr));
}
__device__ __forceinline__ void ldsm4t(uint32_t &r0, uint32_t &r1, uint32_t &r2, uint32_t &r3, uint32_t addr) {
    asm volatile("ldmatrix.sync.aligned.m8n8.x4.trans.shared.b16 {%0,%1,%2,%3}, [%4];"
        : "=r"(r0), "=r"(r1), "=r"(r2), "=r"(r3) : "r"(addr));
}
__device__ __forceinline__ void mma16816(float* c,
    uint32_t a0, uint32_t a1, uint32_t a2, uint32_t a3, uint32_t b0, uint32_t b1) {
    asm volatile("mma.sync.aligned.m16n8k16.row.col.f32.bf16.bf16.f32 "
        "{%0,%1,%2,%3}, {%4,%5,%6,%7}, {%8,%9}, {%0,%1,%2,%3};"
        : "+f"(c[0]), "+f"(c[1]), "+f"(c[2]), "+f"(c[3])
        : "r"(a0), "r"(a1), "r"(a2), "r"(a3), "r"(b0), "r"(b1));
}

// fast exp on the fma/alu pipes (keeps MUFU free)
__device__ __forceinline__ float fexp_poly(float x) {
    float z = x * 1.4426950408889634f;
    z = fmaxf(z, -120.f);
    float m = z + 12582912.0f;
    int n = __float_as_int(m) - 0x4B400000;
    float f = z - (m - 12582912.0f);
    float p = 1.3333558e-3f;
    p = fmaf(p, f, 9.6181291e-3f);
    p = fmaf(p, f, 5.5504109e-2f);
    p = fmaf(p, f, 2.4022651e-1f);
    p = fmaf(p, f, 6.9314718e-1f);
    p = fmaf(p, f, 1.0f);
    float r = __int_as_float(__float_as_int(p) + (n << 23));
    return (x < -80.f) ? 0.f : r;
}

// ---------------- device scratch ----------------
__device__ __nv_bfloat16 g_Qbh[MBT*Ss*HD];
__device__ __nv_bfloat16 g_Qbl[MBT*Ss*HD];
__device__ __nv_bfloat16 g_Kbh[MBT*Ss*HD];
__device__ __nv_bfloat16 g_Kbl[MBT*Ss*HD];
__device__ __nv_bfloat16 g_Vbh[MBT*Ss*HD];
__device__ __nv_bfloat16 g_Vbl[MBT*Ss*HD];
__device__ __nv_bfloat16 g_Xh[MROWS*Dm];
__device__ __nv_bfloat16 g_Xl[MROWS*Dm];
__device__ __nv_bfloat16 g_Wh[3*Dm*Dm];
__device__ __nv_bfloat16 g_Wl[3*Dm*Dm];
__device__ float g_Xbar[Bb*NBR*Dm];
__device__ float g_tcb[Bb*NBR];
__device__ float g_tcf[Bb*NBR];
__device__ float g_Qh[MBT*NBR*HD];
__device__ float g_Kh[MBT*NBR*HD];
__device__ float g_Vh[MBT*NBR*HD];
__device__ float g_ll[MBT*NBR*NBR];
__device__ float g_prior[MBT*NBR*NBR];
__device__ float g_rowmax[MBT*NBR];
__device__ float g_thresh[MBT];
__device__ int   g_cnt[MBT*NBR];
__device__ int   g_list[MBT*NBR*NBR];
__device__ float g_low_out[MBT*NBR*HD];
__device__ float g_low_norm[MBT*NBR];

__device__ __forceinline__ unsigned f2ord(float f) {
    unsigned u = __float_as_uint(f);
    return (u & 0x80000000u) ? ~u : (u | 0x80000000u);
}

// ---------------- kernel 0a: split X into bf16 hi/lo ----------------
__global__ void convX_kernel(const float* __restrict__ X)
{
    int i = (blockIdx.x*256 + threadIdx.x)*4;
    float4 v = *(const float4*)(X + i);
    float vf[4] = {v.x, v.y, v.z, v.w};
    __nv_bfloat16 h[4], l[4];
    #pragma unroll
    for (int j = 0; j < 4; j++) {
        h[j] = __float2bfloat16(vf[j]);
        l[j] = __float2bfloat16(vf[j] - __bfloat162float(h[j]));
    }
    *(ull*)(g_Xh + i) = *(ull*)h;
    *(ull*)(g_Xl + i) = *(ull*)l;
}

// ---------------- kernel 0b: split W into bf16 hi/lo ----------------
__global__ void convW_kernel(const float* __restrict__ Wq,
                             const float* __restrict__ Wk,
                             const float* __restrict__ Wv)
{
    int mat = blockIdx.y;
    const float* W = (mat == 0) ? Wq : (mat == 1) ? Wk : Wv;
    int i = (blockIdx.x*256 + threadIdx.x)*4;
    float4 v = *(const float4*)(W + i);
    float vf[4] = {v.x, v.y, v.z, v.w};
    __nv_bfloat16 h[4], l[4];
    #pragma unroll
    for (int j = 0; j < 4; j++) {
        h[j] = __float2bfloat16(vf[j]);
        l[j] = __float2bfloat16(vf[j] - __bfloat162float(h[j]));
    }
    size_t o = (size_t)mat*Dm*Dm + i;
    *(ull*)(g_Wh + o) = *(ull*)h;
    *(ull*)(g_Wl + o) = *(ull*)l;
}

// ---------------- kernel 0c: masked block-mean of X ----------------
__global__ void xbar_kernel(const float* __restrict__ X, const float* __restrict__ mask)
{
    int bn = blockIdx.x;             // Bb*NBR
    int bb = bn >> 7, n = bn & 127;
    int d = threadIdx.x;             // 768
    const float* mrow = mask + (size_t)bb*Ss + n*BLKSZ;
    float tc = 0.f;
    #pragma unroll
    for (int t = 0; t < BLKSZ; t++) tc += mrow[t];
    float denom = tc + 1e-6f;
    const float* xp = X + ((size_t)bb*Ss + n*BLKSZ)*Dm + d;
    float s = 0.f;
    #pragma unroll 4
    for (int t = 0; t < BLKSZ; t++) s += mrow[t]*xp[(size_t)t*Dm];
    g_Xbar[(size_t)bn*Dm + d] = s/denom;
    if (d == 0) { g_tcb[bn] = tc; g_tcf[bn] = tc/denom; }
}

// ---------------- kernel 1: QKV projection via mma.sync bf16 (3-term split) ----------------
#define BUFA_L 10240
#define BUFB_H 20480
#define BUFB_L 40960
#define BUF_STRIDE 61440
#define GEMM_SMEM (3*BUF_STRIDE)

__global__ __launch_bounds__(512, 1) void qkv_mma_kernel(
    const float* __restrict__ mask,
    const float* __restrict__ bq, const float* __restrict__ bk, const float* __restrict__ bv)
{
    extern __shared__ __align__(16) char smem[];
    const uint32_t sb = smem_u32(smem);
    const int tid = threadIdx.x, lane = tid & 31, wid = tid >> 5;
    const int m0 = blockIdx.x * 128;
    const int tile = blockIdx.y;          // 0..8
    const int mat = tile / 3;
    const int n0 = (tile % 3) * 256;
    const int wm = wid & 3;
    const int wn = wid >> 2;

    const uint4* XH = (const uint4*)g_Xh;
    const uint4* XL = (const uint4*)g_Xl;
    const uint4* WH = (const uint4*)(g_Wh + (size_t)mat*Dm*Dm);
    const uint4* WL = (const uint4*)(g_Wl + (size_t)mat*Dm*Dm);
    const float* bias = (mat == 0) ? bq : (mat == 1) ? bk : bv;
    __nv_bfloat16* outH = (mat == 0) ? g_Qbh : (mat == 1) ? g_Kbh : g_Vbh;
    __nv_bfloat16* outL = (mat == 0) ? g_Qbl : (mat == 1) ? g_Kbl : g_Vbl;

    float acc[2][8][4];
    #pragma unroll
    for (int a = 0; a < 2; a++)
        #pragma unroll
        for (int b = 0; b < 8; b++)
            #pragma unroll
            for (int c = 0; c < 4; c++) acc[a][b][c] = 0.f;

    const int arow = tid >> 2, ac = tid & 3;

    #define ISSUE_STAGE(s) do { \
        const int _buf = (s) % 3; \
        const uint32_t _bb = sb + _buf*BUF_STRIDE; \
        const int _kc4 = (s)*4; \
        { \
            uint32_t _so = _bb + arow*80 + ac*16; \
            CP_ASYNC16(_so, &XH[(size_t)(m0 + arow)*96 + _kc4 + ac]); \
            CP_ASYNC16(_so + BUFA_L, &XL[(size_t)(m0 + arow)*96 + _kc4 + ac]); \
        } \
        _Pragma("unroll") \
        for (int _i = 0; _i < 2; _i++) { \
            int _row = arow + _i*128; \
            uint32_t _so = _bb + BUFB_H + _row*80 + ac*16; \
            CP_ASYNC16(_so, &WH[(size_t)(n0 + _row)*96 + _kc4 + ac]); \
            CP_ASYNC16(_so + (BUFB_L - BUFB_H), &WL[(size_t)(n0 + _row)*96 + _kc4 + ac]); \
        } \
        CP_COMMIT(); \
    } while (0)

    ISSUE_STAGE(0);
    ISSUE_STAGE(1);

    const int blrow = (lane & 7);
    const int bhalf = ((lane >> 3) & 1)*16;
    const int bhi = (lane >> 4)*8;

    for (int s = 0; s < 24; s++) {
        if (s < 23) { asm volatile("cp.async.wait_group 1;" ::: "memory"); }
        else        { asm volatile("cp.async.wait_group 0;" ::: "memory"); }
        __syncthreads();
        if (s + 2 < 24) ISSUE_STAGE(s + 2);
        const uint32_t base = sb + (s % 3)*BUF_STRIDE;

        #pragma unroll
        for (int kk = 0; kk < 2; kk++) {
            const uint32_t koff = kk*32;
            uint32_t ah[2][4], al[2][4];
            #pragma unroll
            for (int mt = 0; mt < 2; mt++) {
                int row = wm*32 + mt*16 + (lane & 7) + ((lane >> 3) & 1)*8;
                uint32_t ad = base + row*80 + koff + (lane >> 4)*16;
                ldsm4(ah[mt][0], ah[mt][1], ah[mt][2], ah[mt][3], ad);
                ldsm4(al[mt][0], al[mt][1], al[mt][2], al[mt][3], ad + BUFA_L);
            }
            uint32_t bh[2][4], bl[4];
            {
                int n = wn*64 + blrow + bhi;
                uint32_t bd = base + BUFB_H + n*80 + koff + bhalf;
                ldsm4(bh[0][0], bh[0][1], bh[0][2], bh[0][3], bd);
            }
            #pragma unroll
            for (int np = 0; np < 4; np++) {
                const int cb = np & 1;
                {
                    int n = wn*64 + np*16 + blrow + bhi;
                    uint32_t bd = base + BUFB_L + n*80 + koff + bhalf;
                    ldsm4(bl[0], bl[1], bl[2], bl[3], bd);
                }
                if (np < 3) {
                    int n = wn*64 + (np+1)*16 + blrow + bhi;
                    uint32_t bd = base + BUFB_H + n*80 + koff + bhalf;
                    ldsm4(bh[cb^1][0], bh[cb^1][1], bh[cb^1][2], bh[cb^1][3], bd);
                }
                #pragma unroll
                for (int mt = 0; mt < 2; mt++) {
                    mma16816(acc[mt][np*2],   ah[mt][0], ah[mt][1], ah[mt][2], ah[mt][3], bh[cb][0], bh[cb][1]);
                    mma16816(acc[mt][np*2+1], ah[mt][0], ah[mt][1], ah[mt][2], ah[mt][3], bh[cb][2], bh[cb][3]);
                    mma16816(acc[mt][np*2],   al[mt][0], al[mt][1], al[mt][2], al[mt][3], bh[cb][0], bh[cb][1]);
                    mma16816(acc[mt][np*2+1], al[mt][0], al[mt][1], al[mt][2], al[mt][3], bh[cb][2], bh[cb][3]);
                    mma16816(acc[mt][np*2],   ah[mt][0], ah[mt][1], ah[mt][2], ah[mt][3], bl[0], bl[1]);
                    mma16816(acc[mt][np*2+1], ah[mt][0], ah[mt][1], ah[mt][2], ah[mt][3], bl[2], bl[3]);
                }
            }
        }
    }

    const int h = (n0 + wn*64) >> 6;
    const float* bp = bias + n0 + wn*64;
    float2 bias2[8];
    #pragma unroll
    for (int nt = 0; nt < 8; nt++) bias2[nt] = *(const float2*)(bp + nt*8 + (lane & 3)*2);

    #pragma unroll
    for (int mt = 0; mt < 2; mt++) {
        #pragma unroll
        for (int half = 0; half < 2; half++) {
            int m = m0 + wm*32 + mt*16 + (lane >> 2) + half*8;
            int bbm = m >> 12, sx = m & 4095;
            float mv = mask[(size_t)bbm*Ss + sx];
            size_t ob = ((size_t)(bbm*Hh + h)*Ss + sx)*HD;
            #pragma unroll
            for (int nt = 0; nt < 8; nt++) {
                int col = nt*8 + (lane & 3)*2;
                float wx = (acc[mt][nt][half*2+0] + bias2[nt].x)*mv;
                float wy = (acc[mt][nt][half*2+1] + bias2[nt].y)*mv;
                __nv_bfloat162 hv = __floats2bfloat162_rn(wx, wy);
                float hx = __bfloat162float(__low2bfloat16(hv));
                float hy = __bfloat162float(__high2bfloat16(hv));
                __nv_bfloat162 lv = __floats2bfloat162_rn(wx - hx, wy - hy);
                *(__nv_bfloat162*)(outH + ob + col) = hv;
                *(__nv_bfloat162*)(outL + ob + col) = lv;
            }
        }
    }
}

// ---------------- kernel 1b: exact fp32 block-mean projection (f32x2 inner loop) ----------------
__global__ __launch_bounds__(256) void hmean_gemm_kernel(
    const float* __restrict__ Wq, const float* __restrict__ Wk, const float* __restrict__ Wv,
    const float* __restrict__ bq, const float* __restrict__ bk, const float* __restrict__ bv)
{
    __shared__ float As[32][33];
    __shared__ float Bs[128][33];

    const int mat = blockIdx.z;
    const float* W = (mat == 0) ? Wq : (mat == 1) ? Wk : Wv;
    const float* bias = (mat == 0) ? bq : (mat == 1) ? bk : bv;
    float* out = (mat == 0) ? g_Qh : (mat == 1) ? g_Kh : g_Vh;

    const int tid = threadIdx.x;
    const int r0 = blockIdx.x * 32;
    const int e0 = blockIdx.y * 128;
    const int tn = tid >> 4;
    const int tm2 = tid & 15;

    ull acc2[8];
    #pragma unroll
    for (int j = 0; j < 8; j++) acc2[j] = 0ull;

    for (int k0 = 0; k0 < Dm; k0 += 32) {
        {
            int r = tid >> 3, kq = tid & 7;
            float4 v = *(const float4*)&g_Xbar[(size_t)(r0 + r)*Dm + k0 + kq*4];
            As[r][kq*4+0] = v.x; As[r][kq*4+1] = v.y; As[r][kq*4+2] = v.z; As[r][kq*4+3] = v.w;
        }
        #pragma unroll
        for (int t = 0; t < 4; t++) {
            int idx = tid + t*256;
            int r = idx >> 3, kq = idx & 7;
            float4 v = *(const float4*)&W[(size_t)(e0 + r)*Dm + k0 + kq*4];
            Bs[r][kq*4+0] = v.x; Bs[r][kq*4+1] = v.y; Bs[r][kq*4+2] = v.z; Bs[r][kq*4+3] = v.w;
        }
        __syncthreads();
        #pragma unroll 8
        for (int k = 0; k < 32; k++) {
            ull a2 = pack2(As[tm2*2][k], As[tm2*2+1][k]);
            #pragma unroll
            for (int j = 0; j < 8; j++) {
                float b = Bs[tn*8+j][k];
                ffma2(acc2[j], a2, pack2(b, b));
            }
        }
        __syncthreads();
    }

    #pragma unroll
    for (int j = 0; j < 8; j++) {
        float v0, v1;
        unpack2(acc2[j], v0, v1);
        int e = e0 + tn*8 + j;
        int hh = e >> 6, hd = e & 63;
        #pragma unroll
        for (int i = 0; i < 2; i++) {
            const int r = r0 + tm2*2 + i;
            const int bb2 = r >> 7, n = r & 127;
            const float tcf = g_tcf[r];
            out[(((size_t)(bb2*Hh + hh))*NBR + n)*HD + hd] = (i ? v1 : v0) + bias[e]*tcf;
        }
    }
}

// ---------------- kernel 3: low-res logits (16 q-rows per CTA) ----------------
__global__ __launch_bounds__(256) void lowlogit_kernel()
{
    const int mb = blockIdx.y, q0 = blockIdx.x*16;
    const int bb = mb / Hh;
    const int tid = threadIdx.x;
    __shared__ float Kt[64][129];     // [d][m]
    __shared__ float Qhs[16][65];
    __shared__ float tcs[NBR];

    for (int i = tid; i < NBR*HD; i += 256) {
        int m = i >> 6, d = i & 63;
        Kt[d][m] = g_Kh[((size_t)mb*NBR + m)*HD + d];
    }
    for (int i = tid; i < 16*HD; i += 256) {
        int qq = i >> 6, d = i & 63;
        Qhs[qq][d] = g_Qh[((size_t)mb*NBR + q0 + qq)*HD + d];
    }
    if (tid < NBR) tcs[tid] = g_tcb[bb*NBR + tid];
    __syncthreads();

    const int q = tid >> 4, mg = tid & 15;
    float s[8];
    #pragma unroll
    for (int k = 0; k < 8; k++) s[k] = 0.f;
    for (int d = 0; d < HD; d++) {
        float qv = Qhs[q][d];
        const float* kr = &Kt[d][mg];
        #pragma unroll
        for (int k = 0; k < 8; k++) s[k] += qv*kr[16*k];
    }
    #pragma unroll
    for (int k = 0; k < 8; k++) s[k] *= 0.125f;

    float mx = s[0];
    #pragma unroll
    for (int k = 1; k < 8; k++) mx = fmaxf(mx, s[k]);
    #pragma unroll
    for (int off = 8; off >= 1; off >>= 1)
        mx = fmaxf(mx, __shfl_xor_sync(0xffffffffu, mx, off, 16));
    const int n = q0 + q;
    if (mg == 0) g_rowmax[mb*NBR + n] = mx;

    const float tcn = tcs[n];
    float* llr = g_ll + ((size_t)mb*NBR + n)*NBR;
    float* prr = g_prior + ((size_t)mb*NBR + n)*NBR;
    #pragma unroll
    for (int k = 0; k < 8; k++) {
        int m = mg + 16*k;
        float pe = (tcn*tcs[m] < 0.5f) ? 1.0f : 0.0f;
        float ll = s[k] - 1e4f*pe;
        float prior = ll - mx;
        int dif = n - m; if (dif < 0) dif = -dif;
        if (dif <= 1) prior += 5e3f;
        llr[m] = ll;
        prr[m] = prior;
    }
}

// ---------------- kernel 4+5 merged: radix threshold + deterministic select ----------------
#define TS_SMEM (NBR*NBR*4 + 256*4 + 16)
__global__ __launch_bounds__(256) void threshsel_kernel()
{
    extern __shared__ __align__(16) float ts_sm[];
    float* prs = ts_sm;
    unsigned* hist = (unsigned*)(ts_sm + NBR*NBR);
    unsigned* ctrl = hist + 256;

    const int mb = blockIdx.x;
    const int tid = threadIdx.x;
    const int lane = tid & 31;
    const float* pr = g_prior + (size_t)mb*NBR*NBR;
    for (int i = tid; i < NBR*NBR; i += 256) prs[i] = pr[i];
    if (tid == 0) { ctrl[0] = 0u; ctrl[1] = NUMBLK; }
    __syncthreads();

    for (int pass = 0; pass < 4; pass++) {
        int shift = 24 - pass*8;
        hist[tid] = 0u;
        __syncthreads();
        unsigned pref = ctrl[0];
        for (int i = tid; i < NBR*NBR; i += 256) {
            unsigned u = f2ord(prs[i]);
            bool ok = (pass == 0) ? true : (((u ^ pref) >> (shift + 8)) == 0u);
            unsigned bin = ok ? ((u >> shift) & 255u) : 0xFFFFFFFFu;
            unsigned mm = __match_any_sync(0xffffffffu, bin);
            if (bin != 0xFFFFFFFFu && (__ffs(mm) - 1) == lane)
                atomicAdd(&hist[bin], __popc(mm));
        }
        __syncthreads();
        if (tid == 0) {
            int k = (int)ctrl[1]; unsigned cum = 0u; int sel = 0;
            for (int bbin = 255; bbin >= 0; bbin--) {
                unsigned h = hist[bbin];
                if (cum + h >= (unsigned)k) { sel = bbin; break; }
                cum += h;
            }
            ctrl[1] = (unsigned)(k - (int)cum);
            ctrl[0] = pref | ((unsigned)sel << shift);
        }
        __syncthreads();
    }
    float t;
    {
        unsigned u = ctrl[0];
        unsigned raw = (u & 0x80000000u) ? (u & 0x7FFFFFFFu) : ~u;
        t = __uint_as_float(raw);
    }
    if (tid == 0) g_thresh[mb] = t;

    if (tid < 128) {
        const int n = tid;
        const float* prow = prs + n*NBR;
        int* lst = g_list + ((size_t)mb*NBR + n)*NBR;
        int c = 0;
        for (int m = 0; m < NBR; m++)
            if (prow[m] >= t) lst[c++] = m;
        g_cnt[mb*NBR + n] = c;
    }
}

// ---------------- kernel 7: low-res attention (16 n-rows per CTA) ----------------
__global__ __launch_bounds__(256) void lowres_kernel()
{
    const int mb = blockIdx.y, n0 = blockIdx.x*16;
    const int bb = mb / Hh;
    const int tid = threadIdx.x;
    __shared__ float4 V4[NBR][16];
    __shared__ float a_sh[16][129];
    __shared__ float tcs[NBR];

    for (int i = tid; i < NBR*16; i += 256) {
        int m = i >> 4, dg = i & 15;
        V4[m][dg] = *(const float4*)&g_Vh[((size_t)mb*NBR + m)*HD + dg*4];
    }
    if (tid < NBR) tcs[tid] = g_tcb[bb*NBR + tid];
    __syncthreads();

    const int nn = tid >> 4, mg = tid & 15;
    const int n = n0 + nn;
    const float rmv = g_rowmax[mb*NBR + n];
    const float t = g_thresh[mb];
    const float* llr = g_ll + ((size_t)mb*NBR + n)*NBR;
    const float* prr = g_prior + ((size_t)mb*NBR + n)*NBR;
    float psum = 0.f;
    #pragma unroll
    for (int k = 0; k < 8; k++) {
        int m = mg + 16*k;
        float sel = (prr[m] >= t) ? 1e4f : 0.f;
        float a = __expf(llr[m] - rmv - sel) * tcs[m];
        a_sh[nn][m] = a;
        psum += a;
    }
    #pragma unroll
    for (int off = 8; off >= 1; off >>= 1)
        psum += __shfl_xor_sync(0xffffffffu, psum, off, 16);
    if (mg == 0) g_low_norm[mb*NBR + n] = psum;
    __syncthreads();

    {
        const int dg = tid & 15;
        const float* ar = a_sh[tid >> 4];
        float4 acc = make_float4(0.f, 0.f, 0.f, 0.f);
        #pragma unroll 8
        for (int m = 0; m < NBR; m++) {
            float av = ar[m];
            float4 v = V4[m][dg];
            acc.x += av*v.x; acc.y += av*v.y; acc.z += av*v.z; acc.w += av*v.w;
        }
        *(float4*)&g_low_out[((size_t)mb*NBR + n0 + (tid >> 4))*HD + dg*4] = acc;
    }
}

// ---------------- kernel 6: high-res attention + fused combine epilogue ----------------
#define OKH 0
#define OKL 9216
#define OVH 18432
#define OVL 27648
#define OKM 36864
#define OPH 37120
#define OPL 39680
#define OMAXP 42240
#define OSUMP 42752
#define ORM 43264
#define OSC 43392
#define ONRM 43520
#define HR_SMEM 43648

__global__ __launch_bounds__(128) void highres_kernel(const float* __restrict__ mask,
                                                      float* __restrict__ gout)
{
    __shared__ __align__(16) char sm[HR_SMEM];
    __shared__ float QM[32];
    __shared__ float LOWR[64];
    __shared__ float s_rmb, s_ln;
    const uint32_t sb = smem_u32(sm);
    const int mbn = blockIdx.x;
    const int mb = mbn >> 7, q = mbn & 127;
    const int bb = mb / Hh, hh = mb % Hh;
    const int tid = threadIdx.x;
    const int lane = tid & 31, w = tid >> 5;

    const int nb = g_cnt[mbn];
    const int* lst = g_list + (size_t)mbn*NBR;
    const size_t qrow = (size_t)mb*Ss + q*BLKSZ;

    float* RM  = (float*)(sm + ORM);
    float* SC  = (float*)(sm + OSC);
    float* NRM = (float*)(sm + ONRM);
    float* MAXP = (float*)(sm + OMAXP);
    float* SUMP = (float*)(sm + OSUMP);

    for (int i = tid; i < 256; i += 128) {
        int r = i >> 3, ch = i & 7;
        *(uint4*)(sm + OKH + r*144 + ch*16)        = ((const uint4*)(g_Qbh + (qrow + r)*HD))[ch];
        *(uint4*)(sm + OKH + 4608 + r*144 + ch*16) = ((const uint4*)(g_Qbl + (qrow + r)*HD))[ch];
    }
    if (tid < 32) {
        RM[tid] = -1e30f; NRM[tid] = 0.f;
        QM[tid] = mask[(size_t)bb*Ss + q*BLKSZ + tid];
    }
    if (tid >= 64 && tid < 128) LOWR[tid - 64] = g_low_out[((size_t)mb*NBR + q)*HD + tid - 64];
    if (tid == 32) s_rmb = g_rowmax[mb*NBR + q];
    if (tid == 33) s_ln = g_low_norm[mb*NBR + q];
    __syncthreads();

    uint32_t aQh[2][4][4], aQl[2][4][4];
    #pragma unroll
    for (int mt = 0; mt < 2; mt++) {
        int row = mt*16 + (lane & 7) + ((lane >> 3) & 1)*8;
        #pragma unroll
        for (int ks = 0; ks < 4; ks++) {
            uint32_t ad = sb + OKH + row*144 + (ks*2 + (lane >> 4))*16;
            ldsm4(aQh[mt][ks][0], aQh[mt][ks][1], aQh[mt][ks][2], aQh[mt][ks][3], ad);
            ldsm4(aQl[mt][ks][0], aQl[mt][ks][1], aQl[mt][ks][2], aQl[mt][ks][3], ad + 4608);
        }
    }
    __syncthreads();

    float o[2][2][4];
    #pragma unroll
    for (int mt = 0; mt < 2; mt++)
        #pragma unroll
        for (int nt = 0; nt < 2; nt++)
            #pragma unroll
            for (int j = 0; j < 4; j++) o[mt][nt][j] = 0.f;

    #define HR_LOAD(st, kb) do { \
        size_t _rb = (size_t)mb*Ss + (size_t)(kb)*BLKSZ; \
        for (int _i = tid; _i < 256; _i += 128) { \
            int _r = _i >> 3, _ch = _i & 7; \
            uint32_t _so = (st)*4608 + _r*144 + _ch*16; \
            CP_ASYNC16(sb + OKH + _so, ((const uint4*)(g_Kbh + (_rb + _r)*HD)) + _ch); \
            CP_ASYNC16(sb + OKL + _so, ((const uint4*)(g_Kbl + (_rb + _r)*HD)) + _ch); \
            CP_ASYNC16(sb + OVH + _so, ((const uint4*)(g_Vbh + (_rb + _r)*HD)) + _ch); \
            CP_ASYNC16(sb + OVL + _so, ((const uint4*)(g_Vbl + (_rb + _r)*HD)) + _ch); \
        } \
        if (tid < 8) CP_ASYNC16(sb + OKM + (st)*128 + tid*16, &mask[(size_t)bb*Ss + (size_t)(kb)*BLKSZ + tid*4]); \
        CP_COMMIT(); \
    } while (0)

    if (nb > 0) HR_LOAD(0, lst[0]);

    for (int it = 0; it < nb; it++) {
        const int cur = it & 1;
        if (it + 1 < nb) {
            HR_LOAD((it+1) & 1, lst[it+1]);
            asm volatile("cp.async.wait_group 1;" ::: "memory");
        } else {
            asm volatile("cp.async.wait_group 0;" ::: "memory");
        }
        __syncthreads();

        float sacc[2][4];
        #pragma unroll
        for (int mt = 0; mt < 2; mt++)
            #pragma unroll
            for (int j = 0; j < 4; j++) sacc[mt][j] = 0.f;

        const uint32_t khb = sb + OKH + cur*4608;
        uint32_t kbh[4][2], kbl[4][2];
        #pragma unroll
        for (int ks = 0; ks < 4; ks++) {
            uint32_t baddr = khb + (8*w + (lane & 7))*144 + (ks*2 + ((lane >> 3) & 1))*16;
            ldsm2(kbh[ks][0], kbh[ks][1], baddr);
            ldsm2(kbl[ks][0], kbl[ks][1], baddr + (OKL - OKH));
        }
        #pragma unroll
        for (int ks = 0; ks < 4; ks++) {
            #pragma unroll
            for (int mt = 0; mt < 2; mt++) {
                mma16816(sacc[mt], aQh[mt][ks][0], aQh[mt][ks][1], aQh[mt][ks][2], aQh[mt][ks][3], kbh[ks][0], kbh[ks][1]);
                mma16816(sacc[mt], aQh[mt][ks][0], aQh[mt][ks][1], aQh[mt][ks][2], aQh[mt][ks][3], kbl[ks][0], kbl[ks][1]);
                mma16816(sacc[mt], aQl[mt][ks][0], aQl[mt][ks][1], aQl[mt][ks][2], aQl[mt][ks][3], kbh[ks][0], kbh[ks][1]);
            }
        }
        #pragma unroll
        for (int mt = 0; mt < 2; mt++)
            #pragma unroll
            for (int j = 0; j < 4; j++) sacc[mt][j] *= 0.125f;

        #pragma unroll
        for (int mt = 0; mt < 2; mt++) {
            float m1 = fmaxf(sacc[mt][0], sacc[mt][1]);
            float m2 = fmaxf(sacc[mt][2], sacc[mt][3]);
            m1 = fmaxf(m1, __shfl_xor_sync(0xffffffffu, m1, 1, 4));
            m1 = fmaxf(m1, __shfl_xor_sync(0xffffffffu, m1, 2, 4));
            m2 = fmaxf(m2, __shfl_xor_sync(0xffffffffu, m2, 1, 4));
            m2 = fmaxf(m2, __shfl_xor_sync(0xffffffffu, m2, 2, 4));
            if ((lane & 3) == 0) {
                int r1 = mt*16 + (lane >> 2);
                MAXP[r1*4 + w] = m1;
                MAXP[(r1+8)*4 + w] = m2;
            }
        }
        __syncthreads();
        if (tid < 32) {
            float tm = fmaxf(fmaxf(MAXP[tid*4], MAXP[tid*4+1]), fmaxf(MAXP[tid*4+2], MAXP[tid*4+3]));
            float old = RM[tid];
            float nm = fmaxf(old, tm);
            SC[tid] = __expf(old - nm);
            RM[tid] = nm;
        }
        __syncthreads();

        const float kmv0 = ((const float*)(sm + OKM + cur*128))[8*w + (lane & 3)*2];
        const float kmv1 = ((const float*)(sm + OKM + cur*128))[8*w + (lane & 3)*2 + 1];
        const float pen0 = 1e4f*(1.f - kmv0), pen1 = 1e4f*(1.f - kmv1);
        const int colb = (8*w + (lane & 3)*2)*2;

        #pragma unroll
        for (int mt = 0; mt < 2; mt++) {
            int r1 = mt*16 + (lane >> 2), r2 = r1 + 8;
            float sc1 = SC[r1], sc2 = SC[r2];
            float rm1 = RM[r1], rm2 = RM[r2];
            #pragma unroll
            for (int nt = 0; nt < 2; nt++) {
                o[mt][nt][0] *= sc1; o[mt][nt][1] *= sc1;
                o[mt][nt][2] *= sc2; o[mt][nt][3] *= sc2;
            }
            float p00, p01, p10, p11;
            if (mt == 0) {
                p00 = __expf(sacc[mt][0] - rm1 - pen0);
                p01 = __expf(sacc[mt][1] - rm1 - pen1);
                p10 = __expf(sacc[mt][2] - rm2 - pen0);
                p11 = fexp_poly(sacc[mt][3] - rm2 - pen1);
            } else {
                p00 = __expf(sacc[mt][0] - rm1 - pen0);
                p01 = __expf(sacc[mt][1] - rm1 - pen1);
                p10 = fexp_poly(sacc[mt][2] - rm2 - pen0);
                p11 = fexp_poly(sacc[mt][3] - rm2 - pen1);
            }

            __nv_bfloat162 ph0 = __floats2bfloat162_rn(p00, p01);
            __nv_bfloat162 pl0 = __floats2bfloat162_rn(
                p00 - __bfloat162float(__low2bfloat16(ph0)),
                p01 - __bfloat162float(__high2bfloat16(ph0)));
            __nv_bfloat162 ph1 = __floats2bfloat162_rn(p10, p11);
            __nv_bfloat162 pl1 = __floats2bfloat162_rn(
                p10 - __bfloat162float(__low2bfloat16(ph1)),
                p11 - __bfloat162float(__high2bfloat16(ph1)));
            *(__nv_bfloat162*)(sm + OPH + r1*80 + colb) = ph0;
            *(__nv_bfloat162*)(sm + OPL + r1*80 + colb) = pl0;
            *(__nv_bfloat162*)(sm + OPH + r2*80 + colb) = ph1;
            *(__nv_bfloat162*)(sm + OPL + r2*80 + colb) = pl1;

            float s1 = p00 + p01, s2 = p10 + p11;
            s1 += __shfl_xor_sync(0xffffffffu, s1, 1, 4);
            s1 += __shfl_xor_sync(0xffffffffu, s1, 2, 4);
            s2 += __shfl_xor_sync(0xffffffffu, s2, 1, 4);
            s2 += __shfl_xor_sync(0xffffffffu, s2, 2, 4);
            if ((lane & 3) == 0) {
                SUMP[r1*4 + w] = s1;
                SUMP[r2*4 + w] = s2;
            }
        }
        __syncthreads();
        if (tid < 32) {
            float s = SUMP[tid*4] + SUMP[tid*4+1] + SUMP[tid*4+2] + SUMP[tid*4+3];
            NRM[tid] = NRM[tid]*SC[tid] + s;
        }

        const uint32_t vhb = sb + OVH + cur*4608;
        #pragma unroll
        for (int ks = 0; ks < 2; ks++) {
            uint32_t aPh[2][4], aPl[2][4];
            #pragma unroll
            for (int mt = 0; mt < 2; mt++) {
                int row = mt*16 + (lane & 7) + ((lane >> 3) & 1)*8;
                uint32_t pad = sb + OPH + row*80 + (ks*2 + (lane >> 4))*16;
                ldsm4(aPh[mt][0], aPh[mt][1], aPh[mt][2], aPh[mt][3], pad);
                ldsm4(aPl[mt][0], aPl[mt][1], aPl[mt][2], aPl[mt][3], pad + (OPL - OPH));
            }
            int vrow = ks*16 + (lane & 7) + ((lane >> 3) & 1)*8;
            uint32_t vad = vhb + vrow*144 + (2*w + (lane >> 4))*16;
            uint32_t bh0, bh1, bh2, bh3, bl0, bl1, bl2, bl3;
            ldsm4t(bh0, bh1, bh2, bh3, vad);
            ldsm4t(bl0, bl1, bl2, bl3, vad + (OVL - OVH));
            #pragma unroll
            for (int mt = 0; mt < 2; mt++) {
                mma16816(o[mt][0], aPh[mt][0], aPh[mt][1], aPh[mt][2], aPh[mt][3], bh0, bh1);
                mma16816(o[mt][1], aPh[mt][0], aPh[mt][1], aPh[mt][2], aPh[mt][3], bh2, bh3);
                mma16816(o[mt][0], aPh[mt][0], aPh[mt][1], aPh[mt][2], aPh[mt][3], bl0, bl1);
                mma16816(o[mt][1], aPh[mt][0], aPh[mt][1], aPh[mt][2], aPh[mt][3], bl2, bl3);
                mma16816(o[mt][0], aPl[mt][0], aPl[mt][1], aPl[mt][2], aPl[mt][3], bh0, bh1);
                mma16816(o[mt][1], aPl[mt][0], aPl[mt][1], aPl[mt][2], aPl[mt][3], bh2, bh3);
            }
        }
        __syncthreads();
    }

    // ---- fused combine epilogue: write final output directly ----
    const float rmb = s_rmb, lnv = s_ln;
    #pragma unroll
    for (int mt = 0; mt < 2; mt++) {
        int r1 = mt*16 + (lane >> 2), r2 = r1 + 8;
        float mx1 = fmaxf(RM[r1], -1e6f), mx2 = fmaxf(RM[r2], -1e6f);
        float lcl1 = (rmb - mx1)*QM[r1], lcl2 = (rmb - mx2)*QM[r2];
        float lc1 = __expf(fminf(lcl1, 0.f)), hc1 = __expf(-fmaxf(lcl1, 0.f));
        float lc2 = __expf(fminf(lcl2, 0.f)), hc2 = __expf(-fmaxf(lcl2, 0.f));
        float inv1 = 1.f/(NRM[r1]*hc1 + lnv*lc1 + 1e-6f);
        float inv2 = 1.f/(NRM[r2]*hc2 + lnv*lc2 + 1e-6f);
        float* op1 = gout + ((size_t)bb*Ss + q*BLKSZ + r1)*Dm + hh*HD;
        float* op2 = gout + ((size_t)bb*Ss + q*BLKSZ + r2)*Dm + hh*HD;
        #pragma unroll
        for (int nt = 0; nt < 2; nt++) {
            int col = 16*w + nt*8 + (lane & 3)*2;
            float2 w1, w2;
            w1.x = (o[mt][nt][0]*hc1 + LOWR[col]*lc1)*inv1;
            w1.y = (o[mt][nt][1]*hc1 + LOWR[col+1]*lc1)*inv1;
            w2.x = (o[mt][nt][2]*hc2 + LOWR[col]*lc2)*inv2;
            w2.y = (o[mt][nt][3]*hc2 + LOWR[col+1]*lc2)*inv2;
            *(float2*)(op1 + col) = w1;
            *(float2*)(op2 + col) = w2;
        }
    }
}

// ---------------- launch ----------------
extern "C" void kernel_launch(void* const* d_in, const int* in_sizes, int n_in,
                              void* d_out, int out_size)
{
    const float* X    = (const float*)d_in[0];
    const float* mask = (const float*)d_in[1];
    const float* Wq   = (const float*)d_in[2];
    const float* bq   = (const float*)d_in[3];
    const float* Wk   = (const float*)d_in[4];
    const float* bk   = (const float*)d_in[5];
    const float* Wv   = (const float*)d_in[6];
    const float* bv   = (const float*)d_in[7];
    float* out = (float*)d_out;

    cudaFuncSetAttribute(qkv_mma_kernel, cudaFuncAttributeMaxDynamicSharedMemorySize, GEMM_SMEM);
    cudaFuncSetAttribute(threshsel_kernel, cudaFuncAttributeMaxDynamicSharedMemorySize, TS_SMEM);

    convX_kernel<<<MROWS*Dm/1024, 256>>>(X);                       // 1
    convW_kernel<<<dim3(Dm*Dm/1024, 3), 256>>>(Wq, Wk, Wv);        // 2
    xbar_kernel<<<Bb*NBR, Dm>>>(X, mask);                          // 3
    qkv_mma_kernel<<<dim3(MROWS/128, 9), 512, GEMM_SMEM>>>(mask, bq, bk, bv);  // 4
    hmean_gemm_kernel<<<dim3(8, 6, 3), 256>>>(Wq, Wk, Wv, bq, bk, bv);         // 5
    lowlogit_kernel<<<dim3(8, MBT), 256>>>();                      // 6
    threshsel_kernel<<<MBT, 256, TS_SMEM>>>();                     // 7
    lowres_kernel<<<dim3(8, MBT), 256>>>();                        // 8
    highres_kernel<<<MBT*NBR, 128>>>(mask, out);                   // 9 (writes final out)
}

// round 12
// speedup vs baseline: 2.8221x; 1.1734x over previous
#include <cuda_runtime.h>
#include <cuda_bf16.h>
#include <cstdint>

// ---------------- problem constants ----------------
#define Bb 2
#define Ss 4096
#define Dm 768
#define Hh 12
#define HD 64
#define BLKSZ 32
#define NBR 128
#define NUMBLK 1024
#define MBT (Bb*Hh)        // 24
#define MROWS (Bb*Ss)      // 8192

typedef unsigned long long ull;

__device__ __forceinline__ uint32_t smem_u32(const void* p) {
    uint32_t a;
    asm("{ .reg .u64 t; cvta.to.shared.u64 t, %1; cvt.u32.u64 %0, t; }" : "=r"(a) : "l"(p));
    return a;
}

// ---------------- mbarrier + bulk-copy helpers (base sm_90 PTX) ----------------
#define MB_INIT(mb, c) \
    asm volatile("mbarrier.init.shared.b64 [%0], %1;" :: "r"((uint32_t)(mb)), "r"((uint32_t)(c)) : "memory")
#define MB_ARRIVE_TX(mb, bytes) \
    asm volatile("mbarrier.arrive.expect_tx.shared.b64 _, [%0], %1;" :: "r"((uint32_t)(mb)), "r"((uint32_t)(bytes)) : "memory")
#define BULK_G2S(dst, src, size, mb) \
    asm volatile("cp.async.bulk.shared::cluster.global.mbarrier::complete_tx::bytes [%0], [%1], %2, [%3];" \
        :: "r"((uint32_t)(dst)), "l"(src), "r"((uint32_t)(size)), "r"((uint32_t)(mb)) : "memory")
#define MB_WAIT(mb, ph) do { \
    uint32_t _m = (uint32_t)(mb); uint32_t _p = (uint32_t)(ph); uint32_t _d; \
    asm volatile("{\n\t.reg .pred p;\n\tmbarrier.try_wait.parity.acquire.cta.shared::cta.b64 p, [%1], %2;\n\tselp.b32 %0, 1, 0, p;\n\t}" \
        : "=r"(_d) : "r"(_m), "r"(_p) : "memory"); \
    if (!_d) { \
        asm volatile("{\n\t.reg .pred P1;\n\tWL_%=:\n\tmbarrier.try_wait.parity.acquire.cta.shared::cta.b64 P1, [%0], %1, 0x989680;\n\t@P1 bra.uni WD_%=;\n\tbra.uni WL_%=;\n\tWD_%=:\n\t}" \
            :: "r"(_m), "r"(_p) : "memory"); \
    } } while (0)

// ---------------- mma.sync helpers ----------------
__device__ __forceinline__ void ldsm4(uint32_t &r0, uint32_t &r1, uint32_t &r2, uint32_t &r3, uint32_t addr) {
    asm volatile("ldmatrix.sync.aligned.m8n8.x4.shared.b16 {%0,%1,%2,%3}, [%4];"
        : "=r"(r0), "=r"(r1), "=r"(r2), "=r"(r3) : "r"(addr));
}
__device__ __forceinline__ void ldsm2(uint32_t &r0, uint32_t &r1, uint32_t addr) {
    asm volatile("ldmatrix.sync.aligned.m8n8.x2.shared.b16 {%0,%1}, [%2];"
        : "=r"(r0), "=r"(r1) : "r"(addr));
}
__device__ __forceinline__ void ldsm4t(uint32_t &r0, uint32_t &r1, uint32_t &r2, uint32_t &r3, uint32_t addr) {
    asm volatile("ldmatrix.sync.aligned.m8n8.x4.trans.shared.b16 {%0,%1,%2,%3}, [%4];"
        : "=r"(r0), "=r"(r1), "=r"(r2), "=r"(r3) : "r"(addr));
}
__device__ __forceinline__ void mma16816(float* c,
    uint32_t a0, uint32_t a1, uint32_t a2, uint32_t a3, uint32_t b0, uint32_t b1) {
    asm volatile("mma.sync.aligned.m16n8k16.row.col.f32.bf16.bf16.f32 "
        "{%0,%1,%2,%3}, {%4,%5,%6,%7}, {%8,%9}, {%0,%1,%2,%3};"
        : "+f"(c[0]), "+f"(c[1]), "+f"(c[2]), "+f"(c[3])
        : "r"(a0), "r"(a1), "r"(a2), "r"(a3), "r"(b0), "r"(b1));
}

// ---------------- f32x2 helpers ----------------
__device__ __forceinline__ void ffma2(ull &d, ull a, ull b) {
    asm("fma.rn.f32x2 %0, %1, %2, %0;" : "+l"(d) : "l"(a), "l"(b));
}
__device__ __forceinline__ ull pack2(float x, float y) {
    ull r; asm("mov.b64 %0, {%1, %2};" : "=l"(r) : "f"(x), "f"(y)); return r;
}
__device__ __forceinline__ void unpack2(ull v, float &x, float &y) {
    asm("mov.b64 {%0, %1}, %2;" : "=f"(x), "=f"(y) : "l"(v));
}

// fast exp on the fma/alu pipes
__device__ __forceinline__ float fexp_poly(float x) {
    float z = x * 1.4426950408889634f;
    z = fmaxf(z, -120.f);
    float m = z + 12582912.0f;
    int n = __float_as_int(m) - 0x4B400000;
    float f = z - (m - 12582912.0f);
    float p = 1.3333558e-3f;
    p = fmaf(p, f, 9.6181291e-3f);
    p = fmaf(p, f, 5.5504109e-2f);
    p = fmaf(p, f, 2.4022651e-1f);
    p = fmaf(p, f, 6.9314718e-1f);
    p = fmaf(p, f, 1.0f);
    float r = __int_as_float(__float_as_int(p) + (n << 23));
    return (x < -80.f) ? 0.f : r;
}

// ---------------- device scratch ----------------
// Blocked, pre-swizzled layouts for bulk copies:
//  X: [kchunk 0..23][row 0..8191][32 bf16], 16B cell c4 stored at c4^((row>>1)&3)
//  W: [mat][kchunk][n 0..767][32 bf16], swizzle c4^((n>>1)&3)
//  Q/K/V: [mb][blk 0..127][r 0..31][64 bf16], 16B cell c8 stored at c8^(r&7)
__device__ __align__(256) __nv_bfloat16 g_Qbh[MBT*Ss*HD];
__device__ __align__(256) __nv_bfloat16 g_Qbl[MBT*Ss*HD];
__device__ __align__(256) __nv_bfloat16 g_Kbh[MBT*Ss*HD];
__device__ __align__(256) __nv_bfloat16 g_Kbl[MBT*Ss*HD];
__device__ __align__(256) __nv_bfloat16 g_Vbh[MBT*Ss*HD];
__device__ __align__(256) __nv_bfloat16 g_Vbl[MBT*Ss*HD];
__device__ __align__(256) __nv_bfloat16 g_Xh[MROWS*Dm];
__device__ __align__(256) __nv_bfloat16 g_Xl[MROWS*Dm];
__device__ __align__(256) __nv_bfloat16 g_Wh[3*Dm*Dm];
__device__ __align__(256) __nv_bfloat16 g_Wl[3*Dm*Dm];
__device__ float g_Xbar[Bb*NBR*Dm];
__device__ float g_tcb[Bb*NBR];
__device__ float g_tcf[Bb*NBR];
__device__ float g_Qh[MBT*NBR*HD];
__device__ float g_Kh[MBT*NBR*HD];
__device__ float g_Vh[MBT*NBR*HD];
__device__ float g_ll[MBT*NBR*NBR];
__device__ float g_prior[MBT*NBR*NBR];
__device__ float g_rowmax[MBT*NBR];
__device__ float g_thresh[MBT];
__device__ int   g_cnt[MBT*NBR];
__device__ int   g_list[MBT*NBR*NBR];
__device__ float g_low_out[MBT*NBR*HD];
__device__ float g_low_norm[MBT*NBR];

__device__ __forceinline__ unsigned f2ord(float f) {
    unsigned u = __float_as_uint(f);
    return (u & 0x80000000u) ? ~u : (u | 0x80000000u);
}

// ---------------- kernel 0a: split X -> k-chunk-major swizzled bf16 hi/lo ----------------
__global__ void convX_kernel(const float* __restrict__ X)
{
    int idx = blockIdx.x*256 + threadIdx.x;    // one 16B cell (8 elems)
    int row = idx / 96, cidx = idx % 96;
    int kc = cidx >> 2, c4 = cidx & 3;
    const float* src = X + (size_t)row*Dm + cidx*8;
    float4 v0 = *(const float4*)src;
    float4 v1 = *(const float4*)(src + 4);
    float vf[8] = {v0.x, v0.y, v0.z, v0.w, v1.x, v1.y, v1.z, v1.w};
    __nv_bfloat16 h[8], l[8];
    #pragma unroll
    for (int j = 0; j < 8; j++) {
        h[j] = __float2bfloat16(vf[j]);
        l[j] = __float2bfloat16(vf[j] - __bfloat162float(h[j]));
    }
    size_t dst = ((size_t)kc*MROWS + row)*64 + ((c4 ^ ((row>>1)&3))<<4);
    *(uint4*)((char*)g_Xh + dst) = *(uint4*)h;
    *(uint4*)((char*)g_Xl + dst) = *(uint4*)l;
}

// ---------------- kernel 0b: split W -> k-chunk-major swizzled bf16 hi/lo ----------------
__global__ void convW_kernel(const float* __restrict__ Wq,
                             const float* __restrict__ Wk,
                             const float* __restrict__ Wv)
{
    int mat = blockIdx.y;
    const float* W = (mat == 0) ? Wq : (mat == 1) ? Wk : Wv;
    int idx = blockIdx.x*256 + threadIdx.x;
    int n = idx / 96, cidx = idx % 96;
    int kc = cidx >> 2, c4 = cidx & 3;
    const float* src = W + (size_t)n*Dm + cidx*8;
    float4 v0 = *(const float4*)src;
    float4 v1 = *(const float4*)(src + 4);
    float vf[8] = {v0.x, v0.y, v0.z, v0.w, v1.x, v1.y, v1.z, v1.w};
    __nv_bfloat16 h[8], l[8];
    #pragma unroll
    for (int j = 0; j < 8; j++) {
        h[j] = __float2bfloat16(vf[j]);
        l[j] = __float2bfloat16(vf[j] - __bfloat162float(h[j]));
    }
    size_t dst = (((size_t)mat*24 + kc)*Dm + n)*64 + ((c4 ^ ((n>>1)&3))<<4);
    *(uint4*)((char*)g_Wh + dst) = *(uint4*)h;
    *(uint4*)((char*)g_Wl + dst) = *(uint4*)l;
}

// ---------------- kernel 0c: masked block-mean of X ----------------
__global__ void xbar_kernel(const float* __restrict__ X, const float* __restrict__ mask)
{
    int bn = blockIdx.x;
    int bb = bn >> 7, n = bn & 127;
    int d = threadIdx.x;             // 768
    const float* mrow = mask + (size_t)bb*Ss + n*BLKSZ;
    float tc = 0.f;
    #pragma unroll
    for (int t = 0; t < BLKSZ; t++) tc += mrow[t];
    float denom = tc + 1e-6f;
    const float* xp = X + ((size_t)bb*Ss + n*BLKSZ)*Dm + d;
    float s = 0.f;
    #pragma unroll 4
    for (int t = 0; t < BLKSZ; t++) s += mrow[t]*xp[(size_t)t*Dm];
    g_Xbar[(size_t)bn*Dm + d] = s/denom;
    if (d == 0) { g_tcb[bn] = tc; g_tcf[bn] = tc/denom; }
}

// ---------------- kernel 1: QKV projection, bulk-copy pipeline ----------------
// stage = one k-chunk (32). Stage smem: A-hi 8K | A-lo 8K | B-hi 16K | B-lo 16K = 48K, x3 stages.
#define QSTG 49152
#define QMBAR (3*QSTG)
#define GEMM_SMEM (QMBAR + 64)

__global__ __launch_bounds__(512, 1) void qkv_mma_kernel(
    const float* __restrict__ mask,
    const float* __restrict__ bq, const float* __restrict__ bk, const float* __restrict__ bv)
{
    extern __shared__ __align__(128) char smem[];
    const uint32_t sb = smem_u32(smem);
    const int tid = threadIdx.x, lane = tid & 31, wid = tid >> 5;
    const int m0 = blockIdx.x * 128;
    const int tile = blockIdx.y;          // 0..8
    const int mat = tile / 3;
    const int n0 = (tile % 3) * 256;
    const int wm = wid & 3;               // m strip of 32
    const int wn = wid >> 2;              // n strip of 64

    const float* bias = (mat == 0) ? bq : (mat == 1) ? bk : bv;
    __nv_bfloat16* outH = (mat == 0) ? g_Qbh : (mat == 1) ? g_Kbh : g_Vbh;
    __nv_bfloat16* outL = (mat == 0) ? g_Qbl : (mat == 1) ? g_Kbl : g_Vbl;

    if (tid == 0) {
        MB_INIT(sb + QMBAR + 0, 1);
        MB_INIT(sb + QMBAR + 8, 1);
        MB_INIT(sb + QMBAR + 16, 1);
    }
    __syncthreads();

    float acc[2][8][4];
    #pragma unroll
    for (int a = 0; a < 2; a++)
        #pragma unroll
        for (int b = 0; b < 8; b++)
            #pragma unroll
            for (int c = 0; c < 4; c++) acc[a][b][c] = 0.f;

    #define QISSUE(s) do { if (tid == 0) { \
        const int _b = (s) % 3; \
        const uint32_t _bb = sb + _b*QSTG; \
        const uint32_t _mb = sb + QMBAR + _b*8; \
        MB_ARRIVE_TX(_mb, 49152); \
        BULK_G2S(_bb,         (const char*)g_Xh + ((size_t)(s)*MROWS + m0)*64, 8192, _mb); \
        BULK_G2S(_bb + 8192,  (const char*)g_Xl + ((size_t)(s)*MROWS + m0)*64, 8192, _mb); \
        BULK_G2S(_bb + 16384, (const char*)g_Wh + (((size_t)mat*24 + (s))*Dm + n0)*64, 16384, _mb); \
        BULK_G2S(_bb + 32768, (const char*)g_Wl + (((size_t)mat*24 + (s))*Dm + n0)*64, 16384, _mb); \
    } } while (0)

    QISSUE(0);
    QISSUE(1);

    for (int s = 0; s < 24; s++) {
        MB_WAIT(sb + QMBAR + (s % 3)*8, (s / 3) & 1);
        __syncthreads();
        if (s + 2 < 24) QISSUE(s + 2);
        const uint32_t base = sb + (s % 3)*QSTG;

        #pragma unroll
        for (int kk = 0; kk < 2; kk++) {
            uint32_t ah[2][4], al[2][4];
            #pragma unroll
            for (int mt = 0; mt < 2; mt++) {
                int row = wm*32 + mt*16 + (lane & 7) + ((lane >> 3) & 1)*8;
                int cell = kk*2 + (lane >> 4);
                uint32_t ad = base + row*64 + ((cell ^ ((row >> 1) & 3)) << 4);
                ldsm4(ah[mt][0], ah[mt][1], ah[mt][2], ah[mt][3], ad);
                ldsm4(al[mt][0], al[mt][1], al[mt][2], al[mt][3], ad + 8192);
            }
            #pragma unroll
            for (int np = 0; np < 4; np++) {
                int n = wn*64 + np*16 + (lane & 7) + ((lane >> 4) << 3);
                int cellB = kk*2 + ((lane >> 3) & 1);
                uint32_t bd = base + 16384 + n*64 + ((cellB ^ ((n >> 1) & 3)) << 4);
                uint32_t b0, b1, b2, b3, c0, c1, c2, c3;
                ldsm4(b0, b1, b2, b3, bd);
                ldsm4(c0, c1, c2, c3, bd + 16384);
                #pragma unroll
                for (int mt = 0; mt < 2; mt++) {
                    mma16816(acc[mt][np*2],   ah[mt][0], ah[mt][1], ah[mt][2], ah[mt][3], b0, b1);
                    mma16816(acc[mt][np*2+1], ah[mt][0], ah[mt][1], ah[mt][2], ah[mt][3], b2, b3);
                    mma16816(acc[mt][np*2],   al[mt][0], al[mt][1], al[mt][2], al[mt][3], b0, b1);
                    mma16816(acc[mt][np*2+1], al[mt][0], al[mt][1], al[mt][2], al[mt][3], b2, b3);
                    mma16816(acc[mt][np*2],   ah[mt][0], ah[mt][1], ah[mt][2], ah[mt][3], c0, c1);
                    mma16816(acc[mt][np*2+1], ah[mt][0], ah[mt][1], ah[mt][2], ah[mt][3], c2, c3);
                }
            }
        }
    }

    const int h = (n0 + wn*64) >> 6;
    const float* bp = bias + n0 + wn*64;
    float2 bias2[8];
    #pragma unroll
    for (int nt = 0; nt < 8; nt++) bias2[nt] = *(const float2*)(bp + nt*8 + (lane & 3)*2);

    #pragma unroll
    for (int mt = 0; mt < 2; mt++) {
        #pragma unroll
        for (int half = 0; half < 2; half++) {
            int m = m0 + wm*32 + mt*16 + (lane >> 2) + half*8;
            int bbm = m >> 12, sx = m & 4095;
            float mv = mask[(size_t)bbm*Ss + sx];
            int mb_ = bbm*Hh + h, kb = sx >> 5, r = sx & 31;
            size_t tb = ((size_t)(mb_*128 + kb)*32 + r)*64;
            #pragma unroll
            for (int nt = 0; nt < 8; nt++) {
                size_t off = tb + ((nt ^ (r & 7)) << 3) + (lane & 3)*2;
                float wx = (acc[mt][nt][half*2+0] + bias2[nt].x)*mv;
                float wy = (acc[mt][nt][half*2+1] + bias2[nt].y)*mv;
                __nv_bfloat162 hv = __floats2bfloat162_rn(wx, wy);
                float hx = __bfloat162float(__low2bfloat16(hv));
                float hy = __bfloat162float(__high2bfloat16(hv));
                __nv_bfloat162 lv = __floats2bfloat162_rn(wx - hx, wy - hy);
                *(__nv_bfloat162*)(outH + off) = hv;
                *(__nv_bfloat162*)(outL + off) = lv;
            }
        }
    }
}

// ---------------- kernel 1b: exact fp32 block-mean projection (f32x2) ----------------
__global__ __launch_bounds__(256) void hmean_gemm_kernel(
    const float* __restrict__ Wq, const float* __restrict__ Wk, const float* __restrict__ Wv,
    const float* __restrict__ bq, const float* __restrict__ bk, const float* __restrict__ bv)
{
    __shared__ float As[32][33];
    __shared__ float Bs[128][33];

    const int mat = blockIdx.z;
    const float* W = (mat == 0) ? Wq : (mat == 1) ? Wk : Wv;
    const float* bias = (mat == 0) ? bq : (mat == 1) ? bk : bv;
    float* out = (mat == 0) ? g_Qh : (mat == 1) ? g_Kh : g_Vh;

    const int tid = threadIdx.x;
    const int r0 = blockIdx.x * 32;
    const int e0 = blockIdx.y * 128;
    const int tn = tid >> 4;
    const int tm2 = tid & 15;

    ull acc2[8];
    #pragma unroll
    for (int j = 0; j < 8; j++) acc2[j] = 0ull;

    for (int k0 = 0; k0 < Dm; k0 += 32) {
        {
            int r = tid >> 3, kq = tid & 7;
            float4 v = *(const float4*)&g_Xbar[(size_t)(r0 + r)*Dm + k0 + kq*4];
            As[r][kq*4+0] = v.x; As[r][kq*4+1] = v.y; As[r][kq*4+2] = v.z; As[r][kq*4+3] = v.w;
        }
        #pragma unroll
        for (int t = 0; t < 4; t++) {
            int idx = tid + t*256;
            int r = idx >> 3, kq = idx & 7;
            float4 v = *(const float4*)&W[(size_t)(e0 + r)*Dm + k0 + kq*4];
            Bs[r][kq*4+0] = v.x; Bs[r][kq*4+1] = v.y; Bs[r][kq*4+2] = v.z; Bs[r][kq*4+3] = v.w;
        }
        __syncthreads();
        #pragma unroll 8
        for (int k = 0; k < 32; k++) {
            ull a2 = pack2(As[tm2*2][k], As[tm2*2+1][k]);
            #pragma unroll
            for (int j = 0; j < 8; j++) {
                float b = Bs[tn*8+j][k];
                ffma2(acc2[j], a2, pack2(b, b));
            }
        }
        __syncthreads();
    }

    #pragma unroll
    for (int j = 0; j < 8; j++) {
        float v0, v1;
        unpack2(acc2[j], v0, v1);
        int e = e0 + tn*8 + j;
        int hh = e >> 6, hd = e & 63;
        #pragma unroll
        for (int i = 0; i < 2; i++) {
            const int r = r0 + tm2*2 + i;
            const int bb2 = r >> 7, n = r & 127;
            const float tcf = g_tcf[r];
            out[(((size_t)(bb2*Hh + hh))*NBR + n)*HD + hd] = (i ? v1 : v0) + bias[e]*tcf;
        }
    }
}

// ---------------- kernel 3: low-res logits (16 q-rows per CTA) ----------------
__global__ __launch_bounds__(256) void lowlogit_kernel()
{
    const int mb = blockIdx.y, q0 = blockIdx.x*16;
    const int bb = mb / Hh;
    const int tid = threadIdx.x;
    __shared__ float Kt[64][129];     // [d][m]
    __shared__ float Qhs[16][65];
    __shared__ float tcs[NBR];

    for (int i = tid; i < NBR*HD; i += 256) {
        int m = i >> 6, d = i & 63;
        Kt[d][m] = g_Kh[((size_t)mb*NBR + m)*HD + d];
    }
    for (int i = tid; i < 16*HD; i += 256) {
        int qq = i >> 6, d = i & 63;
        Qhs[qq][d] = g_Qh[((size_t)mb*NBR + q0 + qq)*HD + d];
    }
    if (tid < NBR) tcs[tid] = g_tcb[bb*NBR + tid];
    __syncthreads();

    const int q = tid >> 4, mg = tid & 15;
    float s[8];
    #pragma unroll
    for (int k = 0; k < 8; k++) s[k] = 0.f;
    for (int d = 0; d < HD; d++) {
        float qv = Qhs[q][d];
        const float* kr = &Kt[d][mg];
        #pragma unroll
        for (int k = 0; k < 8; k++) s[k] += qv*kr[16*k];
    }
    #pragma unroll
    for (int k = 0; k < 8; k++) s[k] *= 0.125f;

    float mx = s[0];
    #pragma unroll
    for (int k = 1; k < 8; k++) mx = fmaxf(mx, s[k]);
    #pragma unroll
    for (int off = 8; off >= 1; off >>= 1)
        mx = fmaxf(mx, __shfl_xor_sync(0xffffffffu, mx, off, 16));
    const int n = q0 + q;
    if (mg == 0) g_rowmax[mb*NBR + n] = mx;

    const float tcn = tcs[n];
    float* llr = g_ll + ((size_t)mb*NBR + n)*NBR;
    float* prr = g_prior + ((size_t)mb*NBR + n)*NBR;
    #pragma unroll
    for (int k = 0; k < 8; k++) {
        int m = mg + 16*k;
        float pe = (tcn*tcs[m] < 0.5f) ? 1.0f : 0.0f;
        float ll = s[k] - 1e4f*pe;
        float prior = ll - mx;
        int dif = n - m; if (dif < 0) dif = -dif;
        if (dif <= 1) prior += 5e3f;
        llr[m] = ll;
        prr[m] = prior;
    }
}

// ---------------- kernel 4+5 merged: radix threshold + deterministic select ----------------
#define TS_SMEM (NBR*NBR*4 + 256*4 + 16)
__global__ __launch_bounds__(256) void threshsel_kernel()
{
    extern __shared__ __align__(16) float ts_sm[];
    float* prs = ts_sm;
    unsigned* hist = (unsigned*)(ts_sm + NBR*NBR);
    unsigned* ctrl = hist + 256;

    const int mb = blockIdx.x;
    const int tid = threadIdx.x;
    const int lane = tid & 31;
    const float* pr = g_prior + (size_t)mb*NBR*NBR;
    for (int i = tid; i < NBR*NBR; i += 256) prs[i] = pr[i];
    if (tid == 0) { ctrl[0] = 0u; ctrl[1] = NUMBLK; }
    __syncthreads();

    for (int pass = 0; pass < 4; pass++) {
        int shift = 24 - pass*8;
        hist[tid] = 0u;
        __syncthreads();
        unsigned pref = ctrl[0];
        for (int i = tid; i < NBR*NBR; i += 256) {
            unsigned u = f2ord(prs[i]);
            bool ok = (pass == 0) ? true : (((u ^ pref) >> (shift + 8)) == 0u);
            unsigned bin = ok ? ((u >> shift) & 255u) : 0xFFFFFFFFu;
            unsigned mm = __match_any_sync(0xffffffffu, bin);
            if (bin != 0xFFFFFFFFu && (__ffs(mm) - 1) == lane)
                atomicAdd(&hist[bin], __popc(mm));
        }
        __syncthreads();
        if (tid == 0) {
            int k = (int)ctrl[1]; unsigned cum = 0u; int sel = 0;
            for (int bbin = 255; bbin >= 0; bbin--) {
                unsigned h = hist[bbin];
                if (cum + h >= (unsigned)k) { sel = bbin; break; }
                cum += h;
            }
            ctrl[1] = (unsigned)(k - (int)cum);
            ctrl[0] = pref | ((unsigned)sel << shift);
        }
        __syncthreads();
    }
    float t;
    {
        unsigned u = ctrl[0];
        unsigned raw = (u & 0x80000000u) ? (u & 0x7FFFFFFFu) : ~u;
        t = __uint_as_float(raw);
    }
    if (tid == 0) g_thresh[mb] = t;

    if (tid < 128) {
        const int n = tid;
        const float* prow = prs + n*NBR;
        int* lst = g_list + ((size_t)mb*NBR + n)*NBR;
        int c = 0;
        for (int m = 0; m < NBR; m++)
            if (prow[m] >= t) lst[c++] = m;
        g_cnt[mb*NBR + n] = c;
    }
}

// ---------------- kernel 7: low-res attention (16 n-rows per CTA) ----------------
__global__ __launch_bounds__(256) void lowres_kernel()
{
    const int mb = blockIdx.y, n0 = blockIdx.x*16;
    const int bb = mb / Hh;
    const int tid = threadIdx.x;
    __shared__ float4 V4[NBR][16];
    __shared__ float a_sh[16][129];
    __shared__ float tcs[NBR];

    for (int i = tid; i < NBR*16; i += 256) {
        int m = i >> 4, dg = i & 15;
        V4[m][dg] = *(const float4*)&g_Vh[((size_t)mb*NBR + m)*HD + dg*4];
    }
    if (tid < NBR) tcs[tid] = g_tcb[bb*NBR + tid];
    __syncthreads();

    const int nn = tid >> 4, mg = tid & 15;
    const int n = n0 + nn;
    const float rmv = g_rowmax[mb*NBR + n];
    const float t = g_thresh[mb];
    const float* llr = g_ll + ((size_t)mb*NBR + n)*NBR;
    const float* prr = g_prior + ((size_t)mb*NBR + n)*NBR;
    float psum = 0.f;
    #pragma unroll
    for (int k = 0; k < 8; k++) {
        int m = mg + 16*k;
        float sel = (prr[m] >= t) ? 1e4f : 0.f;
        float a = __expf(llr[m] - rmv - sel) * tcs[m];
        a_sh[nn][m] = a;
        psum += a;
    }
    #pragma unroll
    for (int off = 8; off >= 1; off >>= 1)
        psum += __shfl_xor_sync(0xffffffffu, psum, off, 16);
    if (mg == 0) g_low_norm[mb*NBR + n] = psum;
    __syncthreads();

    {
        const int dg = tid & 15;
        const float* ar = a_sh[tid >> 4];
        float4 acc = make_float4(0.f, 0.f, 0.f, 0.f);
        #pragma unroll 8
        for (int m = 0; m < NBR; m++) {
            float av = ar[m];
            float4 v = V4[m][dg];
            acc.x += av*v.x; acc.y += av*v.y; acc.z += av*v.z; acc.w += av*v.w;
        }
        *(float4*)&g_low_out[((size_t)mb*NBR + n0 + (tid >> 4))*HD + dg*4] = acc;
    }
}

// ---------------- kernel 6: high-res attention (bulk-copy K/V) + fused combine ----------------
#define SKH 0
#define SKL 8192
#define SVH 16384
#define SVL 24576
#define SQH 32768
#define SQL 36864
#define SMK 40960
#define SPH 41216
#define SPL 43776
#define SMAXP 46336
#define SSUMP 46848
#define SRM 47360
#define SSC 47488
#define SNRM 47616
#define SMBR 47744
#define HR_SMEM 47872

__global__ __launch_bounds__(128) void highres_kernel(const float* __restrict__ mask,
                                                      float* __restrict__ gout)
{
    __shared__ __align__(128) char sm[HR_SMEM];
    __shared__ float QM[32];
    __shared__ float LOWR[64];
    __shared__ float s_rmb, s_ln;
    const uint32_t sb = smem_u32(sm);
    const int mbn = blockIdx.x;
    const int mb = mbn >> 7, q = mbn & 127;
    const int bb = mb / Hh, hh = mb % Hh;
    const int tid = threadIdx.x;
    const int lane = tid & 31, w = tid >> 5;

    const int nb = g_cnt[mbn];
    const int* lst = g_list + (size_t)mbn*NBR;

    float* RM  = (float*)(sm + SRM);
    float* SC  = (float*)(sm + SSC);
    float* NRM = (float*)(sm + SNRM);
    float* MAXP = (float*)(sm + SMAXP);
    float* SUMP = (float*)(sm + SSUMP);

    // Q tiles are contiguous swizzled 4KB blocks: linear copy
    {
        size_t qtb = ((size_t)mb*128 + q)*4096;
        const uint4* qh = (const uint4*)((const char*)g_Qbh + qtb);
        const uint4* ql = (const uint4*)((const char*)g_Qbl + qtb);
        for (int i = tid; i < 256; i += 128) {
            ((uint4*)(sm + SQH))[i] = qh[i];
            ((uint4*)(sm + SQL))[i] = ql[i];
        }
    }
    if (tid == 0) { MB_INIT(sb + SMBR, 1); MB_INIT(sb + SMBR + 8, 1); }
    if (tid < 32) {
        RM[tid] = -1e30f; NRM[tid] = 0.f;
        QM[tid] = mask[(size_t)bb*Ss + q*BLKSZ + tid];
    }
    if (tid >= 64 && tid < 128) LOWR[tid - 64] = g_low_out[((size_t)mb*NBR + q)*HD + tid - 64];
    if (tid == 32) s_rmb = g_rowmax[mb*NBR + q];
    if (tid == 33) s_ln = g_low_norm[mb*NBR + q];
    __syncthreads();

    uint32_t aQh[2][4][4], aQl[2][4][4];
    #pragma unroll
    for (int mt = 0; mt < 2; mt++) {
        int row = mt*16 + (lane & 7) + ((lane >> 3) & 1)*8;
        #pragma unroll
        for (int ks = 0; ks < 4; ks++) {
            int cell = ks*2 + (lane >> 4);
            uint32_t ad = sb + SQH + row*128 + ((cell ^ (row & 7)) << 4);
            ldsm4(aQh[mt][ks][0], aQh[mt][ks][1], aQh[mt][ks][2], aQh[mt][ks][3], ad);
            ldsm4(aQl[mt][ks][0], aQl[mt][ks][1], aQl[mt][ks][2], aQl[mt][ks][3], ad + 4096);
        }
    }
    __syncthreads();

    float o[2][2][4];
    #pragma unroll
    for (int mt = 0; mt < 2; mt++)
        #pragma unroll
        for (int nt = 0; nt < 2; nt++)
            #pragma unroll
            for (int j = 0; j < 4; j++) o[mt][nt][j] = 0.f;

    #define HR_ISSUE(st, kb) do { if (tid == 0) { \
        uint32_t _mb = sb + SMBR + (st)*8; \
        MB_ARRIVE_TX(_mb, 16512); \
        size_t _tb = ((size_t)mb*128 + (kb))*4096; \
        BULK_G2S(sb + SKH + (st)*4096, (const char*)g_Kbh + _tb, 4096, _mb); \
        BULK_G2S(sb + SKL + (st)*4096, (const char*)g_Kbl + _tb, 4096, _mb); \
        BULK_G2S(sb + SVH + (st)*4096, (const char*)g_Vbh + _tb, 4096, _mb); \
        BULK_G2S(sb + SVL + (st)*4096, (const char*)g_Vbl + _tb, 4096, _mb); \
        BULK_G2S(sb + SMK + (st)*128, (const char*)(mask + (size_t)bb*Ss + (size_t)(kb)*BLKSZ), 128, _mb); \
    } } while (0)

    if (nb > 0) HR_ISSUE(0, lst[0]);

    for (int it = 0; it < nb; it++) {
        const int cur = it & 1;
        if (it + 1 < nb) HR_ISSUE((it+1) & 1, lst[it+1]);
        MB_WAIT(sb + SMBR + cur*8, (it >> 1) & 1);
        __syncthreads();

        float sacc[2][4];
        #pragma unroll
        for (int mt = 0; mt < 2; mt++)
            #pragma unroll
            for (int j = 0; j < 4; j++) sacc[mt][j] = 0.f;

        const uint32_t khb = sb + SKH + cur*4096;
        uint32_t kbh[4][2], kbl[4][2];
        #pragma unroll
        for (int ks = 0; ks < 4; ks++) {
            int kr = 8*w + (lane & 7);
            int cell = ks*2 + ((lane >> 3) & 1);
            uint32_t baddr = khb + kr*128 + ((cell ^ (kr & 7)) << 4);
            ldsm2(kbh[ks][0], kbh[ks][1], baddr);
            ldsm2(kbl[ks][0], kbl[ks][1], baddr + 8192);
        }
        #pragma unroll
        for (int ks = 0; ks < 4; ks++) {
            #pragma unroll
            for (int mt = 0; mt < 2; mt++) {
                mma16816(sacc[mt], aQh[mt][ks][0], aQh[mt][ks][1], aQh[mt][ks][2], aQh[mt][ks][3], kbh[ks][0], kbh[ks][1]);
                mma16816(sacc[mt], aQh[mt][ks][0], aQh[mt][ks][1], aQh[mt][ks][2], aQh[mt][ks][3], kbl[ks][0], kbl[ks][1]);
                mma16816(sacc[mt], aQl[mt][ks][0], aQl[mt][ks][1], aQl[mt][ks][2], aQl[mt][ks][3], kbh[ks][0], kbh[ks][1]);
            }
        }
        #pragma unroll
        for (int mt = 0; mt < 2; mt++)
            #pragma unroll
            for (int j = 0; j < 4; j++) sacc[mt][j] *= 0.125f;

        #pragma unroll
        for (int mt = 0; mt < 2; mt++) {
            float m1 = fmaxf(sacc[mt][0], sacc[mt][1]);
            float m2 = fmaxf(sacc[mt][2], sacc[mt][3]);
            m1 = fmaxf(m1, __shfl_xor_sync(0xffffffffu, m1, 1, 4));
            m1 = fmaxf(m1, __shfl_xor_sync(0xffffffffu, m1, 2, 4));
            m2 = fmaxf(m2, __shfl_xor_sync(0xffffffffu, m2, 1, 4));
            m2 = fmaxf(m2, __shfl_xor_sync(0xffffffffu, m2, 2, 4));
            if ((lane & 3) == 0) {
                int r1 = mt*16 + (lane >> 2);
                MAXP[r1*4 + w] = m1;
                MAXP[(r1+8)*4 + w] = m2;
            }
        }
        __syncthreads();
        if (tid < 32) {
            float tm = fmaxf(fmaxf(MAXP[tid*4], MAXP[tid*4+1]), fmaxf(MAXP[tid*4+2], MAXP[tid*4+3]));
            float old = RM[tid];
            float nm = fmaxf(old, tm);
            SC[tid] = __expf(old - nm);
            RM[tid] = nm;
        }
        __syncthreads();

        const float kmv0 = ((const float*)(sm + SMK + cur*128))[8*w + (lane & 3)*2];
        const float kmv1 = ((const float*)(sm + SMK + cur*128))[8*w + (lane & 3)*2 + 1];
        const float pen0 = 1e4f*(1.f - kmv0), pen1 = 1e4f*(1.f - kmv1);
        const int colb = (8*w + (lane & 3)*2)*2;

        #pragma unroll
        for (int mt = 0; mt < 2; mt++) {
            int r1 = mt*16 + (lane >> 2), r2 = r1 + 8;
            float sc1 = SC[r1], sc2 = SC[r2];
            float rm1 = RM[r1], rm2 = RM[r2];
            #pragma unroll
            for (int nt = 0; nt < 2; nt++) {
                o[mt][nt][0] *= sc1; o[mt][nt][1] *= sc1;
                o[mt][nt][2] *= sc2; o[mt][nt][3] *= sc2;
            }
            float p00, p01, p10, p11;
            if (mt == 0) {
                p00 = __expf(sacc[mt][0] - rm1 - pen0);
                p01 = __expf(sacc[mt][1] - rm1 - pen1);
                p10 = __expf(sacc[mt][2] - rm2 - pen0);
                p11 = fexp_poly(sacc[mt][3] - rm2 - pen1);
            } else {
                p00 = __expf(sacc[mt][0] - rm1 - pen0);
                p01 = __expf(sacc[mt][1] - rm1 - pen1);
                p10 = fexp_poly(sacc[mt][2] - rm2 - pen0);
                p11 = fexp_poly(sacc[mt][3] - rm2 - pen1);
            }

            __nv_bfloat162 ph0 = __floats2bfloat162_rn(p00, p01);
            __nv_bfloat162 pl0 = __floats2bfloat162_rn(
                p00 - __bfloat162float(__low2bfloat16(ph0)),
                p01 - __bfloat162float(__high2bfloat16(ph0)));
            __nv_bfloat162 ph1 = __floats2bfloat162_rn(p10, p11);
            __nv_bfloat162 pl1 = __floats2bfloat162_rn(
                p10 - __bfloat162float(__low2bfloat16(ph1)),
                p11 - __bfloat162float(__high2bfloat16(ph1)));
            *(__nv_bfloat162*)(sm + SPH + r1*80 + colb) = ph0;
            *(__nv_bfloat162*)(sm + SPL + r1*80 + colb) = pl0;
            *(__nv_bfloat162*)(sm + SPH + r2*80 + colb) = ph1;
            *(__nv_bfloat162*)(sm + SPL + r2*80 + colb) = pl1;

            float s1 = p00 + p01, s2 = p10 + p11;
            s1 += __shfl_xor_sync(0xffffffffu, s1, 1, 4);
            s1 += __shfl_xor_sync(0xffffffffu, s1, 2, 4);
            s2 += __shfl_xor_sync(0xffffffffu, s2, 1, 4);
            s2 += __shfl_xor_sync(0xffffffffu, s2, 2, 4);
            if ((lane & 3) == 0) {
                SUMP[r1*4 + w] = s1;
                SUMP[r2*4 + w] = s2;
            }
        }
        __syncthreads();
        if (tid < 32) {
            float s = SUMP[tid*4] + SUMP[tid*4+1] + SUMP[tid*4+2] + SUMP[tid*4+3];
            NRM[tid] = NRM[tid]*SC[tid] + s;
        }

        const uint32_t vhb = sb + SVH + cur*4096;
        #pragma unroll
        for (int ks = 0; ks < 2; ks++) {
            uint32_t aPh[2][4], aPl[2][4];
            #pragma unroll
            for (int mt = 0; mt < 2; mt++) {
                int row = mt*16 + (lane & 7) + ((lane >> 3) & 1)*8;
                uint32_t pad = sb + SPH + row*80 + (ks*2 + (lane >> 4))*16;
                ldsm4(aPh[mt][0], aPh[mt][1], aPh[mt][2], aPh[mt][3], pad);
                ldsm4(aPl[mt][0], aPl[mt][1], aPl[mt][2], aPl[mt][3], pad + (SPL - SPH));
            }
            int vrow = ks*16 + (lane & 7) + ((lane >> 3) & 1)*8;
            int vcell = 2*w + (lane >> 4);
            uint32_t vad = vhb + vrow*128 + ((vcell ^ (vrow & 7)) << 4);
            uint32_t bh0, bh1, bh2, bh3, bl0, bl1, bl2, bl3;
            ldsm4t(bh0, bh1, bh2, bh3, vad);
            ldsm4t(bl0, bl1, bl2, bl3, vad + 8192);
            #pragma unroll
            for (int mt = 0; mt < 2; mt++) {
                mma16816(o[mt][0], aPh[mt][0], aPh[mt][1], aPh[mt][2], aPh[mt][3], bh0, bh1);
                mma16816(o[mt][1], aPh[mt][0], aPh[mt][1], aPh[mt][2], aPh[mt][3], bh2, bh3);
                mma16816(o[mt][0], aPh[mt][0], aPh[mt][1], aPh[mt][2], aPh[mt][3], bl0, bl1);
                mma16816(o[mt][1], aPh[mt][0], aPh[mt][1], aPh[mt][2], aPh[mt][3], bl2, bl3);
                mma16816(o[mt][0], aPl[mt][0], aPl[mt][1], aPl[mt][2], aPl[mt][3], bh0, bh1);
                mma16816(o[mt][1], aPl[mt][0], aPl[mt][1], aPl[mt][2], aPl[mt][3], bh2, bh3);
            }
        }
        __syncthreads();
    }

    // ---- fused combine epilogue ----
    const float rmb = s_rmb, lnv = s_ln;
    #pragma unroll
    for (int mt = 0; mt < 2; mt++) {
        int r1 = mt*16 + (lane >> 2), r2 = r1 + 8;
        float mx1 = fmaxf(RM[r1], -1e6f), mx2 = fmaxf(RM[r2], -1e6f);
        float lcl1 = (rmb - mx1)*QM[r1], lcl2 = (rmb - mx2)*QM[r2];
        float lc1 = __expf(fminf(lcl1, 0.f)), hc1 = __expf(-fmaxf(lcl1, 0.f));
        float lc2 = __expf(fminf(lcl2, 0.f)), hc2 = __expf(-fmaxf(lcl2, 0.f));
        float inv1 = 1.f/(NRM[r1]*hc1 + lnv*lc1 + 1e-6f);
        float inv2 = 1.f/(NRM[r2]*hc2 + lnv*lc2 + 1e-6f);
        float* op1 = gout + ((size_t)bb*Ss + q*BLKSZ + r1)*Dm + hh*HD;
        float* op2 = gout + ((size_t)bb*Ss + q*BLKSZ + r2)*Dm + hh*HD;
        #pragma unroll
        for (int nt = 0; nt < 2; nt++) {
            int col = 16*w + nt*8 + (lane & 3)*2;
            float2 w1, w2;
            w1.x = (o[mt][nt][0]*hc1 + LOWR[col]*lc1)*inv1;
            w1.y = (o[mt][nt][1]*hc1 + LOWR[col+1]*lc1)*inv1;
            w2.x = (o[mt][nt][2]*hc2 + LOWR[col]*lc2)*inv2;
            w2.y = (o[mt][nt][3]*hc2 + LOWR[col+1]*lc2)*inv2;
            *(float2*)(op1 + col) = w1;
            *(float2*)(op2 + col) = w2;
        }
    }
}

// ---------------- launch ----------------
extern "C" void kernel_launch(void* const* d_in, const int* in_sizes, int n_in,
                              void* d_out, int out_size)
{
    const float* X    = (const float*)d_in[0];
    const float* mask = (const float*)d_in[1];
    const float* Wq   = (const float*)d_in[2];
    const float* bq   = (const float*)d_in[3];
    const float* Wk   = (const float*)d_in[4];
    const float* bk   = (const float*)d_in[5];
    const float* Wv   = (const float*)d_in[6];
    const float* bv   = (const float*)d_in[7];
    float* out = (float*)d_out;

    cudaFuncSetAttribute(qkv_mma_kernel, cudaFuncAttributeMaxDynamicSharedMemorySize, GEMM_SMEM);
    cudaFuncSetAttribute(threshsel_kernel, cudaFuncAttributeMaxDynamicSharedMemorySize, TS_SMEM);

    convX_kernel<<<MROWS*96/256, 256>>>(X);                        // 1
    convW_kernel<<<dim3(Dm*96/256, 3), 256>>>(Wq, Wk, Wv);         // 2
    xbar_kernel<<<Bb*NBR, Dm>>>(X, mask);                          // 3
    qkv_mma_kernel<<<dim3(MROWS/128, 9), 512, GEMM_SMEM>>>(mask, bq, bk, bv);  // 4 (profiled slot)
    hmean_gemm_kernel<<<dim3(8, 6, 3), 256>>>(Wq, Wk, Wv, bq, bk, bv);         // 5
    lowlogit_kernel<<<dim3(8, MBT), 256>>>();                      // 6
    threshsel_kernel<<<MBT, 256, TS_SMEM>>>();                     // 7
    lowres_kernel<<<dim3(8, MBT), 256>>>();                        // 8
    highres_kernel<<<MBT*NBR, 128>>>(mask, out);                   // 9 (writes final out)
}